// round 1
// baseline (speedup 1.0000x reference)
#include <cuda_runtime.h>
#include <math.h>

#define Bb   8
#define Nn   1024
#define Dd   64
#define Hh   4
#define Cc   129
#define Kk   16
#define Mm   4096
#define ROWS 8192   // B*N

// ---------------- scratch (static __device__; no allocations) ----------------
__device__ float g_combined[ROWS * Cc];     // 4.2 MB
__device__ float g_q[Hh * ROWS * Kk];       // 2 MB
__device__ float g_k[Hh * ROWS * Kk];       // 2 MB
__device__ float g_v[Hh * ROWS * Cc];       // 16.9 MB
__device__ float g_hp[ROWS * Hh * Cc];      // 16.9 MB  (attn_cat layout [row][h*C+c])
__device__ float g_hn[Mm * Dd];             // r * h_sel
__device__ float g_u[Mm * Dd];
__device__ float g_sel2[Mm * Cc];           // [x_sel | hn]

// ---------------- K0: combined = concat(x, h) ----------------
__global__ void k_combined(const float* __restrict__ x, const float* __restrict__ h) {
    int idx = blockIdx.x * 256 + threadIdx.x;
    if (idx >= ROWS * Cc) return;
    int row = idx / Cc, c = idx - row * Cc;
    g_combined[idx] = (c < 65) ? x[row * 65 + c] : h[row * 64 + (c - 65)];
}

// ---------------- K1: q, k projections (small) ----------------
__global__ void __launch_bounds__(256) k_qk(const float* __restrict__ Wq, const float* __restrict__ bq,
                                            const float* __restrict__ Wk, const float* __restrict__ bk) {
    int t = blockIdx.x * 256 + threadIdx.x;        // < H*ROWS*K = 524288
    int kk  = t & 15;
    int row = (t >> 4) & (ROWS - 1);
    int hh  = t >> 17;
    const float* comb = g_combined + row * Cc;
    const float* wq = Wq + hh * Cc * Kk + kk;
    const float* wk = Wk + hh * Cc * Kk + kk;
    float aq = bq[hh * 16 + kk], ak = bk[hh * 16 + kk];
    #pragma unroll 4
    for (int i = 0; i < Cc; i++) {
        float cv = comb[i];
        aq += cv * wq[i * 16];
        ak += cv * wk[i * 16];
    }
    g_q[t] = aq;
    g_k[t] = ak;
}

// ---------------- K2: v projection (tiled GEMM) ----------------
__global__ void __launch_bounds__(256) k_v(const float* __restrict__ Wv, const float* __restrict__ bv) {
    extern __shared__ float sm[];
    float* comb_s = sm;                 // 64*132
    float* w_s    = sm + 64 * 132;      // 129*136 (+pad)
    int tile = blockIdx.x, hh = blockIdx.y, tid = threadIdx.x;

    for (int e = tid; e < 64 * Cc; e += 256) {
        int r = e / Cc, c = e - r * Cc;
        comb_s[r * 132 + c] = g_combined[(tile * 64 + r) * Cc + c];
    }
    for (int e = tid; e < Cc * Cc; e += 256) {
        int i = e / Cc, c = e - i * Cc;
        w_s[i * 136 + c] = Wv[(hh * Cc + i) * Cc + c];
    }
    __syncthreads();

    int rg = tid >> 4, cg = tid & 15;
    int r0 = rg * 4, c0 = cg * 9;
    float acc[4][9] = {};
    #pragma unroll 2
    for (int i = 0; i < Cc; i++) {
        float a0 = comb_s[(r0 + 0) * 132 + i];
        float a1 = comb_s[(r0 + 1) * 132 + i];
        float a2 = comb_s[(r0 + 2) * 132 + i];
        float a3 = comb_s[(r0 + 3) * 132 + i];
        #pragma unroll
        for (int jj = 0; jj < 9; jj++) {
            float w = w_s[i * 136 + c0 + jj];
            acc[0][jj] += a0 * w; acc[1][jj] += a1 * w;
            acc[2][jj] += a2 * w; acc[3][jj] += a3 * w;
        }
    }
    #pragma unroll
    for (int j = 0; j < 4; j++)
        #pragma unroll
        for (int jj = 0; jj < 9; jj++) {
            int c = c0 + jj;
            if (c < Cc)
                g_v[(hh * ROWS + tile * 64 + r0 + j) * Cc + c] = acc[j][jj] + bv[hh * Cc + c];
        }
}

// ---------------- K3: fused masked-softmax attention + attn@v ----------------
// block = (h, b, 64-row n-tile); flash-style over m in 8 chunks of 128.
// No max-subtraction: scores are bounded small by construction; masked -> p=0.
__global__ void __launch_bounds__(256) k_attn(const int* __restrict__ adj) {
    extern __shared__ float sm[];
    float* q_s = sm;                        // 64*17
    float* k_s = q_s + 64 * 17;             // 128*17
    float* p_s = k_s + 128 * 17;            // 64*133
    float* v_s = p_s + 64 * 133;            // 128*136
    float* l_s = v_s + 128 * 136;           // 64 (+pad)
    int ntile = blockIdx.x, b = blockIdx.y, hh = blockIdx.z;
    int tid = threadIdx.x;
    int base_row = b * Nn + ntile * 64;

    for (int e = tid; e < 64 * 16; e += 256) {
        int r = e >> 4, kk = e & 15;
        q_s[r * 17 + kk] = g_q[(hh * ROWS + base_row + r) * 16 + kk];
    }
    if (tid < 64) l_s[tid] = 0.f;

    int rg = tid >> 4, cg = tid & 15;
    int r0 = rg * 4, c0 = cg * 9;
    float acc[4][9] = {};

    for (int cc = 0; cc < 8; cc++) {
        __syncthreads();
        int m0 = cc * 128;
        for (int e = tid; e < 128 * 16; e += 256) {
            int m = e >> 4, kk = e & 15;
            k_s[m * 17 + kk] = g_k[(hh * ROWS + b * Nn + m0 + m) * 16 + kk];
        }
        for (int e = tid; e < 128 * 129; e += 256) {
            int m = e / 129, c = e - m * 129;
            v_s[m * 136 + c] = g_v[(hh * ROWS + b * Nn + m0 + m) * Cc + c];
        }
        __syncthreads();

        // scores -> p (leaky + mask + exp), 8192 entries
        #pragma unroll 4
        for (int i = 0; i < 32; i++) {
            int e = tid + 256 * i;
            int r = e >> 7, m = e & 127;
            float s = 0.f;
            #pragma unroll
            for (int j = 0; j < 16; j++) s += q_s[r * 17 + j] * k_s[m * 17 + j];
            s *= 0.25f;
            s = s > 0.f ? s : 0.2f * s;
            int a = adj[(ntile * 64 + r) * Nn + m0 + m];
            p_s[r * 133 + m] = a ? __expf(s) : 0.f;
        }
        __syncthreads();

        if (tid < 64) {
            float sum = 0.f;
            #pragma unroll 8
            for (int m = 0; m < 128; m++) sum += p_s[tid * 133 + m];
            l_s[tid] += sum;
        }
        // acc += p @ v_chunk
        #pragma unroll 4
        for (int m = 0; m < 128; m++) {
            float p0 = p_s[(r0 + 0) * 133 + m];
            float p1 = p_s[(r0 + 1) * 133 + m];
            float p2 = p_s[(r0 + 2) * 133 + m];
            float p3 = p_s[(r0 + 3) * 133 + m];
            #pragma unroll
            for (int jj = 0; jj < 9; jj++) {
                float v = v_s[m * 136 + c0 + jj];
                acc[0][jj] += p0 * v; acc[1][jj] += p1 * v;
                acc[2][jj] += p2 * v; acc[3][jj] += p3 * v;
            }
        }
    }
    __syncthreads();

    #pragma unroll
    for (int j = 0; j < 4; j++) {
        float inv = 1.f / l_s[r0 + j];
        int row = base_row + r0 + j;
        #pragma unroll
        for (int jj = 0; jj < 9; jj++) {
            int c = c0 + jj;
            if (c < Cc) g_hp[row * 516 + hh * Cc + c] = acc[j][jj] * inv;
        }
    }
}

// ---------------- K4: attention MLP + skip (in-place into g_combined) ----------------
__global__ void __launch_bounds__(256) k_mlp(const float* __restrict__ W1, const float* __restrict__ b1,
                                             const float* __restrict__ W2, const float* __restrict__ b2) {
    extern __shared__ float sm[];
    float* in_s  = sm;                          // 64*90
    float* w1_s  = sm + 64 * 90;                // 86*136
    float* hid_s = sm + 64 * 90 + 86 * 136;     // 64*133
    float* w2_s  = sm;                          // alias over in_s+w1_s (129*134 fits)
    int blk = blockIdx.x, tid = threadIdx.x;
    int rg = tid >> 4, cg = tid & 15;
    int r0 = rg * 4, c0 = cg * 9;

    float acc[4][9] = {};
    for (int kc = 0; kc < 6; kc++) {
        __syncthreads();
        for (int e = tid; e < 64 * 86; e += 256) {
            int r = e / 86, kk = e - r * 86;
            in_s[r * 90 + kk] = g_hp[(blk * 64 + r) * 516 + kc * 86 + kk];
        }
        for (int e = tid; e < 86 * 129; e += 256) {
            int i = e / 129, c = e - i * 129;
            w1_s[i * 136 + c] = W1[(kc * 86 + i) * 129 + c];
        }
        __syncthreads();
        #pragma unroll 2
        for (int kk = 0; kk < 86; kk++) {
            float a0 = in_s[(r0 + 0) * 90 + kk];
            float a1 = in_s[(r0 + 1) * 90 + kk];
            float a2 = in_s[(r0 + 2) * 90 + kk];
            float a3 = in_s[(r0 + 3) * 90 + kk];
            #pragma unroll
            for (int jj = 0; jj < 9; jj++) {
                float w = w1_s[kk * 136 + c0 + jj];
                acc[0][jj] += a0 * w; acc[1][jj] += a1 * w;
                acc[2][jj] += a2 * w; acc[3][jj] += a3 * w;
            }
        }
    }
    __syncthreads();
    #pragma unroll
    for (int j = 0; j < 4; j++)
        #pragma unroll
        for (int jj = 0; jj < 9; jj++) {
            int c = c0 + jj;
            if (c < Cc) hid_s[(r0 + j) * 133 + c] = fmaxf(acc[j][jj] + b1[c], 0.f);
        }
    __syncthreads();
    for (int e = tid; e < 129 * 129; e += 256) {
        int i = e / 129, c = e - i * 129;
        w2_s[i * 134 + c] = W2[i * 129 + c];
    }
    __syncthreads();

    float acc2[4][9] = {};
    #pragma unroll 2
    for (int i = 0; i < Cc; i++) {
        float a0 = hid_s[(r0 + 0) * 133 + i];
        float a1 = hid_s[(r0 + 1) * 133 + i];
        float a2 = hid_s[(r0 + 2) * 133 + i];
        float a3 = hid_s[(r0 + 3) * 133 + i];
        #pragma unroll
        for (int jj = 0; jj < 9; jj++) {
            float w = w2_s[i * 134 + c0 + jj];
            acc2[0][jj] += a0 * w; acc2[1][jj] += a1 * w;
            acc2[2][jj] += a2 * w; acc2[3][jj] += a3 * w;
        }
    }
    #pragma unroll
    for (int j = 0; j < 4; j++)
        #pragma unroll
        for (int jj = 0; jj < 9; jj++) {
            int c = c0 + jj;
            if (c < Cc) {
                int idx = (blk * 64 + r0 + j) * Cc + c;
                g_combined[idx] = g_combined[idx] + acc2[j][jj] + b2[c];   // skip connection
            }
        }
}

// ---------------- K5: r,u gates (hypernetwork GEMM), build hn & sel2 ----------------
__global__ void __launch_bounds__(256) k_gate_ru(const float* __restrict__ qv,
                                                 const int* __restrict__ nodes_b, const int* __restrict__ nodes_n,
                                                 const float* __restrict__ Wr, const float* __restrict__ br,
                                                 const float* __restrict__ Wu, const float* __restrict__ bu,
                                                 const float* __restrict__ x, const float* __restrict__ hin) {
    extern __shared__ float sm[];
    float* sel_s = sm;                           // 64*132
    float* qv_s  = sel_s + 64 * 132;             // 64*33
    float* z_s   = qv_s + 64 * 33;               // 64*132
    float* wr_s  = z_s + 64 * 132;               // 129*68
    float* wu_s  = wr_s + 129 * 68;              // 129*68
    int blk = blockIdx.x, tid = threadIdx.x;

    for (int e = tid; e < 64 * Cc; e += 256) {
        int lm = e / Cc, i = e - lm * Cc;
        int gm = blk * 64 + lm;
        int node = nodes_b[gm] * Nn + nodes_n[gm];
        sel_s[lm * 132 + i] = g_combined[node * Cc + i];
    }
    for (int e = tid; e < 64 * 32; e += 256) {
        int lm = e >> 5, d = e & 31;
        qv_s[lm * 33 + d] = qv[(blk * 64 + lm) * 32 + d];
    }
    int mg = tid >> 4, og = tid & 15, m0 = mg * 4, o0 = og * 4;
    float ar[4][4] = {}, au[4][4] = {};

    for (int d = 0; d < 32; d++) {
        __syncthreads();
        for (int e = tid; e < 129 * 64; e += 256) {
            int i = e >> 6, o = e & 63;
            wr_s[i * 68 + o] = Wr[(d * Cc + i) * 64 + o];
            wu_s[i * 68 + o] = Wu[(d * Cc + i) * 64 + o];
        }
        for (int e = tid; e < 64 * Cc; e += 256) {
            int lm = e / Cc, i = e - lm * Cc;
            z_s[lm * 132 + i] = qv_s[lm * 33 + d] * sel_s[lm * 132 + i];
        }
        __syncthreads();
        #pragma unroll 2
        for (int i = 0; i < Cc; i++) {
            float z0 = z_s[(m0 + 0) * 132 + i];
            float z1 = z_s[(m0 + 1) * 132 + i];
            float z2 = z_s[(m0 + 2) * 132 + i];
            float z3 = z_s[(m0 + 3) * 132 + i];
            float4 wr4 = *(const float4*)&wr_s[i * 68 + o0];
            float4 wu4 = *(const float4*)&wu_s[i * 68 + o0];
            ar[0][0] += z0 * wr4.x; ar[0][1] += z0 * wr4.y; ar[0][2] += z0 * wr4.z; ar[0][3] += z0 * wr4.w;
            ar[1][0] += z1 * wr4.x; ar[1][1] += z1 * wr4.y; ar[1][2] += z1 * wr4.z; ar[1][3] += z1 * wr4.w;
            ar[2][0] += z2 * wr4.x; ar[2][1] += z2 * wr4.y; ar[2][2] += z2 * wr4.z; ar[2][3] += z2 * wr4.w;
            ar[3][0] += z3 * wr4.x; ar[3][1] += z3 * wr4.y; ar[3][2] += z3 * wr4.z; ar[3][3] += z3 * wr4.w;
            au[0][0] += z0 * wu4.x; au[0][1] += z0 * wu4.y; au[0][2] += z0 * wu4.z; au[0][3] += z0 * wu4.w;
            au[1][0] += z1 * wu4.x; au[1][1] += z1 * wu4.y; au[1][2] += z1 * wu4.z; au[1][3] += z1 * wu4.w;
            au[2][0] += z2 * wu4.x; au[2][1] += z2 * wu4.y; au[2][2] += z2 * wu4.z; au[2][3] += z2 * wu4.w;
            au[3][0] += z3 * wu4.x; au[3][1] += z3 * wu4.y; au[3][2] += z3 * wu4.z; au[3][3] += z3 * wu4.w;
        }
    }
    // bias: += qv @ b
    for (int d = 0; d < 32; d++) {
        float4 b4r = *(const float4*)&br[d * 64 + o0];
        float4 b4u = *(const float4*)&bu[d * 64 + o0];
        #pragma unroll
        for (int j = 0; j < 4; j++) {
            float q = qv_s[(m0 + j) * 33 + d];
            ar[j][0] += q * b4r.x; ar[j][1] += q * b4r.y; ar[j][2] += q * b4r.z; ar[j][3] += q * b4r.w;
            au[j][0] += q * b4u.x; au[j][1] += q * b4u.y; au[j][2] += q * b4u.z; au[j][3] += q * b4u.w;
        }
    }
    #pragma unroll
    for (int j = 0; j < 4; j++) {
        int gm = blk * 64 + m0 + j;
        int node = nodes_b[gm] * Nn + nodes_n[gm];
        #pragma unroll
        for (int t = 0; t < 4; t++) {
            int o = o0 + t;
            float hv = hin[node * 64 + o];
            float r = 1.f / (1.f + __expf(-ar[j][t]));
            float u = 1.f / (1.f + __expf(-au[j][t]));
            float hn = r * hv;
            g_hn[gm * 64 + o] = hn;
            g_u[gm * 64 + o] = u;
            g_sel2[gm * Cc + 65 + o] = hn;
        }
    }
    // x part of sel2
    for (int e = tid; e < 64 * 65; e += 256) {
        int lm = e / 65, i = e - lm * 65;
        int gm = blk * 64 + lm;
        int node = nodes_b[gm] * Nn + nodes_n[gm];
        g_sel2[gm * Cc + i] = x[node * 65 + i];
    }
}

// ---------------- K6: cand gate + final gated update -> d_out ----------------
__global__ void __launch_bounds__(256) k_gate_c(const float* __restrict__ qv,
                                                const float* __restrict__ Wc, const float* __restrict__ bc,
                                                float* __restrict__ out) {
    extern __shared__ float sm[];
    float* sel_s = sm;                           // 64*132
    float* qv_s  = sel_s + 64 * 132;             // 64*33
    float* z_s   = qv_s + 64 * 33;               // 64*132
    float* wc_s  = z_s + 64 * 132;               // 129*68
    int blk = blockIdx.x, tid = threadIdx.x;

    for (int e = tid; e < 64 * Cc; e += 256) {
        int lm = e / Cc, i = e - lm * Cc;
        sel_s[lm * 132 + i] = g_sel2[(blk * 64 + lm) * Cc + i];
    }
    for (int e = tid; e < 64 * 32; e += 256) {
        int lm = e >> 5, d = e & 31;
        qv_s[lm * 33 + d] = qv[(blk * 64 + lm) * 32 + d];
    }
    int mg = tid >> 4, og = tid & 15, m0 = mg * 4, o0 = og * 4;
    float ac[4][4] = {};

    for (int d = 0; d < 32; d++) {
        __syncthreads();
        for (int e = tid; e < 129 * 64; e += 256) {
            int i = e >> 6, o = e & 63;
            wc_s[i * 68 + o] = Wc[(d * Cc + i) * 64 + o];
        }
        for (int e = tid; e < 64 * Cc; e += 256) {
            int lm = e / Cc, i = e - lm * Cc;
            z_s[lm * 132 + i] = qv_s[lm * 33 + d] * sel_s[lm * 132 + i];
        }
        __syncthreads();
        #pragma unroll 2
        for (int i = 0; i < Cc; i++) {
            float z0 = z_s[(m0 + 0) * 132 + i];
            float z1 = z_s[(m0 + 1) * 132 + i];
            float z2 = z_s[(m0 + 2) * 132 + i];
            float z3 = z_s[(m0 + 3) * 132 + i];
            float4 w4 = *(const float4*)&wc_s[i * 68 + o0];
            ac[0][0] += z0 * w4.x; ac[0][1] += z0 * w4.y; ac[0][2] += z0 * w4.z; ac[0][3] += z0 * w4.w;
            ac[1][0] += z1 * w4.x; ac[1][1] += z1 * w4.y; ac[1][2] += z1 * w4.z; ac[1][3] += z1 * w4.w;
            ac[2][0] += z2 * w4.x; ac[2][1] += z2 * w4.y; ac[2][2] += z2 * w4.z; ac[2][3] += z2 * w4.w;
            ac[3][0] += z3 * w4.x; ac[3][1] += z3 * w4.y; ac[3][2] += z3 * w4.z; ac[3][3] += z3 * w4.w;
        }
    }
    for (int d = 0; d < 32; d++) {
        float4 b4 = *(const float4*)&bc[d * 64 + o0];
        #pragma unroll
        for (int j = 0; j < 4; j++) {
            float q = qv_s[(m0 + j) * 33 + d];
            ac[j][0] += q * b4.x; ac[j][1] += q * b4.y; ac[j][2] += q * b4.z; ac[j][3] += q * b4.w;
        }
    }
    #pragma unroll
    for (int j = 0; j < 4; j++) {
        int gm = blk * 64 + m0 + j;
        #pragma unroll
        for (int t = 0; t < 4; t++) {
            int o = o0 + t;
            float cand = tanhf(ac[j][t]);
            float u = g_u[gm * 64 + o];
            float hn = g_hn[gm * 64 + o];
            out[gm * 64 + o] = (1.f - u) * hn + u * cand;
        }
    }
}

// ---------------- launch ----------------
extern "C" void kernel_launch(void* const* d_in, const int* in_sizes, int n_in,
                              void* d_out, int out_size) {
    const float* x   = (const float*)d_in[0];
    const float* h   = (const float*)d_in[1];
    const float* qv  = (const float*)d_in[2];
    const int*   adj = (const int*)  d_in[3];
    const int*   nb  = (const int*)  d_in[4];
    const int*   nn  = (const int*)  d_in[5];
    const float* Wq  = (const float*)d_in[6];
    const float* bq  = (const float*)d_in[7];
    const float* Wk  = (const float*)d_in[8];
    const float* bk  = (const float*)d_in[9];
    const float* Wv  = (const float*)d_in[10];
    const float* bv  = (const float*)d_in[11];
    const float* W1  = (const float*)d_in[12];
    const float* b1  = (const float*)d_in[13];
    const float* W2  = (const float*)d_in[14];
    const float* b2  = (const float*)d_in[15];
    const float* Wr  = (const float*)d_in[16];
    const float* br  = (const float*)d_in[17];
    const float* Wu  = (const float*)d_in[18];
    const float* bu  = (const float*)d_in[19];
    const float* Wc  = (const float*)d_in[20];
    const float* bc  = (const float*)d_in[21];
    float* out = (float*)d_out;

    const int SZ_V  = (64 * 132 + 129 * 136 + 16) * 4;
    const int SZ_A  = (64 * 17 + 128 * 17 + 64 * 133 + 128 * 136 + 64 + 16) * 4;
    const int SZ_M  = (64 * 90 + 86 * 136 + 64 * 133 + 16) * 4;
    const int SZ_RU = (64 * 132 + 64 * 33 + 64 * 132 + 2 * 129 * 68 + 16) * 4;
    const int SZ_C  = (64 * 132 + 64 * 33 + 64 * 132 + 129 * 68 + 16) * 4;

    cudaFuncSetAttribute(k_v,       cudaFuncAttributeMaxDynamicSharedMemorySize, SZ_V);
    cudaFuncSetAttribute(k_attn,    cudaFuncAttributeMaxDynamicSharedMemorySize, SZ_A);
    cudaFuncSetAttribute(k_mlp,     cudaFuncAttributeMaxDynamicSharedMemorySize, SZ_M);
    cudaFuncSetAttribute(k_gate_ru, cudaFuncAttributeMaxDynamicSharedMemorySize, SZ_RU);
    cudaFuncSetAttribute(k_gate_c,  cudaFuncAttributeMaxDynamicSharedMemorySize, SZ_C);

    k_combined<<<(ROWS * Cc + 255) / 256, 256>>>(x, h);
    k_qk<<<(Hh * ROWS * Kk) / 256, 256>>>(Wq, bq, Wk, bk);
    k_v<<<dim3(128, 4), 256, SZ_V>>>(Wv, bv);
    k_attn<<<dim3(16, 8, 4), 256, SZ_A>>>(adj);
    k_mlp<<<128, 256, SZ_M>>>(W1, b1, W2, b2);
    k_gate_ru<<<64, 256, SZ_RU>>>(qv, nb, nn, Wr, br, Wu, bu, x, h);
    k_gate_c<<<64, 256, SZ_C>>>(qv, Wc, bc, out);
}

// round 2
// speedup vs baseline: 1.4290x; 1.4290x over previous
#include <cuda_runtime.h>
#include <math.h>

#define Bb   8
#define Nn   1024
#define Dd   64
#define Hh   4
#define Cc   129
#define Kk   16
#define Mm   4096
#define ROWS 8192   // B*N

// ---------------- scratch (static __device__; no allocations) ----------------
__device__ float g_combined[ROWS * Cc];
__device__ float g_q[Hh * ROWS * Kk];
__device__ float g_k[Hh * ROWS * Kk];
__device__ float g_v[Hh * ROWS * Cc];
__device__ float g_hp[ROWS * Hh * Cc];       // final attn_cat [row][h*129+c]
__device__ float g_hp0[ROWS * Hh * Cc];      // partial (m-half 0), unnormalized
__device__ float g_hp1[ROWS * Hh * Cc];      // partial (m-half 1), unnormalized
__device__ float g_lp[2][Hh * ROWS];         // partial row sums
__device__ float g_hn[Mm * Dd];
__device__ float g_u[Mm * Dd];
__device__ float g_sel2[Mm * Cc];

// ---------------- K0: combined = concat(x, h) ----------------
__global__ void k_combined(const float* __restrict__ x, const float* __restrict__ h) {
    int idx = blockIdx.x * 256 + threadIdx.x;
    if (idx >= ROWS * Cc) return;
    int row = idx / Cc, c = idx - row * Cc;
    g_combined[idx] = (c < 65) ? x[row * 65 + c] : h[row * 64 + (c - 65)];
}

// ---------------- K1: q, k projections ----------------
__global__ void __launch_bounds__(256) k_qk(const float* __restrict__ Wq, const float* __restrict__ bq,
                                            const float* __restrict__ Wk, const float* __restrict__ bk) {
    int t = blockIdx.x * 256 + threadIdx.x;
    int kk  = t & 15;
    int row = (t >> 4) & (ROWS - 1);
    int hh  = t >> 17;
    const float* comb = g_combined + row * Cc;
    const float* wq = Wq + hh * Cc * Kk + kk;
    const float* wk = Wk + hh * Cc * Kk + kk;
    float aq = bq[hh * 16 + kk], ak = bk[hh * 16 + kk];
    #pragma unroll 4
    for (int i = 0; i < Cc; i++) {
        float cv = comb[i];
        aq += cv * wq[i * 16];
        ak += cv * wk[i * 16];
    }
    g_q[t] = aq;
    g_k[t] = ak;
}

// ---------------- K2: v projection (tiled GEMM) ----------------
__global__ void __launch_bounds__(256) k_v(const float* __restrict__ Wv, const float* __restrict__ bv) {
    extern __shared__ float sm[];
    float* comb_s = sm;                 // 64*132
    float* w_s    = sm + 64 * 132;      // 129*136
    int tile = blockIdx.x, hh = blockIdx.y, tid = threadIdx.x;

    for (int e = tid; e < 64 * Cc; e += 256) {
        int r = e / Cc, c = e - r * Cc;
        comb_s[r * 132 + c] = g_combined[(tile * 64 + r) * Cc + c];
    }
    for (int e = tid; e < Cc * Cc; e += 256) {
        int i = e / Cc, c = e - i * Cc;
        w_s[i * 136 + c] = Wv[(hh * Cc + i) * Cc + c];
    }
    __syncthreads();

    int rg = tid >> 4, cg = tid & 15;
    int r0 = rg * 4, c0 = cg * 9;
    float acc[4][9] = {};
    #pragma unroll 2
    for (int i = 0; i < Cc; i++) {
        float a0 = comb_s[(r0 + 0) * 132 + i];
        float a1 = comb_s[(r0 + 1) * 132 + i];
        float a2 = comb_s[(r0 + 2) * 132 + i];
        float a3 = comb_s[(r0 + 3) * 132 + i];
        #pragma unroll
        for (int jj = 0; jj < 9; jj++) {
            float w = w_s[i * 136 + c0 + jj];
            acc[0][jj] += a0 * w; acc[1][jj] += a1 * w;
            acc[2][jj] += a2 * w; acc[3][jj] += a3 * w;
        }
    }
    #pragma unroll
    for (int j = 0; j < 4; j++)
        #pragma unroll
        for (int jj = 0; jj < 9; jj++) {
            int c = c0 + jj;
            if (c < Cc)
                g_v[(hh * ROWS + tile * 64 + r0 + j) * Cc + c] = acc[j][jj] + bv[hh * Cc + c];
        }
}

// ---------------- K3: fused attention, m-split in halves, 64-m chunks ----------------
// grid (32, 8, 4): blockIdx.x = ntile*2 + half. Writes unnormalized partials.
__global__ void __launch_bounds__(256, 3) k_attn(const int* __restrict__ adj) {
    extern __shared__ float sm[];
    float* qT = sm;                 // [16][68]  qT[kk][r]
    float* kT = sm + 16 * 68;       // [16][68]  kT[kk][m]
    float* pS = sm + 2 * 16 * 68;   // [64][68]  pS[r][m]
    float* vS = pS + 64 * 68;       // [64][132] vS[m][c]

    int bx = blockIdx.x;
    int half = bx & 1, ntile = bx >> 1;
    int b = blockIdx.y, hh = blockIdx.z;
    int tid = threadIdx.x;
    int base_row = b * Nn + ntile * 64;

    // load q transposed (once)
    for (int e = tid; e < 64 * 16; e += 256) {
        int r = e >> 4, kk = e & 15;
        qT[kk * 68 + r] = g_q[(hh * ROWS + base_row + r) * 16 + kk];
    }

    int rg = tid >> 4, cg = tid & 15;
    int r0 = rg * 4;
    int m0s = cg * 4;   // score-phase m tile
    int c0  = cg * 8;   // pv-phase col tile

    float acc[4][8] = {};
    float accX[4] = {};
    float lsum[4] = {};

    for (int cchunk = 0; cchunk < 8; cchunk++) {
        int m0g = half * 512 + cchunk * 64;
        __syncthreads();
        // load k transposed + v tile
        for (int e = tid; e < 64 * 16; e += 256) {
            int m = e >> 4, kk = e & 15;
            kT[kk * 68 + m] = g_k[(hh * ROWS + b * Nn + m0g + m) * 16 + kk];
        }
        for (int e = tid; e < 64 * 129; e += 256) {
            int m = e / 129, c = e - m * 129;
            vS[m * 132 + c] = g_v[(hh * ROWS + b * Nn + m0g + m) * Cc + c];
        }
        __syncthreads();

        // scores: 4x4 register tile, float4 operands
        float sc[4][4] = {};
        #pragma unroll
        for (int kk = 0; kk < 16; kk++) {
            float4 q4 = *(const float4*)&qT[kk * 68 + r0];
            float4 k4 = *(const float4*)&kT[kk * 68 + m0s];
            sc[0][0] += q4.x * k4.x; sc[0][1] += q4.x * k4.y; sc[0][2] += q4.x * k4.z; sc[0][3] += q4.x * k4.w;
            sc[1][0] += q4.y * k4.x; sc[1][1] += q4.y * k4.y; sc[1][2] += q4.y * k4.z; sc[1][3] += q4.y * k4.w;
            sc[2][0] += q4.z * k4.x; sc[2][1] += q4.z * k4.y; sc[2][2] += q4.z * k4.z; sc[2][3] += q4.z * k4.w;
            sc[3][0] += q4.w * k4.x; sc[3][1] += q4.w * k4.y; sc[3][2] += q4.w * k4.z; sc[3][3] += q4.w * k4.w;
        }
        #pragma unroll
        for (int j = 0; j < 4; j++) {
            int4 a4 = *(const int4*)&adj[(ntile * 64 + r0 + j) * Nn + m0g + m0s];
            float4 pr;
            float s;
            s = sc[j][0] * 0.25f; s = s > 0.f ? s : 0.2f * s; pr.x = a4.x ? __expf(s) : 0.f;
            s = sc[j][1] * 0.25f; s = s > 0.f ? s : 0.2f * s; pr.y = a4.y ? __expf(s) : 0.f;
            s = sc[j][2] * 0.25f; s = s > 0.f ? s : 0.2f * s; pr.z = a4.z ? __expf(s) : 0.f;
            s = sc[j][3] * 0.25f; s = s > 0.f ? s : 0.2f * s; pr.w = a4.w ? __expf(s) : 0.f;
            *(float4*)&pS[(r0 + j) * 68 + m0s] = pr;
        }
        __syncthreads();

        // p @ v : vectorized
        for (int mq = 0; mq < 64; mq += 4) {
            float pv[4][4];
            #pragma unroll
            for (int j = 0; j < 4; j++)
                *(float4*)pv[j] = *(const float4*)&pS[(r0 + j) * 68 + mq];
            if (cg == 0) {
                #pragma unroll
                for (int j = 0; j < 4; j++)
                    lsum[j] += pv[j][0] + pv[j][1] + pv[j][2] + pv[j][3];
            }
            #pragma unroll
            for (int t = 0; t < 4; t++) {
                float4 va = *(const float4*)&vS[(mq + t) * 132 + c0];
                float4 vb = *(const float4*)&vS[(mq + t) * 132 + c0 + 4];
                #pragma unroll
                for (int j = 0; j < 4; j++) {
                    float p = pv[j][t];
                    acc[j][0] += p * va.x; acc[j][1] += p * va.y;
                    acc[j][2] += p * va.z; acc[j][3] += p * va.w;
                    acc[j][4] += p * vb.x; acc[j][5] += p * vb.y;
                    acc[j][6] += p * vb.z; acc[j][7] += p * vb.w;
                }
                if (cg == 15) {
                    float vx = vS[(mq + t) * 132 + 128];
                    #pragma unroll
                    for (int j = 0; j < 4; j++) accX[j] += pv[j][t] * vx;
                }
            }
        }
    }

    float* hpdst = half ? g_hp1 : g_hp0;
    #pragma unroll
    for (int j = 0; j < 4; j++) {
        int row = base_row + r0 + j;
        #pragma unroll
        for (int jj = 0; jj < 8; jj++)
            hpdst[row * 516 + hh * Cc + c0 + jj] = acc[j][jj];
        if (cg == 15) hpdst[row * 516 + hh * Cc + 128] = accX[j];
        if (cg == 0)  g_lp[half][hh * ROWS + row] = lsum[j];
    }
}

// ---------------- K3b: combine partials + normalize ----------------
__global__ void k_comb() {
    int idx = blockIdx.x * 256 + threadIdx.x;
    if (idx >= ROWS * 516) return;
    int row = idx / 516;
    int hc = idx - row * 516;
    int hh = hc / Cc;
    float l = g_lp[0][hh * ROWS + row] + g_lp[1][hh * ROWS + row];
    g_hp[idx] = (g_hp0[idx] + g_hp1[idx]) / l;
}

// ---------------- K4: attention MLP + skip ----------------
__global__ void __launch_bounds__(256) k_mlp(const float* __restrict__ W1, const float* __restrict__ b1,
                                             const float* __restrict__ W2, const float* __restrict__ b2) {
    extern __shared__ float sm[];
    float* in_s  = sm;                          // 64*90
    float* w1_s  = sm + 64 * 90;                // 86*136
    float* hid_s = sm + 64 * 90 + 86 * 136;     // 64*133
    float* w2_s  = sm;                          // alias
    int blk = blockIdx.x, tid = threadIdx.x;
    int rg = tid >> 4, cg = tid & 15;
    int r0 = rg * 4, c0 = cg * 9;

    float acc[4][9] = {};
    for (int kc = 0; kc < 6; kc++) {
        __syncthreads();
        for (int e = tid; e < 64 * 86; e += 256) {
            int r = e / 86, kk = e - r * 86;
            in_s[r * 90 + kk] = g_hp[(blk * 64 + r) * 516 + kc * 86 + kk];
        }
        for (int e = tid; e < 86 * 129; e += 256) {
            int i = e / 129, c = e - i * 129;
            w1_s[i * 136 + c] = W1[(kc * 86 + i) * 129 + c];
        }
        __syncthreads();
        #pragma unroll 2
        for (int kk = 0; kk < 86; kk++) {
            float a0 = in_s[(r0 + 0) * 90 + kk];
            float a1 = in_s[(r0 + 1) * 90 + kk];
            float a2 = in_s[(r0 + 2) * 90 + kk];
            float a3 = in_s[(r0 + 3) * 90 + kk];
            #pragma unroll
            for (int jj = 0; jj < 9; jj++) {
                float w = w1_s[kk * 136 + c0 + jj];
                acc[0][jj] += a0 * w; acc[1][jj] += a1 * w;
                acc[2][jj] += a2 * w; acc[3][jj] += a3 * w;
            }
        }
    }
    __syncthreads();
    #pragma unroll
    for (int j = 0; j < 4; j++)
        #pragma unroll
        for (int jj = 0; jj < 9; jj++) {
            int c = c0 + jj;
            if (c < Cc) hid_s[(r0 + j) * 133 + c] = fmaxf(acc[j][jj] + b1[c], 0.f);
        }
    __syncthreads();
    for (int e = tid; e < 129 * 129; e += 256) {
        int i = e / 129, c = e - i * 129;
        w2_s[i * 134 + c] = W2[i * 129 + c];
    }
    __syncthreads();

    float acc2[4][9] = {};
    #pragma unroll 2
    for (int i = 0; i < Cc; i++) {
        float a0 = hid_s[(r0 + 0) * 133 + i];
        float a1 = hid_s[(r0 + 1) * 133 + i];
        float a2 = hid_s[(r0 + 2) * 133 + i];
        float a3 = hid_s[(r0 + 3) * 133 + i];
        #pragma unroll
        for (int jj = 0; jj < 9; jj++) {
            float w = w2_s[i * 134 + c0 + jj];
            acc2[0][jj] += a0 * w; acc2[1][jj] += a1 * w;
            acc2[2][jj] += a2 * w; acc2[3][jj] += a3 * w;
        }
    }
    #pragma unroll
    for (int j = 0; j < 4; j++)
        #pragma unroll
        for (int jj = 0; jj < 9; jj++) {
            int c = c0 + jj;
            if (c < Cc) {
                int idx = (blk * 64 + r0 + j) * Cc + c;
                g_combined[idx] = g_combined[idx] + acc2[j][jj] + b2[c];
            }
        }
}

// ---------------- K5: r,u gates; grid (64 mblk, 2 col-half) ----------------
__global__ void __launch_bounds__(256) k_gate_ru(const float* __restrict__ qv,
                                                 const int* __restrict__ nodes_b, const int* __restrict__ nodes_n,
                                                 const float* __restrict__ Wr, const float* __restrict__ br,
                                                 const float* __restrict__ Wu, const float* __restrict__ bu,
                                                 const float* __restrict__ x, const float* __restrict__ hin) {
    extern __shared__ float sm[];
    float* sel_s = sm;                           // 64*130
    float* qv_s  = sel_s + 64 * 130;             // 64*33
    float* z_s   = qv_s + 64 * 33;               // 64*130
    float* wr_s  = z_s + 64 * 130;               // 129*34
    float* wu_s  = wr_s + 129 * 34;              // 129*34
    int blk = blockIdx.x, half = blockIdx.y, tid = threadIdx.x;
    int ob = half * 32;

    for (int e = tid; e < 64 * Cc; e += 256) {
        int lm = e / Cc, i = e - lm * Cc;
        int gm = blk * 64 + lm;
        int node = nodes_b[gm] * Nn + nodes_n[gm];
        sel_s[lm * 130 + i] = g_combined[node * Cc + i];
    }
    for (int e = tid; e < 64 * 32; e += 256) {
        int lm = e >> 5, d = e & 31;
        qv_s[lm * 33 + d] = qv[(blk * 64 + lm) * 32 + d];
    }
    int mg = tid >> 4, og = tid & 15, m0 = mg * 4, o0 = og * 2;
    float ar[4][2] = {}, au[4][2] = {};

    for (int d = 0; d < 32; d++) {
        __syncthreads();
        for (int e = tid; e < 129 * 32; e += 256) {
            int i = e >> 5, o = e & 31;
            wr_s[i * 34 + o] = Wr[(d * Cc + i) * 64 + ob + o];
            wu_s[i * 34 + o] = Wu[(d * Cc + i) * 64 + ob + o];
        }
        for (int e = tid; e < 64 * Cc; e += 256) {
            int lm = e / Cc, i = e - lm * Cc;
            z_s[lm * 130 + i] = qv_s[lm * 33 + d] * sel_s[lm * 130 + i];
        }
        __syncthreads();
        #pragma unroll 3
        for (int i = 0; i < Cc; i++) {
            float z0 = z_s[(m0 + 0) * 130 + i];
            float z1 = z_s[(m0 + 1) * 130 + i];
            float z2 = z_s[(m0 + 2) * 130 + i];
            float z3 = z_s[(m0 + 3) * 130 + i];
            float2 wr2 = *(const float2*)&wr_s[i * 34 + o0];
            float2 wu2 = *(const float2*)&wu_s[i * 34 + o0];
            ar[0][0] += z0 * wr2.x; ar[0][1] += z0 * wr2.y;
            ar[1][0] += z1 * wr2.x; ar[1][1] += z1 * wr2.y;
            ar[2][0] += z2 * wr2.x; ar[2][1] += z2 * wr2.y;
            ar[3][0] += z3 * wr2.x; ar[3][1] += z3 * wr2.y;
            au[0][0] += z0 * wu2.x; au[0][1] += z0 * wu2.y;
            au[1][0] += z1 * wu2.x; au[1][1] += z1 * wu2.y;
            au[2][0] += z2 * wu2.x; au[2][1] += z2 * wu2.y;
            au[3][0] += z3 * wu2.x; au[3][1] += z3 * wu2.y;
        }
    }
    #pragma unroll 4
    for (int d = 0; d < 32; d++) {
        float2 b2r = *(const float2*)&br[d * 64 + ob + o0];
        float2 b2u = *(const float2*)&bu[d * 64 + ob + o0];
        #pragma unroll
        for (int j = 0; j < 4; j++) {
            float q = qv_s[(m0 + j) * 33 + d];
            ar[j][0] += q * b2r.x; ar[j][1] += q * b2r.y;
            au[j][0] += q * b2u.x; au[j][1] += q * b2u.y;
        }
    }
    #pragma unroll
    for (int j = 0; j < 4; j++) {
        int gm = blk * 64 + m0 + j;
        int node = nodes_b[gm] * Nn + nodes_n[gm];
        #pragma unroll
        for (int t = 0; t < 2; t++) {
            int o = ob + o0 + t;
            float hv = hin[node * 64 + o];
            float r = 1.f / (1.f + __expf(-ar[j][t]));
            float u = 1.f / (1.f + __expf(-au[j][t]));
            float hn = r * hv;
            g_hn[gm * 64 + o] = hn;
            g_u[gm * 64 + o] = u;
            g_sel2[gm * Cc + 65 + o] = hn;
        }
    }
    if (half == 0) {
        for (int e = tid; e < 64 * 65; e += 256) {
            int lm = e / 65, i = e - lm * 65;
            int gm = blk * 64 + lm;
            int node = nodes_b[gm] * Nn + nodes_n[gm];
            g_sel2[gm * Cc + i] = x[node * 65 + i];
        }
    }
}

// ---------------- K6: cand gate + final update; grid (64, 2) ----------------
__global__ void __launch_bounds__(256) k_gate_c(const float* __restrict__ qv,
                                                const float* __restrict__ Wc, const float* __restrict__ bc,
                                                float* __restrict__ out) {
    extern __shared__ float sm[];
    float* sel_s = sm;                           // 64*130
    float* qv_s  = sel_s + 64 * 130;             // 64*33
    float* z_s   = qv_s + 64 * 33;               // 64*130
    float* wc_s  = z_s + 64 * 130;               // 129*34
    int blk = blockIdx.x, half = blockIdx.y, tid = threadIdx.x;
    int ob = half * 32;

    for (int e = tid; e < 64 * Cc; e += 256) {
        int lm = e / Cc, i = e - lm * Cc;
        sel_s[lm * 130 + i] = g_sel2[(blk * 64 + lm) * Cc + i];
    }
    for (int e = tid; e < 64 * 32; e += 256) {
        int lm = e >> 5, d = e & 31;
        qv_s[lm * 33 + d] = qv[(blk * 64 + lm) * 32 + d];
    }
    int mg = tid >> 4, og = tid & 15, m0 = mg * 4, o0 = og * 2;
    float ac[4][2] = {};

    for (int d = 0; d < 32; d++) {
        __syncthreads();
        for (int e = tid; e < 129 * 32; e += 256) {
            int i = e >> 5, o = e & 31;
            wc_s[i * 34 + o] = Wc[(d * Cc + i) * 64 + ob + o];
        }
        for (int e = tid; e < 64 * Cc; e += 256) {
            int lm = e / Cc, i = e - lm * Cc;
            z_s[lm * 130 + i] = qv_s[lm * 33 + d] * sel_s[lm * 130 + i];
        }
        __syncthreads();
        #pragma unroll 3
        for (int i = 0; i < Cc; i++) {
            float z0 = z_s[(m0 + 0) * 130 + i];
            float z1 = z_s[(m0 + 1) * 130 + i];
            float z2 = z_s[(m0 + 2) * 130 + i];
            float z3 = z_s[(m0 + 3) * 130 + i];
            float2 w2 = *(const float2*)&wc_s[i * 34 + o0];
            ac[0][0] += z0 * w2.x; ac[0][1] += z0 * w2.y;
            ac[1][0] += z1 * w2.x; ac[1][1] += z1 * w2.y;
            ac[2][0] += z2 * w2.x; ac[2][1] += z2 * w2.y;
            ac[3][0] += z3 * w2.x; ac[3][1] += z3 * w2.y;
        }
    }
    #pragma unroll 4
    for (int d = 0; d < 32; d++) {
        float2 b2 = *(const float2*)&bc[d * 64 + ob + o0];
        #pragma unroll
        for (int j = 0; j < 4; j++) {
            float q = qv_s[(m0 + j) * 33 + d];
            ac[j][0] += q * b2.x; ac[j][1] += q * b2.y;
        }
    }
    #pragma unroll
    for (int j = 0; j < 4; j++) {
        int gm = blk * 64 + m0 + j;
        #pragma unroll
        for (int t = 0; t < 2; t++) {
            int o = ob + o0 + t;
            float cand = tanhf(ac[j][t]);
            float u = g_u[gm * 64 + o];
            float hn = g_hn[gm * 64 + o];
            out[gm * 64 + o] = (1.f - u) * hn + u * cand;
        }
    }
}

// ---------------- launch ----------------
extern "C" void kernel_launch(void* const* d_in, const int* in_sizes, int n_in,
                              void* d_out, int out_size) {
    const float* x   = (const float*)d_in[0];
    const float* h   = (const float*)d_in[1];
    const float* qv  = (const float*)d_in[2];
    const int*   adj = (const int*)  d_in[3];
    const int*   nb  = (const int*)  d_in[4];
    const int*   nn  = (const int*)  d_in[5];
    const float* Wq  = (const float*)d_in[6];
    const float* bq  = (const float*)d_in[7];
    const float* Wk  = (const float*)d_in[8];
    const float* bk  = (const float*)d_in[9];
    const float* Wv  = (const float*)d_in[10];
    const float* bv  = (const float*)d_in[11];
    const float* W1  = (const float*)d_in[12];
    const float* b1  = (const float*)d_in[13];
    const float* W2  = (const float*)d_in[14];
    const float* b2  = (const float*)d_in[15];
    const float* Wr  = (const float*)d_in[16];
    const float* br  = (const float*)d_in[17];
    const float* Wu  = (const float*)d_in[18];
    const float* bu  = (const float*)d_in[19];
    const float* Wc  = (const float*)d_in[20];
    const float* bc  = (const float*)d_in[21];
    float* out = (float*)d_out;

    const int SZ_V  = (64 * 132 + 129 * 136 + 16) * 4;
    const int SZ_A  = (16 * 68 * 2 + 64 * 68 + 64 * 132 + 16) * 4;
    const int SZ_M  = (64 * 90 + 86 * 136 + 64 * 133 + 16) * 4;
    const int SZ_RU = (64 * 130 + 64 * 33 + 64 * 130 + 2 * 129 * 34 + 16) * 4;
    const int SZ_C  = (64 * 130 + 64 * 33 + 64 * 130 + 129 * 34 + 16) * 4;

    cudaFuncSetAttribute(k_v,       cudaFuncAttributeMaxDynamicSharedMemorySize, SZ_V);
    cudaFuncSetAttribute(k_attn,    cudaFuncAttributeMaxDynamicSharedMemorySize, SZ_A);
    cudaFuncSetAttribute(k_mlp,     cudaFuncAttributeMaxDynamicSharedMemorySize, SZ_M);
    cudaFuncSetAttribute(k_gate_ru, cudaFuncAttributeMaxDynamicSharedMemorySize, SZ_RU);
    cudaFuncSetAttribute(k_gate_c,  cudaFuncAttributeMaxDynamicSharedMemorySize, SZ_C);

    k_combined<<<(ROWS * Cc + 255) / 256, 256>>>(x, h);
    k_qk<<<(Hh * ROWS * Kk) / 256, 256>>>(Wq, bq, Wk, bk);
    k_v<<<dim3(128, 4), 256, SZ_V>>>(Wv, bv);
    k_attn<<<dim3(32, 8, 4), 256, SZ_A>>>(adj);
    k_comb<<<(ROWS * 516 + 255) / 256, 256>>>();
    k_mlp<<<128, 256, SZ_M>>>(W1, b1, W2, b2);
    k_gate_ru<<<dim3(64, 2), 256, SZ_RU>>>(qv, nb, nn, Wr, br, Wu, bu, x, h);
    k_gate_c<<<dim3(64, 2), 256, SZ_C>>>(qv, Wc, bc, out);
}

// round 3
// speedup vs baseline: 1.6084x; 1.1256x over previous
#include <cuda_runtime.h>
#include <math.h>

#define Bb   8
#define Nn   1024
#define Dd   64
#define Hh   4
#define Cc   129
#define Kk   16
#define Mm   4096
#define ROWS 8192   // B*N
#define VST  132    // padded v row stride

// ---------------- packed f32x2 helpers (sm_100a+) ----------------
__device__ __forceinline__ unsigned long long ffma2(unsigned long long a, unsigned long long b,
                                                    unsigned long long c) {
    unsigned long long d;
    asm("fma.rn.f32x2 %0, %1, %2, %3;" : "=l"(d) : "l"(a), "l"(b), "l"(c));
    return d;
}
__device__ __forceinline__ unsigned long long pack2(float x) {
    unsigned long long r;
    asm("mov.b64 %0, {%1, %1};" : "=l"(r) : "f"(x));
    return r;
}
__device__ __forceinline__ float2 unpack2(unsigned long long v) {
    float2 f;
    asm("mov.b64 {%0, %1}, %2;" : "=f"(f.x), "=f"(f.y) : "l"(v));
    return f;
}

// ---------------- scratch ----------------
__device__ float g_combined[ROWS * Cc];
__device__ float g_q[Hh * ROWS * Kk];
__device__ float g_k[Hh * ROWS * Kk];
__device__ float g_v[Hh * ROWS * VST];       // padded
__device__ float g_hp0[ROWS * Hh * Cc];      // partial (m-half 0), unnormalized
__device__ float g_hp1[ROWS * Hh * Cc];      // partial (m-half 1), unnormalized
__device__ float g_lp[2][Hh * ROWS];         // partial row sums
__device__ float g_hn[Mm * Dd];
__device__ float g_u[Mm * Dd];
__device__ float g_sel2[Mm * Cc];

// ---------------- K0: combined = concat(x, h) ----------------
__global__ void k_combined(const float* __restrict__ x, const float* __restrict__ h) {
    int idx = blockIdx.x * 256 + threadIdx.x;
    if (idx >= ROWS * Cc) return;
    int row = idx / Cc, c = idx - row * Cc;
    g_combined[idx] = (c < 65) ? x[row * 65 + c] : h[row * 64 + (c - 65)];
}

// ---------------- K1: q, k projections ----------------
__global__ void __launch_bounds__(256) k_qk(const float* __restrict__ Wq, const float* __restrict__ bq,
                                            const float* __restrict__ Wk, const float* __restrict__ bk) {
    int t = blockIdx.x * 256 + threadIdx.x;
    int kk  = t & 15;
    int row = (t >> 4) & (ROWS - 1);
    int hh  = t >> 17;
    const float* comb = g_combined + row * Cc;
    const float* wq = Wq + hh * Cc * Kk + kk;
    const float* wk = Wk + hh * Cc * Kk + kk;
    float aq = bq[hh * 16 + kk], ak = bk[hh * 16 + kk];
    #pragma unroll 4
    for (int i = 0; i < Cc; i++) {
        float cv = comb[i];
        aq += cv * wq[i * 16];
        ak += cv * wk[i * 16];
    }
    g_q[t] = aq;
    g_k[t] = ak;
}

// ---------------- K2: v projection (tiled GEMM, padded output) ----------------
__global__ void __launch_bounds__(256) k_v(const float* __restrict__ Wv, const float* __restrict__ bv) {
    extern __shared__ float sm[];
    float* comb_s = sm;                 // 64*132
    float* w_s    = sm + 64 * 132;      // 129*136
    int tile = blockIdx.x, hh = blockIdx.y, tid = threadIdx.x;

    for (int e = tid; e < 64 * Cc; e += 256) {
        int r = e / Cc, c = e - r * Cc;
        comb_s[r * 132 + c] = g_combined[(tile * 64 + r) * Cc + c];
    }
    for (int e = tid; e < Cc * Cc; e += 256) {
        int i = e / Cc, c = e - i * Cc;
        w_s[i * 136 + c] = Wv[(hh * Cc + i) * Cc + c];
    }
    __syncthreads();

    int rg = tid >> 4, cg = tid & 15;
    int r0 = rg * 4, c0 = cg * 9;
    float acc[4][9] = {};
    #pragma unroll 2
    for (int i = 0; i < Cc; i++) {
        float a0 = comb_s[(r0 + 0) * 132 + i];
        float a1 = comb_s[(r0 + 1) * 132 + i];
        float a2 = comb_s[(r0 + 2) * 132 + i];
        float a3 = comb_s[(r0 + 3) * 132 + i];
        #pragma unroll
        for (int jj = 0; jj < 9; jj++) {
            float w = w_s[i * 136 + c0 + jj];
            acc[0][jj] += a0 * w; acc[1][jj] += a1 * w;
            acc[2][jj] += a2 * w; acc[3][jj] += a3 * w;
        }
    }
    #pragma unroll
    for (int j = 0; j < 4; j++)
        #pragma unroll
        for (int jj = 0; jj < 9; jj++) {
            int c = c0 + jj;
            if (c < Cc)
                g_v[(hh * ROWS + tile * 64 + r0 + j) * VST + c] = acc[j][jj] + bv[hh * Cc + c];
        }
}

// ---------------- K3: fused attention; m-halves; f32x2 p@v ----------------
__global__ void __launch_bounds__(256, 3) k_attn(const int* __restrict__ adj) {
    extern __shared__ float sm[];
    float* qT = sm;                 // [16][68]
    float* kT = sm + 16 * 68;       // [16][68]
    float* pS = sm + 2 * 16 * 68;   // [64][68]
    float* vS = pS + 64 * 68;       // [64][132]

    int bx = blockIdx.x;
    int half = bx & 1, ntile = bx >> 1;
    int b = blockIdx.y, hh = blockIdx.z;
    int tid = threadIdx.x;
    int base_row = b * Nn + ntile * 64;

    for (int e = tid; e < 64 * 16; e += 256) {
        int r = e >> 4, kk = e & 15;
        qT[kk * 68 + r] = g_q[(hh * ROWS + base_row + r) * 16 + kk];
    }

    int rg = tid >> 4, cg = tid & 15;
    int r0 = rg * 4;
    int m0s = cg * 4;
    int c0  = cg * 8;

    unsigned long long acc2[4][4] = {};
    float accX[4] = {};
    float lsum[4] = {};

    for (int cchunk = 0; cchunk < 8; cchunk++) {
        int m0g = half * 512 + cchunk * 64;
        __syncthreads();
        for (int e = tid; e < 64 * 16; e += 256) {
            int m = e >> 4, kk = e & 15;
            kT[kk * 68 + m] = g_k[(hh * ROWS + b * Nn + m0g + m) * 16 + kk];
        }
        for (int e = tid; e < 64 * 33; e += 256) {
            int m = e / 33, c4 = (e - m * 33) * 4;
            *(float4*)&vS[m * 132 + c4] =
                *(const float4*)&g_v[(hh * ROWS + b * Nn + m0g + m) * VST + c4];
        }
        __syncthreads();

        // scores 4x4
        float sc[4][4] = {};
        #pragma unroll
        for (int kk = 0; kk < 16; kk++) {
            float4 q4 = *(const float4*)&qT[kk * 68 + r0];
            float4 k4 = *(const float4*)&kT[kk * 68 + m0s];
            sc[0][0] += q4.x * k4.x; sc[0][1] += q4.x * k4.y; sc[0][2] += q4.x * k4.z; sc[0][3] += q4.x * k4.w;
            sc[1][0] += q4.y * k4.x; sc[1][1] += q4.y * k4.y; sc[1][2] += q4.y * k4.z; sc[1][3] += q4.y * k4.w;
            sc[2][0] += q4.z * k4.x; sc[2][1] += q4.z * k4.y; sc[2][2] += q4.z * k4.z; sc[2][3] += q4.z * k4.w;
            sc[3][0] += q4.w * k4.x; sc[3][1] += q4.w * k4.y; sc[3][2] += q4.w * k4.z; sc[3][3] += q4.w * k4.w;
        }
        #pragma unroll
        for (int j = 0; j < 4; j++) {
            int4 a4 = *(const int4*)&adj[(ntile * 64 + r0 + j) * Nn + m0g + m0s];
            float4 pr; float s;
            s = sc[j][0] * 0.25f; s = s > 0.f ? s : 0.2f * s; pr.x = a4.x ? __expf(s) : 0.f;
            s = sc[j][1] * 0.25f; s = s > 0.f ? s : 0.2f * s; pr.y = a4.y ? __expf(s) : 0.f;
            s = sc[j][2] * 0.25f; s = s > 0.f ? s : 0.2f * s; pr.z = a4.z ? __expf(s) : 0.f;
            s = sc[j][3] * 0.25f; s = s > 0.f ? s : 0.2f * s; pr.w = a4.w ? __expf(s) : 0.f;
            *(float4*)&pS[(r0 + j) * 68 + m0s] = pr;
        }
        __syncthreads();

        // p @ v with packed f32x2
        for (int mq = 0; mq < 64; mq += 4) {
            float pv[4][4];
            #pragma unroll
            for (int j = 0; j < 4; j++)
                *(float4*)pv[j] = *(const float4*)&pS[(r0 + j) * 68 + mq];
            if (cg == 0) {
                #pragma unroll
                for (int j = 0; j < 4; j++)
                    lsum[j] += pv[j][0] + pv[j][1] + pv[j][2] + pv[j][3];
            }
            #pragma unroll
            for (int t = 0; t < 4; t++) {
                ulonglong2 va = *(const ulonglong2*)&vS[(mq + t) * 132 + c0];
                ulonglong2 vb = *(const ulonglong2*)&vS[(mq + t) * 132 + c0 + 4];
                #pragma unroll
                for (int j = 0; j < 4; j++) {
                    unsigned long long pp = pack2(pv[j][t]);
                    acc2[j][0] = ffma2(pp, va.x, acc2[j][0]);
                    acc2[j][1] = ffma2(pp, va.y, acc2[j][1]);
                    acc2[j][2] = ffma2(pp, vb.x, acc2[j][2]);
                    acc2[j][3] = ffma2(pp, vb.y, acc2[j][3]);
                }
                if (cg == 15) {
                    float vx = vS[(mq + t) * 132 + 128];
                    #pragma unroll
                    for (int j = 0; j < 4; j++) accX[j] += pv[j][t] * vx;
                }
            }
        }
    }

    float* hpdst = half ? g_hp1 : g_hp0;
    #pragma unroll
    for (int j = 0; j < 4; j++) {
        int row = base_row + r0 + j;
        #pragma unroll
        for (int p = 0; p < 4; p++) {
            float2 f = unpack2(acc2[j][p]);
            hpdst[row * 516 + hh * Cc + c0 + 2 * p]     = f.x;
            hpdst[row * 516 + hh * Cc + c0 + 2 * p + 1] = f.y;
        }
        if (cg == 15) hpdst[row * 516 + hh * Cc + 128] = accX[j];
        if (cg == 0)  g_lp[half][hh * ROWS + row] = lsum[j];
    }
}

// ---------------- K4: attention MLP + skip (folds partial combine + normalize) ----------------
__global__ void __launch_bounds__(256) k_mlp(const float* __restrict__ W1, const float* __restrict__ b1,
                                             const float* __restrict__ W2, const float* __restrict__ b2) {
    extern __shared__ float sm[];
    float* in_s  = sm;                          // 64*90
    float* w1_s  = sm + 64 * 90;                // 86*136
    float* hid_s = sm + 64 * 90 + 86 * 136;     // 64*133
    float* linv  = hid_s + 64 * 133;            // 64*4
    float* w2_s  = sm;                          // alias over in_s+w1_s
    int blk = blockIdx.x, tid = threadIdx.x;
    int rg = tid >> 4, cg = tid & 15;
    int r0 = rg * 4, c0 = cg * 9;

    if (tid < 256) {
        int e = tid;
        if (e < 256) {
            int r = e >> 2, hh = e & 3;
            int row = blk * 64 + r;
            linv[e] = 1.f / (g_lp[0][hh * ROWS + row] + g_lp[1][hh * ROWS + row]);
        }
    }
    __syncthreads();

    float acc[4][9] = {};
    for (int kc = 0; kc < 6; kc++) {
        __syncthreads();
        for (int e = tid; e < 64 * 86; e += 256) {
            int r = e / 86, kk = e - r * 86;
            int c = kc * 86 + kk;
            int hh = (c >= 387) ? 3 : (c >= 258) ? 2 : (c >= 129) ? 1 : 0;
            int idx = (blk * 64 + r) * 516 + c;
            in_s[r * 90 + kk] = (g_hp0[idx] + g_hp1[idx]) * linv[r * 4 + hh];
        }
        for (int e = tid; e < 86 * 129; e += 256) {
            int i = e / 129, c = e - i * 129;
            w1_s[i * 136 + c] = W1[(kc * 86 + i) * 129 + c];
        }
        __syncthreads();
        #pragma unroll 2
        for (int kk = 0; kk < 86; kk++) {
            float a0 = in_s[(r0 + 0) * 90 + kk];
            float a1 = in_s[(r0 + 1) * 90 + kk];
            float a2 = in_s[(r0 + 2) * 90 + kk];
            float a3 = in_s[(r0 + 3) * 90 + kk];
            #pragma unroll
            for (int jj = 0; jj < 9; jj++) {
                float w = w1_s[kk * 136 + c0 + jj];
                acc[0][jj] += a0 * w; acc[1][jj] += a1 * w;
                acc[2][jj] += a2 * w; acc[3][jj] += a3 * w;
            }
        }
    }
    __syncthreads();
    #pragma unroll
    for (int j = 0; j < 4; j++)
        #pragma unroll
        for (int jj = 0; jj < 9; jj++) {
            int c = c0 + jj;
            if (c < Cc) hid_s[(r0 + j) * 133 + c] = fmaxf(acc[j][jj] + b1[c], 0.f);
        }
    __syncthreads();
    for (int e = tid; e < 129 * 129; e += 256) {
        int i = e / 129, c = e - i * 129;
        w2_s[i * 134 + c] = W2[i * 129 + c];
    }
    __syncthreads();

    float acc2[4][9] = {};
    #pragma unroll 2
    for (int i = 0; i < Cc; i++) {
        float a0 = hid_s[(r0 + 0) * 133 + i];
        float a1 = hid_s[(r0 + 1) * 133 + i];
        float a2 = hid_s[(r0 + 2) * 133 + i];
        float a3 = hid_s[(r0 + 3) * 133 + i];
        #pragma unroll
        for (int jj = 0; jj < 9; jj++) {
            float w = w2_s[i * 134 + c0 + jj];
            acc2[0][jj] += a0 * w; acc2[1][jj] += a1 * w;
            acc2[2][jj] += a2 * w; acc2[3][jj] += a3 * w;
        }
    }
    #pragma unroll
    for (int j = 0; j < 4; j++)
        #pragma unroll
        for (int jj = 0; jj < 9; jj++) {
            int c = c0 + jj;
            if (c < Cc) {
                int idx = (blk * 64 + r0 + j) * Cc + c;
                g_combined[idx] = g_combined[idx] + acc2[j][jj] + b2[c];
            }
        }
}

// ---------------- K5: r,u gates (no z_s; factored per-d dot; 512 threads) ----------------
__global__ void __launch_bounds__(512) k_gate_ru(const float* __restrict__ qv,
                                                 const int* __restrict__ nodes_b, const int* __restrict__ nodes_n,
                                                 const float* __restrict__ Wr, const float* __restrict__ br,
                                                 const float* __restrict__ Wu, const float* __restrict__ bu,
                                                 const float* __restrict__ x, const float* __restrict__ hin) {
    extern __shared__ float sm[];
    float* sel_s = sm;                           // 64*130
    float* qv_s  = sel_s + 64 * 130;             // 64*33
    float* wr_s  = qv_s + 64 * 33;               // 129*34
    float* wu_s  = wr_s + 129 * 34;              // 129*34
    int blk = blockIdx.x, half = blockIdx.y, tid = threadIdx.x;
    int ob = half * 32;

    for (int e = tid; e < 64 * Cc; e += 512) {
        int lm = e / Cc, i = e - lm * Cc;
        int gm = blk * 64 + lm;
        int node = nodes_b[gm] * Nn + nodes_n[gm];
        sel_s[lm * 130 + i] = g_combined[node * Cc + i];
    }
    for (int e = tid; e < 64 * 32; e += 512) {
        int lm = e >> 5, d = e & 31;
        qv_s[lm * 33 + d] = qv[(blk * 64 + lm) * 32 + d];
    }
    int mg = tid >> 4, og = tid & 15;     // 32 x 16
    int m0 = mg * 2, o0 = og * 2;
    unsigned long long ar2[2] = {}, au2[2] = {};

    for (int d = 0; d < 32; d++) {
        __syncthreads();
        for (int e = tid; e < 129 * 32; e += 512) {
            int i = e >> 5, o = e & 31;
            wr_s[i * 34 + o] = Wr[(d * Cc + i) * 64 + ob + o];
            wu_s[i * 34 + o] = Wu[(d * Cc + i) * 64 + ob + o];
        }
        __syncthreads();
        unsigned long long tr0 = 0, tr1 = 0, tu0 = 0, tu1 = 0;
        #pragma unroll 3
        for (int i = 0; i < Cc; i++) {
            unsigned long long s0 = pack2(sel_s[(m0 + 0) * 130 + i]);
            unsigned long long s1 = pack2(sel_s[(m0 + 1) * 130 + i]);
            unsigned long long wr = *(const unsigned long long*)&wr_s[i * 34 + o0];
            unsigned long long wu = *(const unsigned long long*)&wu_s[i * 34 + o0];
            tr0 = ffma2(s0, wr, tr0); tr1 = ffma2(s1, wr, tr1);
            tu0 = ffma2(s0, wu, tu0); tu1 = ffma2(s1, wu, tu1);
        }
        unsigned long long q0 = pack2(qv_s[(m0 + 0) * 33 + d]);
        unsigned long long q1 = pack2(qv_s[(m0 + 1) * 33 + d]);
        ar2[0] = ffma2(q0, tr0, ar2[0]); ar2[1] = ffma2(q1, tr1, ar2[1]);
        au2[0] = ffma2(q0, tu0, au2[0]); au2[1] = ffma2(q1, tu1, au2[1]);
    }
    // bias: += qv @ b
    #pragma unroll 4
    for (int d = 0; d < 32; d++) {
        unsigned long long bR = *(const unsigned long long*)&br[d * 64 + ob + o0];
        unsigned long long bU = *(const unsigned long long*)&bu[d * 64 + ob + o0];
        unsigned long long q0 = pack2(qv_s[(m0 + 0) * 33 + d]);
        unsigned long long q1 = pack2(qv_s[(m0 + 1) * 33 + d]);
        ar2[0] = ffma2(q0, bR, ar2[0]); ar2[1] = ffma2(q1, bR, ar2[1]);
        au2[0] = ffma2(q0, bU, au2[0]); au2[1] = ffma2(q1, bU, au2[1]);
    }
    #pragma unroll
    for (int j = 0; j < 2; j++) {
        int gm = blk * 64 + m0 + j;
        int node = nodes_b[gm] * Nn + nodes_n[gm];
        float2 arf = unpack2(ar2[j]);
        float2 auf = unpack2(au2[j]);
        float av[2] = {arf.x, arf.y}, uv[2] = {auf.x, auf.y};
        #pragma unroll
        for (int t = 0; t < 2; t++) {
            int o = ob + o0 + t;
            float hv = hin[node * 64 + o];
            float r = 1.f / (1.f + __expf(-av[t]));
            float u = 1.f / (1.f + __expf(-uv[t]));
            float hn = r * hv;
            g_hn[gm * 64 + o] = hn;
            g_u[gm * 64 + o] = u;
            g_sel2[gm * Cc + 65 + o] = hn;
        }
    }
    if (half == 0) {
        for (int e = tid; e < 64 * 65; e += 512) {
            int lm = e / 65, i = e - lm * 65;
            int gm = blk * 64 + lm;
            int node = nodes_b[gm] * Nn + nodes_n[gm];
            g_sel2[gm * Cc + i] = x[node * 65 + i];
        }
    }
}

// ---------------- K6: cand gate + final update ----------------
__global__ void __launch_bounds__(512) k_gate_c(const float* __restrict__ qv,
                                                const float* __restrict__ Wc, const float* __restrict__ bc,
                                                float* __restrict__ out) {
    extern __shared__ float sm[];
    float* sel_s = sm;                           // 64*130
    float* qv_s  = sel_s + 64 * 130;             // 64*33
    float* wc_s  = qv_s + 64 * 33;               // 129*34
    int blk = blockIdx.x, half = blockIdx.y, tid = threadIdx.x;
    int ob = half * 32;

    for (int e = tid; e < 64 * Cc; e += 512) {
        int lm = e / Cc, i = e - lm * Cc;
        sel_s[lm * 130 + i] = g_sel2[(blk * 64 + lm) * Cc + i];
    }
    for (int e = tid; e < 64 * 32; e += 512) {
        int lm = e >> 5, d = e & 31;
        qv_s[lm * 33 + d] = qv[(blk * 64 + lm) * 32 + d];
    }
    int mg = tid >> 4, og = tid & 15;
    int m0 = mg * 2, o0 = og * 2;
    unsigned long long ac2[2] = {};

    for (int d = 0; d < 32; d++) {
        __syncthreads();
        for (int e = tid; e < 129 * 32; e += 512) {
            int i = e >> 5, o = e & 31;
            wc_s[i * 34 + o] = Wc[(d * Cc + i) * 64 + ob + o];
        }
        __syncthreads();
        unsigned long long t0 = 0, t1 = 0;
        #pragma unroll 3
        for (int i = 0; i < Cc; i++) {
            unsigned long long s0 = pack2(sel_s[(m0 + 0) * 130 + i]);
            unsigned long long s1 = pack2(sel_s[(m0 + 1) * 130 + i]);
            unsigned long long w = *(const unsigned long long*)&wc_s[i * 34 + o0];
            t0 = ffma2(s0, w, t0); t1 = ffma2(s1, w, t1);
        }
        unsigned long long q0 = pack2(qv_s[(m0 + 0) * 33 + d]);
        unsigned long long q1 = pack2(qv_s[(m0 + 1) * 33 + d]);
        ac2[0] = ffma2(q0, t0, ac2[0]); ac2[1] = ffma2(q1, t1, ac2[1]);
    }
    #pragma unroll 4
    for (int d = 0; d < 32; d++) {
        unsigned long long bC = *(const unsigned long long*)&bc[d * 64 + ob + o0];
        unsigned long long q0 = pack2(qv_s[(m0 + 0) * 33 + d]);
        unsigned long long q1 = pack2(qv_s[(m0 + 1) * 33 + d]);
        ac2[0] = ffma2(q0, bC, ac2[0]); ac2[1] = ffma2(q1, bC, ac2[1]);
    }
    #pragma unroll
    for (int j = 0; j < 2; j++) {
        int gm = blk * 64 + m0 + j;
        float2 acf = unpack2(ac2[j]);
        float av[2] = {acf.x, acf.y};
        #pragma unroll
        for (int t = 0; t < 2; t++) {
            int o = ob + o0 + t;
            float cand = tanhf(av[t]);
            float u = g_u[gm * 64 + o];
            float hn = g_hn[gm * 64 + o];
            out[gm * 64 + o] = (1.f - u) * hn + u * cand;
        }
    }
}

// ---------------- launch ----------------
extern "C" void kernel_launch(void* const* d_in, const int* in_sizes, int n_in,
                              void* d_out, int out_size) {
    const float* x   = (const float*)d_in[0];
    const float* h   = (const float*)d_in[1];
    const float* qv  = (const float*)d_in[2];
    const int*   adj = (const int*)  d_in[3];
    const int*   nb  = (const int*)  d_in[4];
    const int*   nn  = (const int*)  d_in[5];
    const float* Wq  = (const float*)d_in[6];
    const float* bq  = (const float*)d_in[7];
    const float* Wk  = (const float*)d_in[8];
    const float* bk  = (const float*)d_in[9];
    const float* Wv  = (const float*)d_in[10];
    const float* bv  = (const float*)d_in[11];
    const float* W1  = (const float*)d_in[12];
    const float* b1  = (const float*)d_in[13];
    const float* W2  = (const float*)d_in[14];
    const float* b2  = (const float*)d_in[15];
    const float* Wr  = (const float*)d_in[16];
    const float* br  = (const float*)d_in[17];
    const float* Wu  = (const float*)d_in[18];
    const float* bu  = (const float*)d_in[19];
    const float* Wc  = (const float*)d_in[20];
    const float* bc  = (const float*)d_in[21];
    float* out = (float*)d_out;

    const int SZ_V  = (64 * 132 + 129 * 136 + 16) * 4;
    const int SZ_A  = (16 * 68 * 2 + 64 * 68 + 64 * 132 + 16) * 4;
    const int SZ_M  = (64 * 90 + 86 * 136 + 64 * 133 + 64 * 4 + 16) * 4;
    const int SZ_RU = (64 * 130 + 64 * 33 + 2 * 129 * 34 + 16) * 4;
    const int SZ_C  = (64 * 130 + 64 * 33 + 129 * 34 + 16) * 4;

    cudaFuncSetAttribute(k_v,       cudaFuncAttributeMaxDynamicSharedMemorySize, SZ_V);
    cudaFuncSetAttribute(k_attn,    cudaFuncAttributeMaxDynamicSharedMemorySize, SZ_A);
    cudaFuncSetAttribute(k_mlp,     cudaFuncAttributeMaxDynamicSharedMemorySize, SZ_M);
    cudaFuncSetAttribute(k_gate_ru, cudaFuncAttributeMaxDynamicSharedMemorySize, SZ_RU);
    cudaFuncSetAttribute(k_gate_c,  cudaFuncAttributeMaxDynamicSharedMemorySize, SZ_C);

    k_combined<<<(ROWS * Cc + 255) / 256, 256>>>(x, h);
    k_qk<<<(Hh * ROWS * Kk) / 256, 256>>>(Wq, bq, Wk, bk);
    k_v<<<dim3(128, 4), 256, SZ_V>>>(Wv, bv);
    k_attn<<<dim3(32, 8, 4), 256, SZ_A>>>(adj);
    k_mlp<<<128, 256, SZ_M>>>(W1, b1, W2, b2);
    k_gate_ru<<<dim3(64, 2), 512, SZ_RU>>>(qv, nb, nn, Wr, br, Wu, bu, x, h);
    k_gate_c<<<dim3(64, 2), 512, SZ_C>>>(qv, Wc, bc, out);
}

// round 7
// speedup vs baseline: 2.3999x; 1.4921x over previous
#include <cuda_runtime.h>
#include <cuda_bf16.h>
#include <cstdint>
#include <math.h>

#define Bb   8
#define Nn   1024
#define Dd   64
#define Hh   4
#define Cc   129
#define Kk   16
#define Mm   4096
#define ROWS 8192   // B*N

// ---------------- helpers ----------------
__device__ __forceinline__ uint32_t cvt_bf16x2(float hi, float lo) {
    uint32_t r;
    asm("cvt.rn.bf16x2.f32 %0, %1, %2;" : "=r"(r) : "f"(hi), "f"(lo));
    return r;
}
__device__ __forceinline__ void mma_bf16(float c[4], uint32_t a0, uint32_t a1, uint32_t a2, uint32_t a3,
                                         uint32_t b0, uint32_t b1) {
    asm volatile("mma.sync.aligned.m16n8k16.row.col.f32.bf16.bf16.f32 "
                 "{%0,%1,%2,%3}, {%4,%5,%6,%7}, {%8,%9}, {%0,%1,%2,%3};"
                 : "+f"(c[0]), "+f"(c[1]), "+f"(c[2]), "+f"(c[3])
                 : "r"(a0), "r"(a1), "r"(a2), "r"(a3), "r"(b0), "r"(b1));
}
__device__ __forceinline__ unsigned long long ffma2(unsigned long long a, unsigned long long b,
                                                    unsigned long long c) {
    unsigned long long d;
    asm("fma.rn.f32x2 %0, %1, %2, %3;" : "=l"(d) : "l"(a), "l"(b), "l"(c));
    return d;
}
__device__ __forceinline__ unsigned long long pack2(float x) {
    unsigned long long r;
    asm("mov.b64 %0, {%1, %1};" : "=l"(r) : "f"(x));
    return r;
}
__device__ __forceinline__ float2 unpack2(unsigned long long v) {
    float2 f;
    asm("mov.b64 {%0, %1}, %2;" : "=f"(f.x), "=f"(f.y) : "l"(v));
    return f;
}
__device__ __forceinline__ float expleaky(float s, uint32_t bit) {
    s *= 0.25f;
    s = s > 0.f ? s : 0.2f * s;
    return bit ? __expf(s) : 0.f;
}

// ================= scratch =================
__device__ float g_combined[ROWS * Cc];
__device__ __nv_bfloat16 g_qb[Hh * ROWS * Kk];
__device__ __nv_bfloat16 g_kb[Hh * ROWS * Kk];
__device__ __nv_bfloat16 g_vtb[Hh * Bb * 128 * 1024];   // [h*8+b][c<128][m]
__device__ float g_v128[Hh * Bb * 1024];                // v col 128
__device__ uint32_t g_adjbits[Nn * 32];
__device__ float g_hp[ROWS * 4 * 132];                  // [row][h][132 padded], normalized
__device__ float g_hn[Mm * Dd];
__device__ float g_u[Mm * Dd];
__device__ float g_sel2[Mm * Cc];

// ---------------- K0: combined = concat(x, h) ----------------
__global__ void k_combined(const float* __restrict__ x, const float* __restrict__ h) {
    int idx = blockIdx.x * 256 + threadIdx.x;
    if (idx >= ROWS * Cc) return;
    int row = idx / Cc, c = idx - row * Cc;
    g_combined[idx] = (c < 65) ? x[row * 65 + c] : h[row * 64 + (c - 65)];
}

// ---------------- K0b: pack adjacency bits ----------------
__global__ void k_adjpack(const int* __restrict__ adj) {
    int idx = blockIdx.x * 256 + threadIdx.x;   // < 1024*1024
    uint32_t bits = __ballot_sync(0xFFFFFFFFu, adj[idx] != 0);
    if ((idx & 31) == 0) g_adjbits[idx >> 5] = bits;
}

// ---------------- K1: q, k projections -> bf16 ----------------
__global__ void __launch_bounds__(256) k_qk(const float* __restrict__ Wq, const float* __restrict__ bq,
                                            const float* __restrict__ Wk, const float* __restrict__ bk) {
    int t = blockIdx.x * 256 + threadIdx.x;
    int kk  = t & 15;
    int row = (t >> 4) & (ROWS - 1);
    int hh  = t >> 17;
    const float* comb = g_combined + row * Cc;
    const float* wq = Wq + hh * Cc * Kk + kk;
    const float* wk = Wk + hh * Cc * Kk + kk;
    float aq = bq[hh * 16 + kk], ak = bk[hh * 16 + kk];
    #pragma unroll 4
    for (int i = 0; i < Cc; i++) {
        float cv = comb[i];
        aq += cv * wq[i * 16];
        ak += cv * wk[i * 16];
    }
    g_qb[t] = __float2bfloat16(aq);
    g_kb[t] = __float2bfloat16(ak);
}

// ---------------- K2: v projection -> transposed bf16 + col128 fp32 ----------------
__global__ void __launch_bounds__(256) k_v(const float* __restrict__ Wv, const float* __restrict__ bv) {
    extern __shared__ float sm[];
    float* comb_s = sm;                 // 64*132 (later reused as vtile)
    float* w_s    = sm + 64 * 132;      // 129*136
    int tile = blockIdx.x, hh = blockIdx.y, tid = threadIdx.x;

    for (int e = tid; e < 64 * Cc; e += 256) {
        int r = e / Cc, c = e - r * Cc;
        comb_s[r * 132 + c] = g_combined[(tile * 64 + r) * Cc + c];
    }
    for (int e = tid; e < Cc * Cc; e += 256) {
        int i = e / Cc, c = e - i * Cc;
        w_s[i * 136 + c] = Wv[(hh * Cc + i) * Cc + c];
    }
    __syncthreads();

    int rg = tid >> 4, cg = tid & 15;
    int r0 = rg * 4, c0 = cg * 9;
    float acc[4][9] = {};
    #pragma unroll 2
    for (int i = 0; i < Cc; i++) {
        float a0 = comb_s[(r0 + 0) * 132 + i];
        float a1 = comb_s[(r0 + 1) * 132 + i];
        float a2 = comb_s[(r0 + 2) * 132 + i];
        float a3 = comb_s[(r0 + 3) * 132 + i];
        #pragma unroll
        for (int jj = 0; jj < 9; jj++) {
            float w = w_s[i * 136 + c0 + jj];
            acc[0][jj] += a0 * w; acc[1][jj] += a1 * w;
            acc[2][jj] += a2 * w; acc[3][jj] += a3 * w;
        }
    }
    __syncthreads();   // done reading comb_s; reuse as vtile
    float* vtile = comb_s;
    #pragma unroll
    for (int j = 0; j < 4; j++)
        #pragma unroll
        for (int jj = 0; jj < 9; jj++) {
            int c = c0 + jj;
            if (c < Cc) vtile[(r0 + j) * 132 + c] = acc[j][jj] + bv[hh * Cc + c];
        }
    __syncthreads();

    int b_idx = tile >> 4;
    int mbase = (tile & 15) * 64;
    size_t hb = hh * 8 + b_idx;
    for (int e = tid; e < 128 * 32; e += 256) {
        int c = e >> 5, mp = e & 31;
        float f0 = vtile[(mp * 2) * 132 + c];
        float f1 = vtile[(mp * 2 + 1) * 132 + c];
        *(__nv_bfloat162*)&g_vtb[(hb * 128 + c) * 1024 + mbase + mp * 2] =
            __float22bfloat162_rn(make_float2(f0, f1));
    }
    for (int e = tid; e < 64; e += 256)
        g_v128[hb * 1024 + mbase + e] = vtile[e * 132 + 128];
}

// ---------------- K3: HMMA (mma.sync bf16) flash attention ----------------
// grid (8 rblk, 8 b, 4 h), 256 threads (8 warps, 16 rows/warp).
#define AKS_OFF 0                      // K chunk: [128 m][12 u32]  = 6144 B
#define AVT_OFF 6144                   // VT chunk: [128 c][68 u32] = 34816 B
#define AV1_OFF (6144 + 34816)         // v128 chunk: 512 B
#define SMEM_ATT (AV1_OFF + 512)

__global__ void __launch_bounds__(256) k_attn_mma() {
    extern __shared__ char smc[];
    uint32_t* Ks  = (uint32_t*)(smc + AKS_OFF);
    uint32_t* VTs = (uint32_t*)(smc + AVT_OFF);
    float*    v1s = (float*)(smc + AV1_OFF);
    int tid = threadIdx.x, w = tid >> 5, lane = tid & 31;
    int g = lane >> 2, t = lane & 3;
    int rblk = blockIdx.x, b = blockIdx.y, hh = blockIdx.z;
    size_t hb = hh * 8 + b;
    int brow = b * 1024 + rblk * 128;

    // Q fragments (per warp, once)
    const __nv_bfloat16* qsrc = g_qb + ((size_t)hh * ROWS + brow + 16 * w) * 16;
    uint32_t qa0 = *(const uint32_t*)(qsrc + g * 16 + 2 * t);
    uint32_t qa1 = *(const uint32_t*)(qsrc + (g + 8) * 16 + 2 * t);
    uint32_t qa2 = *(const uint32_t*)(qsrc + g * 16 + 2 * t + 8);
    uint32_t qa3 = *(const uint32_t*)(qsrc + (g + 8) * 16 + 2 * t + 8);

    int nrow0 = rblk * 128 + 16 * w + g;
    int nrow1 = nrow0 + 8;

    float O[16][4];
    #pragma unroll
    for (int i = 0; i < 16; i++) { O[i][0] = O[i][1] = O[i][2] = O[i][3] = 0.f; }
    float rs0 = 0.f, rs1 = 0.f, ax0 = 0.f, ax1 = 0.f;

    const uint32_t* kbase = (const uint32_t*)(g_kb + ((size_t)hh * ROWS + b * 1024) * 16);
    const __nv_bfloat16* vbase = g_vtb + hb * 131072;

    for (int j = 0; j < 8; j++) {
        __syncthreads();
        // K chunk [128,16] bf16 -> Ks (12-u32 row stride, conflict-free B-frag reads)
        const uint32_t* ks = kbase + j * 128 * 8;
        #pragma unroll
        for (int it = 0; it < 4; it++) {
            int e = tid + 256 * it;
            int r = e >> 3, c8 = e & 7;
            Ks[r * 12 + c8] = ks[e];
        }
        // VT chunk [128 c][128 m] bf16 -> VTs (68-u32 row stride)
        #pragma unroll
        for (int it = 0; it < 8; it++) {
            int e = tid + 256 * it;
            int c = e >> 4, q = e & 15;
            ((uint4*)(smc + AVT_OFF + c * 272))[q] =
                ((const uint4*)(vbase + (size_t)c * 1024 + j * 128))[q];
        }
        if (tid < 128) v1s[tid] = g_v128[hb * 1024 + j * 128 + tid];
        uint4 A0 = ((const uint4*)g_adjbits)[nrow0 * 8 + j];
        uint4 A1 = ((const uint4*)g_adjbits)[nrow1 * 8 + j];
        __syncthreads();

        // GEMM1: S = Q @ K^T (one mma per 8-col tile), epilogue -> A frags of GEMM2
        uint32_t af[8][4];
        #pragma unroll
        for (int nt = 0; nt < 16; nt++) {
            uint32_t b0 = Ks[(8 * nt + g) * 12 + t];
            uint32_t b1 = Ks[(8 * nt + g) * 12 + t + 4];
            float c[4] = {0.f, 0.f, 0.f, 0.f};
            mma_bf16(c, qa0, qa1, qa2, qa3, b0, b1);
            uint32_t wA = (nt < 4) ? A0.x : (nt < 8) ? A0.y : (nt < 12) ? A0.z : A0.w;
            uint32_t wB = (nt < 4) ? A1.x : (nt < 8) ? A1.y : (nt < 12) ? A1.z : A1.w;
            int bitb = ((nt & 3) << 3) + 2 * t;
            float p00 = expleaky(c[0], (wA >> bitb) & 1);
            float p01 = expleaky(c[1], (wA >> (bitb + 1)) & 1);
            float p10 = expleaky(c[2], (wB >> bitb) & 1);
            float p11 = expleaky(c[3], (wB >> (bitb + 1)) & 1);
            rs0 += p00 + p01; rs1 += p10 + p11;
            float2 v2 = *(const float2*)&v1s[8 * nt + 2 * t];
            ax0 += p00 * v2.x + p01 * v2.y;
            ax1 += p10 * v2.x + p11 * v2.y;
            int kc = nt >> 1;
            if ((nt & 1) == 0) {
                af[kc][0] = cvt_bf16x2(p01, p00);
                af[kc][1] = cvt_bf16x2(p11, p10);
            } else {
                af[kc][2] = cvt_bf16x2(p01, p00);
                af[kc][3] = cvt_bf16x2(p11, p10);
            }
        }
        // GEMM2: O += P @ V  (V^T in smem)
        #pragma unroll
        for (int kc = 0; kc < 8; kc++) {
            #pragma unroll
            for (int nt2 = 0; nt2 < 16; nt2++) {
                uint32_t b0 = VTs[(8 * nt2 + g) * 68 + 8 * kc + t];
                uint32_t b1 = VTs[(8 * nt2 + g) * 68 + 8 * kc + t + 4];
                mma_bf16(O[nt2], af[kc][0], af[kc][1], af[kc][2], af[kc][3], b0, b1);
            }
        }
    }

    // reduce rowsum / accX over the 4-lane quad (t dimension)
    rs0 += __shfl_xor_sync(0xFFFFFFFFu, rs0, 1); rs0 += __shfl_xor_sync(0xFFFFFFFFu, rs0, 2);
    rs1 += __shfl_xor_sync(0xFFFFFFFFu, rs1, 1); rs1 += __shfl_xor_sync(0xFFFFFFFFu, rs1, 2);
    ax0 += __shfl_xor_sync(0xFFFFFFFFu, ax0, 1); ax0 += __shfl_xor_sync(0xFFFFFFFFu, ax0, 2);
    ax1 += __shfl_xor_sync(0xFFFFFFFFu, ax1, 1); ax1 += __shfl_xor_sync(0xFFFFFFFFu, ax1, 2);
    float inv0 = 1.f / rs0, inv1 = 1.f / rs1;

    float* d0 = g_hp + ((size_t)(brow + 16 * w + g) * 4 + hh) * 132;
    float* d1 = d0 + 8 * 4 * 132;
    #pragma unroll
    for (int nt2 = 0; nt2 < 16; nt2++) {
        *(float2*)&d0[8 * nt2 + 2 * t] = make_float2(O[nt2][0] * inv0, O[nt2][1] * inv0);
        *(float2*)&d1[8 * nt2 + 2 * t] = make_float2(O[nt2][2] * inv1, O[nt2][3] * inv1);
    }
    if (t == 0) { d0[128] = ax0 * inv0; d1[128] = ax1 * inv1; }
}

// ---------------- K4: attention MLP + skip ----------------
__global__ void __launch_bounds__(256) k_mlp(const float* __restrict__ W1, const float* __restrict__ b1,
                                             const float* __restrict__ W2, const float* __restrict__ b2) {
    extern __shared__ float sm[];
    float* in_s  = sm;                          // 64*90
    float* w1_s  = sm + 64 * 90;                // 86*136
    float* hid_s = sm + 64 * 90 + 86 * 136;     // 64*133
    float* w2_s  = sm;                          // alias
    int blk = blockIdx.x, tid = threadIdx.x;
    int rg = tid >> 4, cg = tid & 15;
    int r0 = rg * 4, c0 = cg * 9;

    float acc[4][9] = {};
    for (int kc = 0; kc < 6; kc++) {
        __syncthreads();
        for (int e = tid; e < 64 * 86; e += 256) {
            int r = e / 86, kk = e - r * 86;
            int c = kc * 86 + kk;
            int hh = c / 129, cc = c - hh * 129;
            in_s[r * 90 + kk] = g_hp[((size_t)(blk * 64 + r) * 4 + hh) * 132 + cc];
        }
        for (int e = tid; e < 86 * 129; e += 256) {
            int i = e / 129, c = e - i * 129;
            w1_s[i * 136 + c] = W1[(kc * 86 + i) * 129 + c];
        }
        __syncthreads();
        #pragma unroll 2
        for (int kk = 0; kk < 86; kk++) {
            float a0 = in_s[(r0 + 0) * 90 + kk];
            float a1 = in_s[(r0 + 1) * 90 + kk];
            float a2 = in_s[(r0 + 2) * 90 + kk];
            float a3 = in_s[(r0 + 3) * 90 + kk];
            #pragma unroll
            for (int jj = 0; jj < 9; jj++) {
                float w = w1_s[kk * 136 + c0 + jj];
                acc[0][jj] += a0 * w; acc[1][jj] += a1 * w;
                acc[2][jj] += a2 * w; acc[3][jj] += a3 * w;
            }
        }
    }
    __syncthreads();
    #pragma unroll
    for (int j = 0; j < 4; j++)
        #pragma unroll
        for (int jj = 0; jj < 9; jj++) {
            int c = c0 + jj;
            if (c < Cc) hid_s[(r0 + j) * 133 + c] = fmaxf(acc[j][jj] + b1[c], 0.f);
        }
    __syncthreads();
    for (int e = tid; e < 129 * 129; e += 256) {
        int i = e / 129, c = e - i * 129;
        w2_s[i * 134 + c] = W2[i * 129 + c];
    }
    __syncthreads();

    float acc2[4][9] = {};
    #pragma unroll 2
    for (int i = 0; i < Cc; i++) {
        float a0 = hid_s[(r0 + 0) * 133 + i];
        float a1 = hid_s[(r0 + 1) * 133 + i];
        float a2 = hid_s[(r0 + 2) * 133 + i];
        float a3 = hid_s[(r0 + 3) * 133 + i];
        #pragma unroll
        for (int jj = 0; jj < 9; jj++) {
            float w = w2_s[i * 134 + c0 + jj];
            acc2[0][jj] += a0 * w; acc2[1][jj] += a1 * w;
            acc2[2][jj] += a2 * w; acc2[3][jj] += a3 * w;
        }
    }
    #pragma unroll
    for (int j = 0; j < 4; j++)
        #pragma unroll
        for (int jj = 0; jj < 9; jj++) {
            int c = c0 + jj;
            if (c < Cc) {
                int idx = (blk * 64 + r0 + j) * Cc + c;
                g_combined[idx] = g_combined[idx] + acc2[j][jj] + b2[c];
            }
        }
}

// ---------------- K5: r,u gates ----------------
__global__ void __launch_bounds__(512) k_gate_ru(const float* __restrict__ qv,
                                                 const int* __restrict__ nodes_b, const int* __restrict__ nodes_n,
                                                 const float* __restrict__ Wr, const float* __restrict__ br,
                                                 const float* __restrict__ Wu, const float* __restrict__ bu,
                                                 const float* __restrict__ x, const float* __restrict__ hin) {
    extern __shared__ float sm[];
    float* sel_s = sm;                           // 64*130
    float* qv_s  = sel_s + 64 * 130;             // 64*33
    float* wr_s  = qv_s + 64 * 33;               // 129*34
    float* wu_s  = wr_s + 129 * 34;              // 129*34
    int blk = blockIdx.x, half = blockIdx.y, tid = threadIdx.x;
    int ob = half * 32;

    for (int e = tid; e < 64 * Cc; e += 512) {
        int lm = e / Cc, i = e - lm * Cc;
        int gm = blk * 64 + lm;
        int node = nodes_b[gm] * Nn + nodes_n[gm];
        sel_s[lm * 130 + i] = g_combined[node * Cc + i];
    }
    for (int e = tid; e < 64 * 32; e += 512) {
        int lm = e >> 5, d = e & 31;
        qv_s[lm * 33 + d] = qv[(blk * 64 + lm) * 32 + d];
    }
    int mg = tid >> 4, og = tid & 15;
    int m0 = mg * 2, o0 = og * 2;
    unsigned long long ar2[2] = {}, au2[2] = {};

    for (int d = 0; d < 32; d++) {
        __syncthreads();
        for (int e = tid; e < 129 * 32; e += 512) {
            int i = e >> 5, o = e & 31;
            wr_s[i * 34 + o] = Wr[(d * Cc + i) * 64 + ob + o];
            wu_s[i * 34 + o] = Wu[(d * Cc + i) * 64 + ob + o];
        }
        __syncthreads();
        unsigned long long tr0 = 0, tr1 = 0, tu0 = 0, tu1 = 0;
        #pragma unroll 3
        for (int i = 0; i < Cc; i++) {
            unsigned long long s0 = pack2(sel_s[(m0 + 0) * 130 + i]);
            unsigned long long s1 = pack2(sel_s[(m0 + 1) * 130 + i]);
            unsigned long long wr = *(const unsigned long long*)&wr_s[i * 34 + o0];
            unsigned long long wu = *(const unsigned long long*)&wu_s[i * 34 + o0];
            tr0 = ffma2(s0, wr, tr0); tr1 = ffma2(s1, wr, tr1);
            tu0 = ffma2(s0, wu, tu0); tu1 = ffma2(s1, wu, tu1);
        }
        unsigned long long q0 = pack2(qv_s[(m0 + 0) * 33 + d]);
        unsigned long long q1 = pack2(qv_s[(m0 + 1) * 33 + d]);
        ar2[0] = ffma2(q0, tr0, ar2[0]); ar2[1] = ffma2(q1, tr1, ar2[1]);
        au2[0] = ffma2(q0, tu0, au2[0]); au2[1] = ffma2(q1, tu1, au2[1]);
    }
    #pragma unroll 4
    for (int d = 0; d < 32; d++) {
        unsigned long long bR = *(const unsigned long long*)&br[d * 64 + ob + o0];
        unsigned long long bU = *(const unsigned long long*)&bu[d * 64 + ob + o0];
        unsigned long long q0 = pack2(qv_s[(m0 + 0) * 33 + d]);
        unsigned long long q1 = pack2(qv_s[(m0 + 1) * 33 + d]);
        ar2[0] = ffma2(q0, bR, ar2[0]); ar2[1] = ffma2(q1, bR, ar2[1]);
        au2[0] = ffma2(q0, bU, au2[0]); au2[1] = ffma2(q1, bU, au2[1]);
    }
    #pragma unroll
    for (int j = 0; j < 2; j++) {
        int gm = blk * 64 + m0 + j;
        int node = nodes_b[gm] * Nn + nodes_n[gm];
        float2 arf = unpack2(ar2[j]);
        float2 auf = unpack2(au2[j]);
        float av[2] = {arf.x, arf.y}, uv[2] = {auf.x, auf.y};
        #pragma unroll
        for (int t = 0; t < 2; t++) {
            int o = ob + o0 + t;
            float hv = hin[node * 64 + o];
            float r = 1.f / (1.f + __expf(-av[t]));
            float u = 1.f / (1.f + __expf(-uv[t]));
            float hn = r * hv;
            g_hn[gm * 64 + o] = hn;
            g_u[gm * 64 + o] = u;
            g_sel2[gm * Cc + 65 + o] = hn;
        }
    }
    if (half == 0) {
        for (int e = tid; e < 64 * 65; e += 512) {
            int lm = e / 65, i = e - lm * 65;
            int gm = blk * 64 + lm;
            int node = nodes_b[gm] * Nn + nodes_n[gm];
            g_sel2[gm * Cc + i] = x[node * 65 + i];
        }
    }
}

// ---------------- K6: cand gate + final update ----------------
__global__ void __launch_bounds__(512) k_gate_c(const float* __restrict__ qv,
                                                const float* __restrict__ Wc, const float* __restrict__ bc,
                                                float* __restrict__ out) {
    extern __shared__ float sm[];
    float* sel_s = sm;                           // 64*130
    float* qv_s  = sel_s + 64 * 130;             // 64*33
    float* wc_s  = qv_s + 64 * 33;               // 129*34
    int blk = blockIdx.x, half = blockIdx.y, tid = threadIdx.x;
    int ob = half * 32;

    for (int e = tid; e < 64 * Cc; e += 512) {
        int lm = e / Cc, i = e - lm * Cc;
        sel_s[lm * 130 + i] = g_sel2[(blk * 64 + lm) * Cc + i];
    }
    for (int e = tid; e < 64 * 32; e += 512) {
        int lm = e >> 5, d = e & 31;
        qv_s[lm * 33 + d] = qv[(blk * 64 + lm) * 32 + d];
    }
    int mg = tid >> 4, og = tid & 15;
    int m0 = mg * 2, o0 = og * 2;
    unsigned long long ac2[2] = {};

    for (int d = 0; d < 32; d++) {
        __syncthreads();
        for (int e = tid; e < 129 * 32; e += 512) {
            int i = e >> 5, o = e & 31;
            wc_s[i * 34 + o] = Wc[(d * Cc + i) * 64 + ob + o];
        }
        __syncthreads();
        unsigned long long t0 = 0, t1 = 0;
        #pragma unroll 3
        for (int i = 0; i < Cc; i++) {
            unsigned long long s0 = pack2(sel_s[(m0 + 0) * 130 + i]);
            unsigned long long s1 = pack2(sel_s[(m0 + 1) * 130 + i]);
            unsigned long long w = *(const unsigned long long*)&wc_s[i * 34 + o0];
            t0 = ffma2(s0, w, t0); t1 = ffma2(s1, w, t1);
        }
        unsigned long long q0 = pack2(qv_s[(m0 + 0) * 33 + d]);
        unsigned long long q1 = pack2(qv_s[(m0 + 1) * 33 + d]);
        ac2[0] = ffma2(q0, t0, ac2[0]); ac2[1] = ffma2(q1, t1, ac2[1]);
    }
    #pragma unroll 4
    for (int d = 0; d < 32; d++) {
        unsigned long long bC = *(const unsigned long long*)&bc[d * 64 + ob + o0];
        unsigned long long q0 = pack2(qv_s[(m0 + 0) * 33 + d]);
        unsigned long long q1 = pack2(qv_s[(m0 + 1) * 33 + d]);
        ac2[0] = ffma2(q0, bC, ac2[0]); ac2[1] = ffma2(q1, bC, ac2[1]);
    }
    #pragma unroll
    for (int j = 0; j < 2; j++) {
        int gm = blk * 64 + m0 + j;
        float2 acf = unpack2(ac2[j]);
        float av[2] = {acf.x, acf.y};
        #pragma unroll
        for (int t = 0; t < 2; t++) {
            int o = ob + o0 + t;
            float cand = tanhf(av[t]);
            float u = g_u[gm * 64 + o];
            float hn = g_hn[gm * 64 + o];
            out[gm * 64 + o] = (1.f - u) * hn + u * cand;
        }
    }
}

// ---------------- launch ----------------
extern "C" void kernel_launch(void* const* d_in, const int* in_sizes, int n_in,
                              void* d_out, int out_size) {
    const float* x   = (const float*)d_in[0];
    const float* h   = (const float*)d_in[1];
    const float* qv  = (const float*)d_in[2];
    const int*   adj = (const int*)  d_in[3];
    const int*   nb  = (const int*)  d_in[4];
    const int*   nn  = (const int*)  d_in[5];
    const float* Wq  = (const float*)d_in[6];
    const float* bq  = (const float*)d_in[7];
    const float* Wk  = (const float*)d_in[8];
    const float* bk  = (const float*)d_in[9];
    const float* Wv  = (const float*)d_in[10];
    const float* bv  = (const float*)d_in[11];
    const float* W1  = (const float*)d_in[12];
    const float* b1  = (const float*)d_in[13];
    const float* W2  = (const float*)d_in[14];
    const float* b2  = (const float*)d_in[15];
    const float* Wr  = (const float*)d_in[16];
    const float* br  = (const float*)d_in[17];
    const float* Wu  = (const float*)d_in[18];
    const float* bu  = (const float*)d_in[19];
    const float* Wc  = (const float*)d_in[20];
    const float* bc  = (const float*)d_in[21];
    float* out = (float*)d_out;

    const int SZ_V  = (64 * 132 + 129 * 136 + 16) * 4;
    const int SZ_M  = (64 * 90 + 86 * 136 + 64 * 133 + 16) * 4;
    const int SZ_RU = (64 * 130 + 64 * 33 + 2 * 129 * 34 + 16) * 4;
    const int SZ_C  = (64 * 130 + 64 * 33 + 129 * 34 + 16) * 4;

    cudaFuncSetAttribute(k_v,        cudaFuncAttributeMaxDynamicSharedMemorySize, SZ_V);
    cudaFuncSetAttribute(k_attn_mma, cudaFuncAttributeMaxDynamicSharedMemorySize, SMEM_ATT);
    cudaFuncSetAttribute(k_mlp,      cudaFuncAttributeMaxDynamicSharedMemorySize, SZ_M);
    cudaFuncSetAttribute(k_gate_ru,  cudaFuncAttributeMaxDynamicSharedMemorySize, SZ_RU);
    cudaFuncSetAttribute(k_gate_c,   cudaFuncAttributeMaxDynamicSharedMemorySize, SZ_C);

    k_combined<<<(ROWS * Cc + 255) / 256, 256>>>(x, h);
    k_adjpack<<<(Nn * Nn) / 256, 256>>>(adj);
    k_qk<<<(Hh * ROWS * Kk) / 256, 256>>>(Wq, bq, Wk, bk);
    k_v<<<dim3(128, 4), 256, SZ_V>>>(Wv, bv);
    k_attn_mma<<<dim3(8, 8, 4), 256, SMEM_ATT>>>();
    k_mlp<<<128, 256, SZ_M>>>(W1, b1, W2, b2);
    k_gate_ru<<<dim3(64, 2), 512, SZ_RU>>>(qv, nb, nn, Wr, br, Wu, bu, x, h);
    k_gate_c<<<dim3(64, 2), 512, SZ_C>>>(qv, Wc, bc, out);
}

// round 8
// speedup vs baseline: 2.6142x; 1.0893x over previous
#include <cuda_runtime.h>
#include <cuda_bf16.h>
#include <cstdint>
#include <math.h>

#define Bb   8
#define Nn   1024
#define Dd   64
#define Hh   4
#define Cc   129
#define Kk   16
#define Mm   4096
#define ROWS 8192   // B*N

// ---------------- helpers ----------------
__device__ __forceinline__ uint32_t cvt_bf16x2(float hi, float lo) {
    uint32_t r;
    asm("cvt.rn.bf16x2.f32 %0, %1, %2;" : "=r"(r) : "f"(hi), "f"(lo));
    return r;
}
__device__ __forceinline__ uint32_t to_tf32(float f) {
    uint32_t r;
    asm("cvt.rna.tf32.f32 %0, %1;" : "=r"(r) : "f"(f));
    return r;
}
__device__ __forceinline__ void mma_bf16(float c[4], uint32_t a0, uint32_t a1, uint32_t a2, uint32_t a3,
                                         uint32_t b0, uint32_t b1) {
    asm volatile("mma.sync.aligned.m16n8k16.row.col.f32.bf16.bf16.f32 "
                 "{%0,%1,%2,%3}, {%4,%5,%6,%7}, {%8,%9}, {%0,%1,%2,%3};"
                 : "+f"(c[0]), "+f"(c[1]), "+f"(c[2]), "+f"(c[3])
                 : "r"(a0), "r"(a1), "r"(a2), "r"(a3), "r"(b0), "r"(b1));
}
__device__ __forceinline__ void mma_tf32(float c[4], uint32_t a0, uint32_t a1, uint32_t a2, uint32_t a3,
                                         uint32_t b0, uint32_t b1) {
    asm volatile("mma.sync.aligned.m16n8k8.row.col.f32.tf32.tf32.f32 "
                 "{%0,%1,%2,%3}, {%4,%5,%6,%7}, {%8,%9}, {%0,%1,%2,%3};"
                 : "+f"(c[0]), "+f"(c[1]), "+f"(c[2]), "+f"(c[3])
                 : "r"(a0), "r"(a1), "r"(a2), "r"(a3), "r"(b0), "r"(b1));
}
__device__ __forceinline__ float expleaky(float s, uint32_t bit) {
    s *= 0.25f;
    s = s > 0.f ? s : 0.2f * s;
    return bit ? __expf(s) : 0.f;
}

// ================= scratch =================
__device__ float g_combined[ROWS * Cc];
__device__ __nv_bfloat16 g_qb[Hh * ROWS * Kk];
__device__ __nv_bfloat16 g_kb[Hh * ROWS * Kk];
__device__ __nv_bfloat16 g_vtb[Hh * Bb * 128 * 1024];   // [h*8+b][c<128][m]
__device__ float g_v128[Hh * Bb * 1024];                // v col 128
__device__ uint32_t g_adjbits[Nn * 32];
__device__ float g_hp[ROWS * 4 * 132];                  // [row][h][132 padded], normalized
__device__ float g_hn[Mm * Dd];
__device__ float g_u[Mm * Dd];
__device__ float g_sel2[Mm * Cc];

// ---------------- K0: combined = concat(x, h) ----------------
__global__ void k_combined(const float* __restrict__ x, const float* __restrict__ h) {
    int idx = blockIdx.x * 256 + threadIdx.x;
    if (idx >= ROWS * Cc) return;
    int row = idx / Cc, c = idx - row * Cc;
    g_combined[idx] = (c < 65) ? x[row * 65 + c] : h[row * 64 + (c - 65)];
}

// ---------------- K0b: pack adjacency bits ----------------
__global__ void k_adjpack(const int* __restrict__ adj) {
    int idx = blockIdx.x * 256 + threadIdx.x;   // < 1024*1024
    uint32_t bits = __ballot_sync(0xFFFFFFFFu, adj[idx] != 0);
    if ((idx & 31) == 0) g_adjbits[idx >> 5] = bits;
}

// ---------------- K1: q, k projections -> bf16 ----------------
__global__ void __launch_bounds__(256) k_qk(const float* __restrict__ Wq, const float* __restrict__ bq,
                                            const float* __restrict__ Wk, const float* __restrict__ bk) {
    int t = blockIdx.x * 256 + threadIdx.x;
    int kk  = t & 15;
    int row = (t >> 4) & (ROWS - 1);
    int hh  = t >> 17;
    const float* comb = g_combined + row * Cc;
    const float* wq = Wq + hh * Cc * Kk + kk;
    const float* wk = Wk + hh * Cc * Kk + kk;
    float aq = bq[hh * 16 + kk], ak = bk[hh * 16 + kk];
    #pragma unroll 4
    for (int i = 0; i < Cc; i++) {
        float cv = comb[i];
        aq += cv * wq[i * 16];
        ak += cv * wk[i * 16];
    }
    g_qb[t] = __float2bfloat16(aq);
    g_kb[t] = __float2bfloat16(ak);
}

// ---------------- K2: v projection -> transposed bf16 + col128 fp32 ----------------
__global__ void __launch_bounds__(256) k_v(const float* __restrict__ Wv, const float* __restrict__ bv) {
    extern __shared__ float sm[];
    float* comb_s = sm;                 // 64*132 (later reused as vtile)
    float* w_s    = sm + 64 * 132;      // 129*136
    int tile = blockIdx.x, hh = blockIdx.y, tid = threadIdx.x;

    for (int e = tid; e < 64 * Cc; e += 256) {
        int r = e / Cc, c = e - r * Cc;
        comb_s[r * 132 + c] = g_combined[(tile * 64 + r) * Cc + c];
    }
    for (int e = tid; e < Cc * Cc; e += 256) {
        int i = e / Cc, c = e - i * Cc;
        w_s[i * 136 + c] = Wv[(hh * Cc + i) * Cc + c];
    }
    __syncthreads();

    int rg = tid >> 4, cg = tid & 15;
    int r0 = rg * 4, c0 = cg * 9;
    float acc[4][9] = {};
    #pragma unroll 2
    for (int i = 0; i < Cc; i++) {
        float a0 = comb_s[(r0 + 0) * 132 + i];
        float a1 = comb_s[(r0 + 1) * 132 + i];
        float a2 = comb_s[(r0 + 2) * 132 + i];
        float a3 = comb_s[(r0 + 3) * 132 + i];
        #pragma unroll
        for (int jj = 0; jj < 9; jj++) {
            float w = w_s[i * 136 + c0 + jj];
            acc[0][jj] += a0 * w; acc[1][jj] += a1 * w;
            acc[2][jj] += a2 * w; acc[3][jj] += a3 * w;
        }
    }
    __syncthreads();   // done reading comb_s; reuse as vtile
    float* vtile = comb_s;
    #pragma unroll
    for (int j = 0; j < 4; j++)
        #pragma unroll
        for (int jj = 0; jj < 9; jj++) {
            int c = c0 + jj;
            if (c < Cc) vtile[(r0 + j) * 132 + c] = acc[j][jj] + bv[hh * Cc + c];
        }
    __syncthreads();

    int b_idx = tile >> 4;
    int mbase = (tile & 15) * 64;
    size_t hb = hh * 8 + b_idx;
    for (int e = tid; e < 128 * 32; e += 256) {
        int c = e >> 5, mp = e & 31;
        float f0 = vtile[(mp * 2) * 132 + c];
        float f1 = vtile[(mp * 2 + 1) * 132 + c];
        *(__nv_bfloat162*)&g_vtb[(hb * 128 + c) * 1024 + mbase + mp * 2] =
            __float22bfloat162_rn(make_float2(f0, f1));
    }
    for (int e = tid; e < 64; e += 256)
        g_v128[hb * 1024 + mbase + e] = vtile[e * 132 + 128];
}

// ---------------- K3: HMMA (mma.sync bf16) flash attention ----------------
#define AKS_OFF 0
#define AVT_OFF 6144
#define AV1_OFF (6144 + 34816)
#define SMEM_ATT (AV1_OFF + 512)

__global__ void __launch_bounds__(256) k_attn_mma() {
    extern __shared__ char smc[];
    uint32_t* Ks  = (uint32_t*)(smc + AKS_OFF);
    uint32_t* VTs = (uint32_t*)(smc + AVT_OFF);
    float*    v1s = (float*)(smc + AV1_OFF);
    int tid = threadIdx.x, w = tid >> 5, lane = tid & 31;
    int g = lane >> 2, t = lane & 3;
    int rblk = blockIdx.x, b = blockIdx.y, hh = blockIdx.z;
    size_t hb = hh * 8 + b;
    int brow = b * 1024 + rblk * 128;

    const __nv_bfloat16* qsrc = g_qb + ((size_t)hh * ROWS + brow + 16 * w) * 16;
    uint32_t qa0 = *(const uint32_t*)(qsrc + g * 16 + 2 * t);
    uint32_t qa1 = *(const uint32_t*)(qsrc + (g + 8) * 16 + 2 * t);
    uint32_t qa2 = *(const uint32_t*)(qsrc + g * 16 + 2 * t + 8);
    uint32_t qa3 = *(const uint32_t*)(qsrc + (g + 8) * 16 + 2 * t + 8);

    int nrow0 = rblk * 128 + 16 * w + g;
    int nrow1 = nrow0 + 8;

    float O[16][4];
    #pragma unroll
    for (int i = 0; i < 16; i++) { O[i][0] = O[i][1] = O[i][2] = O[i][3] = 0.f; }
    float rs0 = 0.f, rs1 = 0.f, ax0 = 0.f, ax1 = 0.f;

    const uint32_t* kbase = (const uint32_t*)(g_kb + ((size_t)hh * ROWS + b * 1024) * 16);
    const __nv_bfloat16* vbase = g_vtb + hb * 131072;

    for (int j = 0; j < 8; j++) {
        __syncthreads();
        const uint32_t* ks = kbase + j * 128 * 8;
        #pragma unroll
        for (int it = 0; it < 4; it++) {
            int e = tid + 256 * it;
            int r = e >> 3, c8 = e & 7;
            Ks[r * 12 + c8] = ks[e];
        }
        #pragma unroll
        for (int it = 0; it < 8; it++) {
            int e = tid + 256 * it;
            int c = e >> 4, q = e & 15;
            ((uint4*)(smc + AVT_OFF + c * 272))[q] =
                ((const uint4*)(vbase + (size_t)c * 1024 + j * 128))[q];
        }
        if (tid < 128) v1s[tid] = g_v128[hb * 1024 + j * 128 + tid];
        uint4 A0 = ((const uint4*)g_adjbits)[nrow0 * 8 + j];
        uint4 A1 = ((const uint4*)g_adjbits)[nrow1 * 8 + j];
        __syncthreads();

        uint32_t af[8][4];
        #pragma unroll
        for (int nt = 0; nt < 16; nt++) {
            uint32_t b0 = Ks[(8 * nt + g) * 12 + t];
            uint32_t b1 = Ks[(8 * nt + g) * 12 + t + 4];
            float c[4] = {0.f, 0.f, 0.f, 0.f};
            mma_bf16(c, qa0, qa1, qa2, qa3, b0, b1);
            uint32_t wA = (nt < 4) ? A0.x : (nt < 8) ? A0.y : (nt < 12) ? A0.z : A0.w;
            uint32_t wB = (nt < 4) ? A1.x : (nt < 8) ? A1.y : (nt < 12) ? A1.z : A1.w;
            int bitb = ((nt & 3) << 3) + 2 * t;
            float p00 = expleaky(c[0], (wA >> bitb) & 1);
            float p01 = expleaky(c[1], (wA >> (bitb + 1)) & 1);
            float p10 = expleaky(c[2], (wB >> bitb) & 1);
            float p11 = expleaky(c[3], (wB >> (bitb + 1)) & 1);
            rs0 += p00 + p01; rs1 += p10 + p11;
            float2 v2 = *(const float2*)&v1s[8 * nt + 2 * t];
            ax0 += p00 * v2.x + p01 * v2.y;
            ax1 += p10 * v2.x + p11 * v2.y;
            int kc = nt >> 1;
            if ((nt & 1) == 0) {
                af[kc][0] = cvt_bf16x2(p01, p00);
                af[kc][1] = cvt_bf16x2(p11, p10);
            } else {
                af[kc][2] = cvt_bf16x2(p01, p00);
                af[kc][3] = cvt_bf16x2(p11, p10);
            }
        }
        #pragma unroll
        for (int kc = 0; kc < 8; kc++) {
            #pragma unroll
            for (int nt2 = 0; nt2 < 16; nt2++) {
                uint32_t b0 = VTs[(8 * nt2 + g) * 68 + 8 * kc + t];
                uint32_t b1 = VTs[(8 * nt2 + g) * 68 + 8 * kc + t + 4];
                mma_bf16(O[nt2], af[kc][0], af[kc][1], af[kc][2], af[kc][3], b0, b1);
            }
        }
    }

    rs0 += __shfl_xor_sync(0xFFFFFFFFu, rs0, 1); rs0 += __shfl_xor_sync(0xFFFFFFFFu, rs0, 2);
    rs1 += __shfl_xor_sync(0xFFFFFFFFu, rs1, 1); rs1 += __shfl_xor_sync(0xFFFFFFFFu, rs1, 2);
    ax0 += __shfl_xor_sync(0xFFFFFFFFu, ax0, 1); ax0 += __shfl_xor_sync(0xFFFFFFFFu, ax0, 2);
    ax1 += __shfl_xor_sync(0xFFFFFFFFu, ax1, 1); ax1 += __shfl_xor_sync(0xFFFFFFFFu, ax1, 2);
    float inv0 = 1.f / rs0, inv1 = 1.f / rs1;

    float* d0 = g_hp + ((size_t)(brow + 16 * w + g) * 4 + hh) * 132;
    float* d1 = d0 + 8 * 4 * 132;
    #pragma unroll
    for (int nt2 = 0; nt2 < 16; nt2++) {
        *(float2*)&d0[8 * nt2 + 2 * t] = make_float2(O[nt2][0] * inv0, O[nt2][1] * inv0);
        *(float2*)&d1[8 * nt2 + 2 * t] = make_float2(O[nt2][2] * inv1, O[nt2][3] * inv1);
    }
    if (t == 0) { d0[128] = ax0 * inv0; d1[128] = ax1 * inv1; }
}

// ---------------- K4: attention MLP + skip ----------------
__global__ void __launch_bounds__(256) k_mlp(const float* __restrict__ W1, const float* __restrict__ b1,
                                             const float* __restrict__ W2, const float* __restrict__ b2) {
    extern __shared__ float sm[];
    float* in_s  = sm;
    float* w1_s  = sm + 64 * 90;
    float* hid_s = sm + 64 * 90 + 86 * 136;
    float* w2_s  = sm;
    int blk = blockIdx.x, tid = threadIdx.x;
    int rg = tid >> 4, cg = tid & 15;
    int r0 = rg * 4, c0 = cg * 9;

    float acc[4][9] = {};
    for (int kc = 0; kc < 6; kc++) {
        __syncthreads();
        for (int e = tid; e < 64 * 86; e += 256) {
            int r = e / 86, kk = e - r * 86;
            int c = kc * 86 + kk;
            int hh = c / 129, cc = c - hh * 129;
            in_s[r * 90 + kk] = g_hp[((size_t)(blk * 64 + r) * 4 + hh) * 132 + cc];
        }
        for (int e = tid; e < 86 * 129; e += 256) {
            int i = e / 129, c = e - i * 129;
            w1_s[i * 136 + c] = W1[(kc * 86 + i) * 129 + c];
        }
        __syncthreads();
        #pragma unroll 2
        for (int kk = 0; kk < 86; kk++) {
            float a0 = in_s[(r0 + 0) * 90 + kk];
            float a1 = in_s[(r0 + 1) * 90 + kk];
            float a2 = in_s[(r0 + 2) * 90 + kk];
            float a3 = in_s[(r0 + 3) * 90 + kk];
            #pragma unroll
            for (int jj = 0; jj < 9; jj++) {
                float w = w1_s[kk * 136 + c0 + jj];
                acc[0][jj] += a0 * w; acc[1][jj] += a1 * w;
                acc[2][jj] += a2 * w; acc[3][jj] += a3 * w;
            }
        }
    }
    __syncthreads();
    #pragma unroll
    for (int j = 0; j < 4; j++)
        #pragma unroll
        for (int jj = 0; jj < 9; jj++) {
            int c = c0 + jj;
            if (c < Cc) hid_s[(r0 + j) * 133 + c] = fmaxf(acc[j][jj] + b1[c], 0.f);
        }
    __syncthreads();
    for (int e = tid; e < 129 * 129; e += 256) {
        int i = e / 129, c = e - i * 129;
        w2_s[i * 134 + c] = W2[i * 129 + c];
    }
    __syncthreads();

    float acc2[4][9] = {};
    #pragma unroll 2
    for (int i = 0; i < Cc; i++) {
        float a0 = hid_s[(r0 + 0) * 133 + i];
        float a1 = hid_s[(r0 + 1) * 133 + i];
        float a2 = hid_s[(r0 + 2) * 133 + i];
        float a3 = hid_s[(r0 + 3) * 133 + i];
        #pragma unroll
        for (int jj = 0; jj < 9; jj++) {
            float w = w2_s[i * 134 + c0 + jj];
            acc2[0][jj] += a0 * w; acc2[1][jj] += a1 * w;
            acc2[2][jj] += a2 * w; acc2[3][jj] += a3 * w;
        }
    }
    #pragma unroll
    for (int j = 0; j < 4; j++)
        #pragma unroll
        for (int jj = 0; jj < 9; jj++) {
            int c = c0 + jj;
            if (c < Cc) {
                int idx = (blk * 64 + r0 + j) * Cc + c;
                g_combined[idx] = g_combined[idx] + acc2[j][jj] + b2[c];
            }
        }
}

// ---------------- K5: r,u gates via tf32 mma ----------------
// grid (64 mblk, 2 n-half), 512 threads = 16 warps: mt(4) x mat(2) x nsub(2 of n16)
__global__ void __launch_bounds__(512) k_gate_ru(const float* __restrict__ qv,
                                                 const int* __restrict__ nodes_b, const int* __restrict__ nodes_n,
                                                 const float* __restrict__ Wr, const float* __restrict__ br,
                                                 const float* __restrict__ Wu, const float* __restrict__ bu,
                                                 const float* __restrict__ x, const float* __restrict__ hin) {
    extern __shared__ float sm[];
    float*    sel_s = sm;                              // [64][132]
    float*    qv_s  = sel_s + 64 * 132;                // [64][33]
    uint32_t* Zs    = (uint32_t*)(qv_s + 64 * 33);     // [64][132] tf32
    uint32_t* Ws    = Zs + 64 * 132;                   // [2][132][36] tf32
    float*    bs    = (float*)(Ws + 2 * 132 * 36);     // [2][32][34]
    int blk = blockIdx.x, nh = blockIdx.y, tid = threadIdx.x;
    int ob = nh * 32;
    int w = tid >> 5, lane = tid & 31;
    int g = lane >> 2, t = lane & 3;
    int mt = w & 3, mat = (w >> 2) & 1, nsub = w >> 3;
    int m0 = mt * 16, n0l = nsub * 16;

    for (int e = tid; e < 64 * 132; e += 512) {
        int lm = e / 132, i = e - lm * 132;
        int gm = blk * 64 + lm;
        int node = nodes_b[gm] * Nn + nodes_n[gm];
        sel_s[e] = (i < Cc) ? g_combined[node * Cc + i] : 0.f;
    }
    for (int e = tid; e < 64 * 32; e += 512) {
        int lm = e >> 5, d = e & 31;
        qv_s[lm * 33 + d] = qv[(blk * 64 + lm) * 32 + d];
    }
    for (int e = tid; e < 2048; e += 512) {
        int m2 = e >> 10, r2 = e & 1023;
        int d2 = r2 >> 5, o = r2 & 31;
        bs[m2 * 1088 + d2 * 34 + o] = (m2 ? bu : br)[d2 * 64 + ob + o];
    }

    float acc[2][4] = {};
    const float* Wsrc = mat ? Wu : Wr;

    for (int d = 0; d < 32; d++) {
        __syncthreads();
        // build Z (tf32-rounded product)
        for (int e = tid; e < 64 * 132; e += 512) {
            int lm = e / 132;
            Zs[e] = to_tf32(qv_s[lm * 33 + d] * sel_s[e]);
        }
        // load W slices for both matrices (tf32-rounded)
        for (int e = tid; e < 2 * 129 * 32; e += 512) {
            int m2 = (e >= 4128);
            int e2 = e - m2 * 4128;
            int k = e2 >> 5, o = e2 & 31;
            Ws[m2 * 4752 + k * 36 + o] =
                to_tf32((m2 ? Wu : Wr)[((size_t)d * Cc + k) * 64 + ob + o]);
        }
        __syncthreads();

        const uint32_t* Wm = Ws + mat * 4752;
        #pragma unroll 4
        for (int ks = 0; ks < 16; ks++) {
            int k0 = ks * 8;
            uint32_t a0 = Zs[(m0 + g) * 132 + k0 + t];
            uint32_t a1 = Zs[(m0 + g + 8) * 132 + k0 + t];
            uint32_t a2 = Zs[(m0 + g) * 132 + k0 + t + 4];
            uint32_t a3 = Zs[(m0 + g + 8) * 132 + k0 + t + 4];
            #pragma unroll
            for (int cn = 0; cn < 2; cn++) {
                uint32_t b0 = Wm[(k0 + t) * 36 + n0l + cn * 8 + g];
                uint32_t b1 = Wm[(k0 + t + 4) * 36 + n0l + cn * 8 + g];
                mma_tf32(acc[cn], a0, a1, a2, a3, b0, b1);
            }
        }
        // scalar tail: k = 128
        float z0 = __uint_as_float(Zs[(m0 + g) * 132 + 128]);
        float z1 = __uint_as_float(Zs[(m0 + g + 8) * 132 + 128]);
        #pragma unroll
        for (int cn = 0; cn < 2; cn++) {
            float w0 = __uint_as_float(Wm[128 * 36 + n0l + cn * 8 + 2 * t]);
            float w1 = __uint_as_float(Wm[128 * 36 + n0l + cn * 8 + 2 * t + 1]);
            acc[cn][0] += z0 * w0; acc[cn][1] += z0 * w1;
            acc[cn][2] += z1 * w0; acc[cn][3] += z1 * w1;
        }
    }

    // bias: += qv @ b (fp32)
    const float* bm = bs + mat * 1088;
    #pragma unroll 4
    for (int d = 0; d < 32; d++) {
        float q0 = qv_s[(m0 + g) * 33 + d];
        float q1 = qv_s[(m0 + g + 8) * 33 + d];
        #pragma unroll
        for (int cn = 0; cn < 2; cn++) {
            float w0 = bm[d * 34 + n0l + cn * 8 + 2 * t];
            float w1 = bm[d * 34 + n0l + cn * 8 + 2 * t + 1];
            acc[cn][0] += q0 * w0; acc[cn][1] += q0 * w1;
            acc[cn][2] += q1 * w0; acc[cn][3] += q1 * w1;
        }
    }

    // stage ar/au into Zs (reused as float scratch): r at col 0, u at col 40
    __syncthreads();
    float* stg = (float*)Zs;
    int cb = mat * 40;
    #pragma unroll
    for (int cn = 0; cn < 2; cn++) {
        int col = cb + n0l + cn * 8 + 2 * t;
        stg[(m0 + g) * 132 + col]     = acc[cn][0];
        stg[(m0 + g) * 132 + col + 1] = acc[cn][1];
        stg[(m0 + g + 8) * 132 + col]     = acc[cn][2];
        stg[(m0 + g + 8) * 132 + col + 1] = acc[cn][3];
    }
    __syncthreads();

    for (int e = tid; e < 64 * 32; e += 512) {
        int lm = e >> 5, o = e & 31;
        int gm = blk * 64 + lm;
        int node = nodes_b[gm] * Nn + nodes_n[gm];
        float ar = stg[lm * 132 + o];
        float au = stg[lm * 132 + 40 + o];
        float hv = hin[node * 64 + ob + o];
        float r = 1.f / (1.f + __expf(-ar));
        float u = 1.f / (1.f + __expf(-au));
        float hn = r * hv;
        g_hn[gm * 64 + ob + o] = hn;
        g_u[gm * 64 + ob + o] = u;
        g_sel2[gm * Cc + 65 + ob + o] = hn;
    }
    if (nh == 0) {
        for (int e = tid; e < 64 * 65; e += 512) {
            int lm = e / 65, i = e - lm * 65;
            int gm = blk * 64 + lm;
            int node = nodes_b[gm] * Nn + nodes_n[gm];
            g_sel2[gm * Cc + i] = x[node * 65 + i];
        }
    }
}

// ---------------- K6: cand gate via tf32 mma + final update ----------------
// grid (64, 2), 256 threads = 8 warps: mt(4) x nsub(2 of n16)
__global__ void __launch_bounds__(256) k_gate_c(const float* __restrict__ qv,
                                                const float* __restrict__ Wc, const float* __restrict__ bc,
                                                float* __restrict__ out) {
    extern __shared__ float sm[];
    float*    sel_s = sm;                              // [64][132]
    float*    qv_s  = sel_s + 64 * 132;                // [64][33]
    uint32_t* Zs    = (uint32_t*)(qv_s + 64 * 33);     // [64][132]
    uint32_t* Ws    = Zs + 64 * 132;                   // [132][36]
    float*    bs    = (float*)(Ws + 132 * 36);         // [32][34]
    int blk = blockIdx.x, nh = blockIdx.y, tid = threadIdx.x;
    int ob = nh * 32;
    int w = tid >> 5, lane = tid & 31;
    int g = lane >> 2, t = lane & 3;
    int mt = w & 3, nsub = w >> 2;
    int m0 = mt * 16, n0l = nsub * 16;

    for (int e = tid; e < 64 * 132; e += 256) {
        int lm = e / 132, i = e - lm * 132;
        sel_s[e] = (i < Cc) ? g_sel2[(blk * 64 + lm) * Cc + i] : 0.f;
    }
    for (int e = tid; e < 64 * 32; e += 256) {
        int lm = e >> 5, d = e & 31;
        qv_s[lm * 33 + d] = qv[(blk * 64 + lm) * 32 + d];
    }
    for (int e = tid; e < 1024; e += 256) {
        int d2 = e >> 5, o = e & 31;
        bs[d2 * 34 + o] = bc[d2 * 64 + ob + o];
    }

    float acc[2][4] = {};

    for (int d = 0; d < 32; d++) {
        __syncthreads();
        for (int e = tid; e < 64 * 132; e += 256) {
            int lm = e / 132;
            Zs[e] = to_tf32(qv_s[lm * 33 + d] * sel_s[e]);
        }
        for (int e = tid; e < 129 * 32; e += 256) {
            int k = e >> 5, o = e & 31;
            Ws[k * 36 + o] = to_tf32(Wc[((size_t)d * Cc + k) * 64 + ob + o]);
        }
        __syncthreads();

        #pragma unroll 4
        for (int ks = 0; ks < 16; ks++) {
            int k0 = ks * 8;
            uint32_t a0 = Zs[(m0 + g) * 132 + k0 + t];
            uint32_t a1 = Zs[(m0 + g + 8) * 132 + k0 + t];
            uint32_t a2 = Zs[(m0 + g) * 132 + k0 + t + 4];
            uint32_t a3 = Zs[(m0 + g + 8) * 132 + k0 + t + 4];
            #pragma unroll
            for (int cn = 0; cn < 2; cn++) {
                uint32_t b0 = Ws[(k0 + t) * 36 + n0l + cn * 8 + g];
                uint32_t b1 = Ws[(k0 + t + 4) * 36 + n0l + cn * 8 + g];
                mma_tf32(acc[cn], a0, a1, a2, a3, b0, b1);
            }
        }
        float z0 = __uint_as_float(Zs[(m0 + g) * 132 + 128]);
        float z1 = __uint_as_float(Zs[(m0 + g + 8) * 132 + 128]);
        #pragma unroll
        for (int cn = 0; cn < 2; cn++) {
            float w0 = __uint_as_float(Ws[128 * 36 + n0l + cn * 8 + 2 * t]);
            float w1 = __uint_as_float(Ws[128 * 36 + n0l + cn * 8 + 2 * t + 1]);
            acc[cn][0] += z0 * w0; acc[cn][1] += z0 * w1;
            acc[cn][2] += z1 * w0; acc[cn][3] += z1 * w1;
        }
    }

    #pragma unroll 4
    for (int d = 0; d < 32; d++) {
        float q0 = qv_s[(m0 + g) * 33 + d];
        float q1 = qv_s[(m0 + g + 8) * 33 + d];
        #pragma unroll
        for (int cn = 0; cn < 2; cn++) {
            float w0 = bs[d * 34 + n0l + cn * 8 + 2 * t];
            float w1 = bs[d * 34 + n0l + cn * 8 + 2 * t + 1];
            acc[cn][0] += q0 * w0; acc[cn][1] += q0 * w1;
            acc[cn][2] += q1 * w0; acc[cn][3] += q1 * w1;
        }
    }

    int gm0 = blk * 64 + m0 + g;
    int gm1 = gm0 + 8;
    #pragma unroll
    for (int cn = 0; cn < 2; cn++) {
        int col = ob + n0l + cn * 8 + 2 * t;
        #pragma unroll
        for (int jj = 0; jj < 2; jj++) {
            int gm = jj ? gm1 : gm0;
            float c0 = acc[cn][2 * jj], c1 = acc[cn][2 * jj + 1];
            float u0 = g_u[gm * 64 + col],     hn0 = g_hn[gm * 64 + col];
            float u1 = g_u[gm * 64 + col + 1], hn1 = g_hn[gm * 64 + col + 1];
            out[gm * 64 + col]     = (1.f - u0) * hn0 + u0 * tanhf(c0);
            out[gm * 64 + col + 1] = (1.f - u1) * hn1 + u1 * tanhf(c1);
        }
    }
}

// ---------------- launch ----------------
extern "C" void kernel_launch(void* const* d_in, const int* in_sizes, int n_in,
                              void* d_out, int out_size) {
    const float* x   = (const float*)d_in[0];
    const float* h   = (const float*)d_in[1];
    const float* qv  = (const float*)d_in[2];
    const int*   adj = (const int*)  d_in[3];
    const int*   nb  = (const int*)  d_in[4];
    const int*   nn  = (const int*)  d_in[5];
    const float* Wq  = (const float*)d_in[6];
    const float* bq  = (const float*)d_in[7];
    const float* Wk  = (const float*)d_in[8];
    const float* bk  = (const float*)d_in[9];
    const float* Wv  = (const float*)d_in[10];
    const float* bv  = (const float*)d_in[11];
    const float* W1  = (const float*)d_in[12];
    const float* b1  = (const float*)d_in[13];
    const float* W2  = (const float*)d_in[14];
    const float* b2  = (const float*)d_in[15];
    const float* Wr  = (const float*)d_in[16];
    const float* br  = (const float*)d_in[17];
    const float* Wu  = (const float*)d_in[18];
    const float* bu  = (const float*)d_in[19];
    const float* Wc  = (const float*)d_in[20];
    const float* bc  = (const float*)d_in[21];
    float* out = (float*)d_out;

    const int SZ_V  = (64 * 132 + 129 * 136 + 16) * 4;
    const int SZ_M  = (64 * 90 + 86 * 136 + 64 * 133 + 16) * 4;
    const int SZ_RU = (64 * 132 + 64 * 33 + 64 * 132 + 2 * 132 * 36 + 2 * 32 * 34 + 16) * 4;
    const int SZ_C  = (64 * 132 + 64 * 33 + 64 * 132 + 132 * 36 + 32 * 34 + 16) * 4;

    cudaFuncSetAttribute(k_v,        cudaFuncAttributeMaxDynamicSharedMemorySize, SZ_V);
    cudaFuncSetAttribute(k_attn_mma, cudaFuncAttributeMaxDynamicSharedMemorySize, SMEM_ATT);
    cudaFuncSetAttribute(k_mlp,      cudaFuncAttributeMaxDynamicSharedMemorySize, SZ_M);
    cudaFuncSetAttribute(k_gate_ru,  cudaFuncAttributeMaxDynamicSharedMemorySize, SZ_RU);
    cudaFuncSetAttribute(k_gate_c,   cudaFuncAttributeMaxDynamicSharedMemorySize, SZ_C);

    k_combined<<<(ROWS * Cc + 255) / 256, 256>>>(x, h);
    k_adjpack<<<(Nn * Nn) / 256, 256>>>(adj);
    k_qk<<<(Hh * ROWS * Kk) / 256, 256>>>(Wq, bq, Wk, bk);
    k_v<<<dim3(128, 4), 256, SZ_V>>>(Wv, bv);
    k_attn_mma<<<dim3(8, 8, 4), 256, SMEM_ATT>>>();
    k_mlp<<<128, 256, SZ_M>>>(W1, b1, W2, b2);
    k_gate_ru<<<dim3(64, 2), 512, SZ_RU>>>(qv, nb, nn, Wr, br, Wu, bu, x, h);
    k_gate_c<<<dim3(64, 2), 256, SZ_C>>>(qv, Wc, bc, out);
}

// round 9
// speedup vs baseline: 2.8746x; 1.0996x over previous
#include <cuda_runtime.h>
#include <cuda_bf16.h>
#include <cstdint>
#include <math.h>

#define Bb   8
#define Nn   1024
#define Dd   64
#define Hh   4
#define Cc   129
#define Kk   16
#define Mm   4096
#define ROWS 8192   // B*N

// ---------------- helpers ----------------
__device__ __forceinline__ uint32_t cvt_bf16x2(float hi, float lo) {
    uint32_t r;
    asm("cvt.rn.bf16x2.f32 %0, %1, %2;" : "=r"(r) : "f"(hi), "f"(lo));
    return r;
}
__device__ __forceinline__ uint32_t to_tf32(float f) {
    uint32_t r;
    asm("cvt.rna.tf32.f32 %0, %1;" : "=r"(r) : "f"(f));
    return r;
}
__device__ __forceinline__ void mma_bf16(float c[4], uint32_t a0, uint32_t a1, uint32_t a2, uint32_t a3,
                                         uint32_t b0, uint32_t b1) {
    asm volatile("mma.sync.aligned.m16n8k16.row.col.f32.bf16.bf16.f32 "
                 "{%0,%1,%2,%3}, {%4,%5,%6,%7}, {%8,%9}, {%0,%1,%2,%3};"
                 : "+f"(c[0]), "+f"(c[1]), "+f"(c[2]), "+f"(c[3])
                 : "r"(a0), "r"(a1), "r"(a2), "r"(a3), "r"(b0), "r"(b1));
}
__device__ __forceinline__ void mma_tf32(float c[4], uint32_t a0, uint32_t a1, uint32_t a2, uint32_t a3,
                                         uint32_t b0, uint32_t b1) {
    asm volatile("mma.sync.aligned.m16n8k8.row.col.f32.tf32.tf32.f32 "
                 "{%0,%1,%2,%3}, {%4,%5,%6,%7}, {%8,%9}, {%0,%1,%2,%3};"
                 : "+f"(c[0]), "+f"(c[1]), "+f"(c[2]), "+f"(c[3])
                 : "r"(a0), "r"(a1), "r"(a2), "r"(a3), "r"(b0), "r"(b1));
}
__device__ __forceinline__ float expleaky(float s, uint32_t bit) {
    s *= 0.25f;
    s = s > 0.f ? s : 0.2f * s;
    return bit ? __expf(s) : 0.f;
}

// ================= scratch =================
__device__ float g_combined[ROWS * Cc];
__device__ __nv_bfloat16 g_qb[Hh * ROWS * Kk];
__device__ __nv_bfloat16 g_kb[Hh * ROWS * Kk];
__device__ __nv_bfloat16 g_vtb[Hh * Bb * 128 * 1024];   // [h*8+b][c<128][m]
__device__ float g_v128[Hh * Bb * 1024];                // v col 128
__device__ uint32_t g_adjbits[Nn * 32];
__device__ float g_hp[ROWS * 4 * 132];                  // [row][h][132 padded], normalized
__device__ float g_hn[Mm * Dd];
__device__ float g_u[Mm * Dd];
__device__ float g_sel2[Mm * Cc];

// ---------------- K0: combined = concat(x, h) ----------------
__global__ void k_combined(const float* __restrict__ x, const float* __restrict__ h) {
    int idx = blockIdx.x * 256 + threadIdx.x;
    if (idx >= ROWS * Cc) return;
    int row = idx / Cc, c = idx - row * Cc;
    g_combined[idx] = (c < 65) ? x[row * 65 + c] : h[row * 64 + (c - 65)];
}

// ---------------- K0b: pack adjacency bits ----------------
__global__ void k_adjpack(const int* __restrict__ adj) {
    int idx = blockIdx.x * 256 + threadIdx.x;   // < 1024*1024
    uint32_t bits = __ballot_sync(0xFFFFFFFFu, adj[idx] != 0);
    if ((idx & 31) == 0) g_adjbits[idx >> 5] = bits;
}

// ---------------- K1: fused q/k/v projections via bf16 mma ----------------
// grid (128 tiles of 64 rows, 4 heads), 256 threads = 8 warps (4 m-tiles x 2 n-halves)
// B matrix n-rows: [0..128]=Wv cols, [136..151]=Wq, [152..167]=Wk, rest zero.
#define QKV_AB_OFF 0                        // u32[64*76]  = 19456 B
#define QKV_WT_OFF 19456                    // u32[176*76] = 53504 B
#define QKV_BS_OFF (19456 + 53504)          // f32[176]
#define SMEM_QKV (QKV_BS_OFF + 176 * 4)

__global__ void __launch_bounds__(256) k_qkv(const float* __restrict__ Wv, const float* __restrict__ bv,
                                             const float* __restrict__ Wq, const float* __restrict__ bq,
                                             const float* __restrict__ Wk, const float* __restrict__ bk) {
    extern __shared__ char smc[];
    uint32_t* Ab = (uint32_t*)(smc + QKV_AB_OFF);
    uint32_t* Wt = (uint32_t*)(smc + QKV_WT_OFF);
    float* bias_s = (float*)(smc + QKV_BS_OFF);
    int tile = blockIdx.x, hh = blockIdx.y, tid = threadIdx.x;
    int w = tid >> 5, lane = tid & 31, g = lane >> 2, t = lane & 3;
    int wm = w & 3, wn = w >> 2;
    int m0 = wm * 16;

    const float* comb = g_combined + (size_t)(tile * 64) * Cc;
    for (int e = tid; e < 64 * 76; e += 256) {
        int r = e / 76, u = e - r * 76;
        uint32_t val = 0;
        if (u < 64)       val = cvt_bf16x2(comb[r * Cc + 2 * u + 1], comb[r * Cc + 2 * u]);
        else if (u == 64) val = cvt_bf16x2(0.f, comb[r * Cc + 128]);
        Ab[e] = val;
    }
    const float* wvh = Wv + (size_t)hh * 129 * 129;
    const float* wqh = Wq + (size_t)hh * 129 * 16;
    const float* wkh = Wk + (size_t)hh * 129 * 16;
    for (int e = tid; e < 76 * 176; e += 256) {
        int u = e / 176, n = e - u * 176;
        float w0 = 0.f, w1 = 0.f;
        if (u < 65) {
            int k0 = 2 * u, k1 = 2 * u + 1;
            if (n < 129) {
                w0 = wvh[k0 * 129 + n];
                if (k1 < 129) w1 = wvh[k1 * 129 + n];
            } else if (n >= 136 && n < 152) {
                int kk = n - 136;
                w0 = wqh[k0 * 16 + kk];
                if (k1 < 129) w1 = wqh[k1 * 16 + kk];
            } else if (n >= 152 && n < 168) {
                int kk = n - 152;
                w0 = wkh[k0 * 16 + kk];
                if (k1 < 129) w1 = wkh[k1 * 16 + kk];
            }
        }
        Wt[n * 76 + u] = cvt_bf16x2(w1, w0);
    }
    for (int e = tid; e < 176; e += 256) {
        float bval = 0.f;
        if (e < 129) bval = bv[hh * 129 + e];
        else if (e >= 136 && e < 152) bval = bq[hh * 16 + e - 136];
        else if (e >= 152 && e < 168) bval = bk[hh * 16 + e - 152];
        bias_s[e] = bval;
    }
    __syncthreads();

    float acc[11][4];
    #pragma unroll
    for (int i = 0; i < 11; i++) { acc[i][0] = acc[i][1] = acc[i][2] = acc[i][3] = 0.f; }
    int ntb = wn * 11;

    #pragma unroll
    for (int ks = 0; ks < 9; ks++) {
        uint32_t a0 = Ab[(m0 + g) * 76 + 8 * ks + t];
        uint32_t a1 = Ab[(m0 + g + 8) * 76 + 8 * ks + t];
        uint32_t a2 = Ab[(m0 + g) * 76 + 8 * ks + t + 4];
        uint32_t a3 = Ab[(m0 + g + 8) * 76 + 8 * ks + t + 4];
        #pragma unroll
        for (int i = 0; i < 11; i++) {
            int nt = ntb + i;
            uint32_t b0 = Wt[(8 * nt + g) * 76 + 8 * ks + t];
            uint32_t b1 = Wt[(8 * nt + g) * 76 + 8 * ks + t + 4];
            mma_bf16(acc[i], a0, a1, a2, a3, b0, b1);
        }
    }

    // q/k epilogue (wn==1, nt 17..20)
    size_t rowbase = (size_t)hh * ROWS + tile * 64 + m0;
    if (wn == 1) {
        #pragma unroll
        for (int i = 6; i < 10; i++) {
            int nt = 11 + i;
            bool isq = nt < 19;
            int col = (nt - (isq ? 17 : 19)) * 8 + 2 * t;
            float b0v = bias_s[(isq ? 136 : 152) + col];
            float b1v = bias_s[(isq ? 136 : 152) + col + 1];
            __nv_bfloat16* dst = isq ? g_qb : g_kb;
            *(uint32_t*)&dst[(rowbase + g) * 16 + col] =
                cvt_bf16x2(acc[i][1] + b1v, acc[i][0] + b0v);
            *(uint32_t*)&dst[(rowbase + g + 8) * 16 + col] =
                cvt_bf16x2(acc[i][3] + b1v, acc[i][2] + b0v);
        }
    }
    __syncthreads();
    float* vtile = (float*)smc;   // aliases Ab/Wt (33792 B < QKV_BS_OFF)
    #pragma unroll
    for (int i = 0; i < 11; i++) {
        int nt = ntb + i;
        if (nt > 16) break;
        int col = 8 * nt + 2 * t;
        if (col <= 128) {
            float bb = bias_s[col];
            vtile[(m0 + g) * 132 + col]     = acc[i][0] + bb;
            vtile[(m0 + g + 8) * 132 + col] = acc[i][2] + bb;
        }
        if (col + 1 <= 128) {
            float bb = bias_s[col + 1];
            vtile[(m0 + g) * 132 + col + 1]     = acc[i][1] + bb;
            vtile[(m0 + g + 8) * 132 + col + 1] = acc[i][3] + bb;
        }
    }
    __syncthreads();

    int b_idx = tile >> 4;
    int mbase = (tile & 15) * 64;
    size_t hb = hh * 8 + b_idx;
    for (int e = tid; e < 128 * 32; e += 256) {
        int c = e >> 5, mp = e & 31;
        float f0 = vtile[(mp * 2) * 132 + c];
        float f1 = vtile[(mp * 2 + 1) * 132 + c];
        *(__nv_bfloat162*)&g_vtb[(hb * 128 + c) * 1024 + mbase + mp * 2] =
            __float22bfloat162_rn(make_float2(f0, f1));
    }
    if (tid < 64)
        g_v128[hb * 1024 + mbase + tid] = vtile[tid * 132 + 128];
}

// ---------------- K3: HMMA (mma.sync bf16) flash attention ----------------
#define AKS_OFF 0
#define AVT_OFF 6144
#define AV1_OFF (6144 + 34816)
#define SMEM_ATT (AV1_OFF + 512)

__global__ void __launch_bounds__(256) k_attn_mma() {
    extern __shared__ char smc[];
    uint32_t* Ks  = (uint32_t*)(smc + AKS_OFF);
    uint32_t* VTs = (uint32_t*)(smc + AVT_OFF);
    float*    v1s = (float*)(smc + AV1_OFF);
    int tid = threadIdx.x, w = tid >> 5, lane = tid & 31;
    int g = lane >> 2, t = lane & 3;
    int rblk = blockIdx.x, b = blockIdx.y, hh = blockIdx.z;
    size_t hb = hh * 8 + b;
    int brow = b * 1024 + rblk * 128;

    const __nv_bfloat16* qsrc = g_qb + ((size_t)hh * ROWS + brow + 16 * w) * 16;
    uint32_t qa0 = *(const uint32_t*)(qsrc + g * 16 + 2 * t);
    uint32_t qa1 = *(const uint32_t*)(qsrc + (g + 8) * 16 + 2 * t);
    uint32_t qa2 = *(const uint32_t*)(qsrc + g * 16 + 2 * t + 8);
    uint32_t qa3 = *(const uint32_t*)(qsrc + (g + 8) * 16 + 2 * t + 8);

    int nrow0 = rblk * 128 + 16 * w + g;
    int nrow1 = nrow0 + 8;

    float O[16][4];
    #pragma unroll
    for (int i = 0; i < 16; i++) { O[i][0] = O[i][1] = O[i][2] = O[i][3] = 0.f; }
    float rs0 = 0.f, rs1 = 0.f, ax0 = 0.f, ax1 = 0.f;

    const uint32_t* kbase = (const uint32_t*)(g_kb + ((size_t)hh * ROWS + b * 1024) * 16);
    const __nv_bfloat16* vbase = g_vtb + hb * 131072;

    for (int j = 0; j < 8; j++) {
        __syncthreads();
        const uint32_t* ks = kbase + j * 128 * 8;
        #pragma unroll
        for (int it = 0; it < 4; it++) {
            int e = tid + 256 * it;
            int r = e >> 3, c8 = e & 7;
            Ks[r * 12 + c8] = ks[e];
        }
        #pragma unroll
        for (int it = 0; it < 8; it++) {
            int e = tid + 256 * it;
            int c = e >> 4, q = e & 15;
            ((uint4*)(smc + AVT_OFF + c * 272))[q] =
                ((const uint4*)(vbase + (size_t)c * 1024 + j * 128))[q];
        }
        if (tid < 128) v1s[tid] = g_v128[hb * 1024 + j * 128 + tid];
        uint4 A0 = ((const uint4*)g_adjbits)[nrow0 * 8 + j];
        uint4 A1 = ((const uint4*)g_adjbits)[nrow1 * 8 + j];
        __syncthreads();

        uint32_t af[8][4];
        #pragma unroll
        for (int nt = 0; nt < 16; nt++) {
            uint32_t b0 = Ks[(8 * nt + g) * 12 + t];
            uint32_t b1 = Ks[(8 * nt + g) * 12 + t + 4];
            float c[4] = {0.f, 0.f, 0.f, 0.f};
            mma_bf16(c, qa0, qa1, qa2, qa3, b0, b1);
            uint32_t wA = (nt < 4) ? A0.x : (nt < 8) ? A0.y : (nt < 12) ? A0.z : A0.w;
            uint32_t wB = (nt < 4) ? A1.x : (nt < 8) ? A1.y : (nt < 12) ? A1.z : A1.w;
            int bitb = ((nt & 3) << 3) + 2 * t;
            float p00 = expleaky(c[0], (wA >> bitb) & 1);
            float p01 = expleaky(c[1], (wA >> (bitb + 1)) & 1);
            float p10 = expleaky(c[2], (wB >> bitb) & 1);
            float p11 = expleaky(c[3], (wB >> (bitb + 1)) & 1);
            rs0 += p00 + p01; rs1 += p10 + p11;
            float2 v2 = *(const float2*)&v1s[8 * nt + 2 * t];
            ax0 += p00 * v2.x + p01 * v2.y;
            ax1 += p10 * v2.x + p11 * v2.y;
            int kc = nt >> 1;
            if ((nt & 1) == 0) {
                af[kc][0] = cvt_bf16x2(p01, p00);
                af[kc][1] = cvt_bf16x2(p11, p10);
            } else {
                af[kc][2] = cvt_bf16x2(p01, p00);
                af[kc][3] = cvt_bf16x2(p11, p10);
            }
        }
        #pragma unroll
        for (int kc = 0; kc < 8; kc++) {
            #pragma unroll
            for (int nt2 = 0; nt2 < 16; nt2++) {
                uint32_t b0 = VTs[(8 * nt2 + g) * 68 + 8 * kc + t];
                uint32_t b1 = VTs[(8 * nt2 + g) * 68 + 8 * kc + t + 4];
                mma_bf16(O[nt2], af[kc][0], af[kc][1], af[kc][2], af[kc][3], b0, b1);
            }
        }
    }

    rs0 += __shfl_xor_sync(0xFFFFFFFFu, rs0, 1); rs0 += __shfl_xor_sync(0xFFFFFFFFu, rs0, 2);
    rs1 += __shfl_xor_sync(0xFFFFFFFFu, rs1, 1); rs1 += __shfl_xor_sync(0xFFFFFFFFu, rs1, 2);
    ax0 += __shfl_xor_sync(0xFFFFFFFFu, ax0, 1); ax0 += __shfl_xor_sync(0xFFFFFFFFu, ax0, 2);
    ax1 += __shfl_xor_sync(0xFFFFFFFFu, ax1, 1); ax1 += __shfl_xor_sync(0xFFFFFFFFu, ax1, 2);
    float inv0 = 1.f / rs0, inv1 = 1.f / rs1;

    float* d0 = g_hp + ((size_t)(brow + 16 * w + g) * 4 + hh) * 132;
    float* d1 = d0 + 8 * 4 * 132;
    #pragma unroll
    for (int nt2 = 0; nt2 < 16; nt2++) {
        *(float2*)&d0[8 * nt2 + 2 * t] = make_float2(O[nt2][0] * inv0, O[nt2][1] * inv0);
        *(float2*)&d1[8 * nt2 + 2 * t] = make_float2(O[nt2][2] * inv1, O[nt2][3] * inv1);
    }
    if (t == 0) { d0[128] = ax0 * inv0; d1[128] = ax1 * inv1; }
}

// ---------------- K4: attention MLP + skip via tf32 mma ----------------
// grid 128, 256 threads = 8 warps (4 m-tiles x 2 n-halves of 9 n8-tiles)
#define MLP_A_OFF 0                         // u32[64*140]  = 35840
#define MLP_W_OFF 35840                     // u32[144*140] = 80640
#define MLP_H_OFF (35840 + 80640)           // u32[64*140]  = 35840
#define MLP_B_OFF (MLP_H_OFF + 35840)       // f32[272]
#define SMEM_MLP (MLP_B_OFF + 272 * 4)

__global__ void __launch_bounds__(256) k_mlp(const float* __restrict__ W1, const float* __restrict__ b1,
                                             const float* __restrict__ W2, const float* __restrict__ b2) {
    extern __shared__ char smc[];
    uint32_t* As = (uint32_t*)(smc + MLP_A_OFF);
    uint32_t* Ws = (uint32_t*)(smc + MLP_W_OFF);
    uint32_t* Hs = (uint32_t*)(smc + MLP_H_OFF);
    float* bias_s = (float*)(smc + MLP_B_OFF);
    int blk = blockIdx.x, tid = threadIdx.x;
    int w = tid >> 5, lane = tid & 31, g = lane >> 2, t = lane & 3;
    int wm = w & 3, wn = w >> 2;
    int m0 = wm * 16;

    for (int e = tid; e < 64 * 140; e += 256) Hs[e] = 0;
    for (int e = tid; e < 272; e += 256) {
        float bval = 0.f;
        if (e < 129) bval = b1[e];
        else if (e >= 136 && e < 265) bval = b2[e - 136];
        bias_s[e] = bval;
    }

    float acc[9][4];
    #pragma unroll
    for (int i = 0; i < 9; i++) { acc[i][0] = acc[i][1] = acc[i][2] = acc[i][3] = 0.f; }

    for (int kc = 0; kc < 4; kc++) {
        __syncthreads();
        for (int e = tid; e < 64 * 140; e += 256) {
            int r = e / 140, u = e - r * 140;
            As[e] = (u < 129) ? to_tf32(g_hp[((size_t)(blk * 64 + r) * 4 + kc) * 132 + u]) : 0;
        }
        for (int e = tid; e < 140 * 144; e += 256) {
            int u = e / 144, n = e - u * 144;
            Ws[n * 140 + u] = (u < 129 && n < 129)
                ? to_tf32(W1[((size_t)kc * 129 + u) * 129 + n]) : 0;
        }
        __syncthreads();
        #pragma unroll
        for (int ks = 0; ks < 17; ks++) {
            uint32_t a0 = As[(m0 + g) * 140 + 8 * ks + t];
            uint32_t a1 = As[(m0 + g + 8) * 140 + 8 * ks + t];
            uint32_t a2 = As[(m0 + g) * 140 + 8 * ks + t + 4];
            uint32_t a3 = As[(m0 + g + 8) * 140 + 8 * ks + t + 4];
            #pragma unroll
            for (int i = 0; i < 9; i++) {
                int nt = wn * 9 + i;
                uint32_t b0 = Ws[(8 * nt + g) * 140 + 8 * ks + t];
                uint32_t b1r = Ws[(8 * nt + g) * 140 + 8 * ks + t + 4];
                mma_tf32(acc[i], a0, a1, a2, a3, b0, b1r);
            }
        }
    }
    // hidden = relu(acc + b1) -> tf32 into Hs
    #pragma unroll
    for (int i = 0; i < 9; i++) {
        int nt = wn * 9 + i;
        int col = 8 * nt + 2 * t;
        if (col <= 128) {
            Hs[(m0 + g) * 140 + col]     = to_tf32(fmaxf(acc[i][0] + bias_s[col], 0.f));
            Hs[(m0 + g + 8) * 140 + col] = to_tf32(fmaxf(acc[i][2] + bias_s[col], 0.f));
        }
        if (col + 1 <= 128) {
            Hs[(m0 + g) * 140 + col + 1]     = to_tf32(fmaxf(acc[i][1] + bias_s[col + 1], 0.f));
            Hs[(m0 + g + 8) * 140 + col + 1] = to_tf32(fmaxf(acc[i][3] + bias_s[col + 1], 0.f));
        }
        acc[i][0] = acc[i][1] = acc[i][2] = acc[i][3] = 0.f;
    }
    __syncthreads();
    for (int e = tid; e < 140 * 144; e += 256) {
        int u = e / 144, n = e - u * 144;
        Ws[n * 140 + u] = (u < 129 && n < 129) ? to_tf32(W2[(size_t)u * 129 + n]) : 0;
    }
    __syncthreads();
    #pragma unroll
    for (int ks = 0; ks < 17; ks++) {
        uint32_t a0 = Hs[(m0 + g) * 140 + 8 * ks + t];
        uint32_t a1 = Hs[(m0 + g + 8) * 140 + 8 * ks + t];
        uint32_t a2 = Hs[(m0 + g) * 140 + 8 * ks + t + 4];
        uint32_t a3 = Hs[(m0 + g + 8) * 140 + 8 * ks + t + 4];
        #pragma unroll
        for (int i = 0; i < 9; i++) {
            int nt = wn * 9 + i;
            uint32_t b0 = Ws[(8 * nt + g) * 140 + 8 * ks + t];
            uint32_t b1r = Ws[(8 * nt + g) * 140 + 8 * ks + t + 4];
            mma_tf32(acc[i], a0, a1, a2, a3, b0, b1r);
        }
    }
    #pragma unroll
    for (int i = 0; i < 9; i++) {
        int nt = wn * 9 + i;
        int col = 8 * nt + 2 * t;
        if (col <= 128) {
            int idx = (blk * 64 + m0 + g) * Cc + col;
            g_combined[idx]          += acc[i][0] + bias_s[136 + col];
            g_combined[idx + 8 * Cc] += acc[i][2] + bias_s[136 + col];
        }
        if (col + 1 <= 128) {
            int idx = (blk * 64 + m0 + g) * Cc + col + 1;
            g_combined[idx]          += acc[i][1] + bias_s[137 + col];
            g_combined[idx + 8 * Cc] += acc[i][3] + bias_s[137 + col];
        }
    }
}

// ---------------- K5: r,u gates via tf32 mma ----------------
__global__ void __launch_bounds__(512) k_gate_ru(const float* __restrict__ qv,
                                                 const int* __restrict__ nodes_b, const int* __restrict__ nodes_n,
                                                 const float* __restrict__ Wr, const float* __restrict__ br,
                                                 const float* __restrict__ Wu, const float* __restrict__ bu,
                                                 const float* __restrict__ x, const float* __restrict__ hin) {
    extern __shared__ float sm[];
    float*    sel_s = sm;                              // [64][132]
    float*    qv_s  = sel_s + 64 * 132;                // [64][33]
    uint32_t* Zs    = (uint32_t*)(qv_s + 64 * 33);     // [64][132] tf32
    uint32_t* Ws    = Zs + 64 * 132;                   // [2][132][36] tf32
    float*    bs    = (float*)(Ws + 2 * 132 * 36);     // [2][32][34]
    int blk = blockIdx.x, nh = blockIdx.y, tid = threadIdx.x;
    int ob = nh * 32;
    int w = tid >> 5, lane = tid & 31;
    int g = lane >> 2, t = lane & 3;
    int mt = w & 3, mat = (w >> 2) & 1, nsub = w >> 3;
    int m0 = mt * 16, n0l = nsub * 16;

    for (int e = tid; e < 64 * 132; e += 512) {
        int lm = e / 132, i = e - lm * 132;
        int gm = blk * 64 + lm;
        int node = nodes_b[gm] * Nn + nodes_n[gm];
        sel_s[e] = (i < Cc) ? g_combined[node * Cc + i] : 0.f;
    }
    for (int e = tid; e < 64 * 32; e += 512) {
        int lm = e >> 5, d = e & 31;
        qv_s[lm * 33 + d] = qv[(blk * 64 + lm) * 32 + d];
    }
    for (int e = tid; e < 2048; e += 512) {
        int m2 = e >> 10, r2 = e & 1023;
        int d2 = r2 >> 5, o = r2 & 31;
        bs[m2 * 1088 + d2 * 34 + o] = (m2 ? bu : br)[d2 * 64 + ob + o];
    }

    float acc[2][4] = {};

    for (int d = 0; d < 32; d++) {
        __syncthreads();
        for (int e = tid; e < 64 * 132; e += 512) {
            int lm = e / 132;
            Zs[e] = to_tf32(qv_s[lm * 33 + d] * sel_s[e]);
        }
        for (int e = tid; e < 2 * 129 * 32; e += 512) {
            int m2 = (e >= 4128);
            int e2 = e - m2 * 4128;
            int k = e2 >> 5, o = e2 & 31;
            Ws[m2 * 4752 + k * 36 + o] =
                to_tf32((m2 ? Wu : Wr)[((size_t)d * Cc + k) * 64 + ob + o]);
        }
        __syncthreads();

        const uint32_t* Wm = Ws + mat * 4752;
        #pragma unroll 4
        for (int ks = 0; ks < 16; ks++) {
            int k0 = ks * 8;
            uint32_t a0 = Zs[(m0 + g) * 132 + k0 + t];
            uint32_t a1 = Zs[(m0 + g + 8) * 132 + k0 + t];
            uint32_t a2 = Zs[(m0 + g) * 132 + k0 + t + 4];
            uint32_t a3 = Zs[(m0 + g + 8) * 132 + k0 + t + 4];
            #pragma unroll
            for (int cn = 0; cn < 2; cn++) {
                uint32_t b0 = Wm[(k0 + t) * 36 + n0l + cn * 8 + g];
                uint32_t b1 = Wm[(k0 + t + 4) * 36 + n0l + cn * 8 + g];
                mma_tf32(acc[cn], a0, a1, a2, a3, b0, b1);
            }
        }
        float z0 = __uint_as_float(Zs[(m0 + g) * 132 + 128]);
        float z1 = __uint_as_float(Zs[(m0 + g + 8) * 132 + 128]);
        #pragma unroll
        for (int cn = 0; cn < 2; cn++) {
            float w0 = __uint_as_float(Wm[128 * 36 + n0l + cn * 8 + 2 * t]);
            float w1 = __uint_as_float(Wm[128 * 36 + n0l + cn * 8 + 2 * t + 1]);
            acc[cn][0] += z0 * w0; acc[cn][1] += z0 * w1;
            acc[cn][2] += z1 * w0; acc[cn][3] += z1 * w1;
        }
    }

    const float* bm = bs + mat * 1088;
    #pragma unroll 4
    for (int d = 0; d < 32; d++) {
        float q0 = qv_s[(m0 + g) * 33 + d];
        float q1 = qv_s[(m0 + g + 8) * 33 + d];
        #pragma unroll
        for (int cn = 0; cn < 2; cn++) {
            float w0 = bm[d * 34 + n0l + cn * 8 + 2 * t];
            float w1 = bm[d * 34 + n0l + cn * 8 + 2 * t + 1];
            acc[cn][0] += q0 * w0; acc[cn][1] += q0 * w1;
            acc[cn][2] += q1 * w0; acc[cn][3] += q1 * w1;
        }
    }

    __syncthreads();
    float* stg = (float*)Zs;
    int cb = mat * 40;
    #pragma unroll
    for (int cn = 0; cn < 2; cn++) {
        int col = cb + n0l + cn * 8 + 2 * t;
        stg[(m0 + g) * 132 + col]     = acc[cn][0];
        stg[(m0 + g) * 132 + col + 1] = acc[cn][1];
        stg[(m0 + g + 8) * 132 + col]     = acc[cn][2];
        stg[(m0 + g + 8) * 132 + col + 1] = acc[cn][3];
    }
    __syncthreads();

    for (int e = tid; e < 64 * 32; e += 512) {
        int lm = e >> 5, o = e & 31;
        int gm = blk * 64 + lm;
        int node = nodes_b[gm] * Nn + nodes_n[gm];
        float ar = stg[lm * 132 + o];
        float au = stg[lm * 132 + 40 + o];
        float hv = hin[node * 64 + ob + o];
        float r = 1.f / (1.f + __expf(-ar));
        float u = 1.f / (1.f + __expf(-au));
        float hn = r * hv;
        g_hn[gm * 64 + ob + o] = hn;
        g_u[gm * 64 + ob + o] = u;
        g_sel2[gm * Cc + 65 + ob + o] = hn;
    }
    if (nh == 0) {
        for (int e = tid; e < 64 * 65; e += 512) {
            int lm = e / 65, i = e - lm * 65;
            int gm = blk * 64 + lm;
            int node = nodes_b[gm] * Nn + nodes_n[gm];
            g_sel2[gm * Cc + i] = x[node * 65 + i];
        }
    }
}

// ---------------- K6: cand gate via tf32 mma + final update ----------------
__global__ void __launch_bounds__(256) k_gate_c(const float* __restrict__ qv,
                                                const float* __restrict__ Wc, const float* __restrict__ bc,
                                                float* __restrict__ out) {
    extern __shared__ float sm[];
    float*    sel_s = sm;
    float*    qv_s  = sel_s + 64 * 132;
    uint32_t* Zs    = (uint32_t*)(qv_s + 64 * 33);
    uint32_t* Ws    = Zs + 64 * 132;
    float*    bs    = (float*)(Ws + 132 * 36);
    int blk = blockIdx.x, nh = blockIdx.y, tid = threadIdx.x;
    int ob = nh * 32;
    int w = tid >> 5, lane = tid & 31;
    int g = lane >> 2, t = lane & 3;
    int mt = w & 3, nsub = w >> 2;
    int m0 = mt * 16, n0l = nsub * 16;

    for (int e = tid; e < 64 * 132; e += 256) {
        int lm = e / 132, i = e - lm * 132;
        sel_s[e] = (i < Cc) ? g_sel2[(blk * 64 + lm) * Cc + i] : 0.f;
    }
    for (int e = tid; e < 64 * 32; e += 256) {
        int lm = e >> 5, d = e & 31;
        qv_s[lm * 33 + d] = qv[(blk * 64 + lm) * 32 + d];
    }
    for (int e = tid; e < 1024; e += 256) {
        int d2 = e >> 5, o = e & 31;
        bs[d2 * 34 + o] = bc[d2 * 64 + ob + o];
    }

    float acc[2][4] = {};

    for (int d = 0; d < 32; d++) {
        __syncthreads();
        for (int e = tid; e < 64 * 132; e += 256) {
            int lm = e / 132;
            Zs[e] = to_tf32(qv_s[lm * 33 + d] * sel_s[e]);
        }
        for (int e = tid; e < 129 * 32; e += 256) {
            int k = e >> 5, o = e & 31;
            Ws[k * 36 + o] = to_tf32(Wc[((size_t)d * Cc + k) * 64 + ob + o]);
        }
        __syncthreads();

        #pragma unroll 4
        for (int ks = 0; ks < 16; ks++) {
            int k0 = ks * 8;
            uint32_t a0 = Zs[(m0 + g) * 132 + k0 + t];
            uint32_t a1 = Zs[(m0 + g + 8) * 132 + k0 + t];
            uint32_t a2 = Zs[(m0 + g) * 132 + k0 + t + 4];
            uint32_t a3 = Zs[(m0 + g + 8) * 132 + k0 + t + 4];
            #pragma unroll
            for (int cn = 0; cn < 2; cn++) {
                uint32_t b0 = Ws[(k0 + t) * 36 + n0l + cn * 8 + g];
                uint32_t b1 = Ws[(k0 + t + 4) * 36 + n0l + cn * 8 + g];
                mma_tf32(acc[cn], a0, a1, a2, a3, b0, b1);
            }
        }
        float z0 = __uint_as_float(Zs[(m0 + g) * 132 + 128]);
        float z1 = __uint_as_float(Zs[(m0 + g + 8) * 132 + 128]);
        #pragma unroll
        for (int cn = 0; cn < 2; cn++) {
            float w0 = __uint_as_float(Ws[128 * 36 + n0l + cn * 8 + 2 * t]);
            float w1 = __uint_as_float(Ws[128 * 36 + n0l + cn * 8 + 2 * t + 1]);
            acc[cn][0] += z0 * w0; acc[cn][1] += z0 * w1;
            acc[cn][2] += z1 * w0; acc[cn][3] += z1 * w1;
        }
    }

    #pragma unroll 4
    for (int d = 0; d < 32; d++) {
        float q0 = qv_s[(m0 + g) * 33 + d];
        float q1 = qv_s[(m0 + g + 8) * 33 + d];
        #pragma unroll
        for (int cn = 0; cn < 2; cn++) {
            float w0 = bs[d * 34 + n0l + cn * 8 + 2 * t];
            float w1 = bs[d * 34 + n0l + cn * 8 + 2 * t + 1];
            acc[cn][0] += q0 * w0; acc[cn][1] += q0 * w1;
            acc[cn][2] += q1 * w0; acc[cn][3] += q1 * w1;
        }
    }

    int gm0 = blk * 64 + m0 + g;
    int gm1 = gm0 + 8;
    #pragma unroll
    for (int cn = 0; cn < 2; cn++) {
        int col = ob + n0l + cn * 8 + 2 * t;
        #pragma unroll
        for (int jj = 0; jj < 2; jj++) {
            int gm = jj ? gm1 : gm0;
            float c0 = acc[cn][2 * jj], c1 = acc[cn][2 * jj + 1];
            float u0 = g_u[gm * 64 + col],     hn0 = g_hn[gm * 64 + col];
            float u1 = g_u[gm * 64 + col + 1], hn1 = g_hn[gm * 64 + col + 1];
            out[gm * 64 + col]     = (1.f - u0) * hn0 + u0 * tanhf(c0);
            out[gm * 64 + col + 1] = (1.f - u1) * hn1 + u1 * tanhf(c1);
        }
    }
}

// ---------------- launch ----------------
extern "C" void kernel_launch(void* const* d_in, const int* in_sizes, int n_in,
                              void* d_out, int out_size) {
    const float* x   = (const float*)d_in[0];
    const float* h   = (const float*)d_in[1];
    const float* qv  = (const float*)d_in[2];
    const int*   adj = (const int*)  d_in[3];
    const int*   nb  = (const int*)  d_in[4];
    const int*   nn  = (const int*)  d_in[5];
    const float* Wq  = (const float*)d_in[6];
    const float* bq  = (const float*)d_in[7];
    const float* Wk  = (const float*)d_in[8];
    const float* bk  = (const float*)d_in[9];
    const float* Wv  = (const float*)d_in[10];
    const float* bv  = (const float*)d_in[11];
    const float* W1  = (const float*)d_in[12];
    const float* b1  = (const float*)d_in[13];
    const float* W2  = (const float*)d_in[14];
    const float* b2  = (const float*)d_in[15];
    const float* Wr  = (const float*)d_in[16];
    const float* br  = (const float*)d_in[17];
    const float* Wu  = (const float*)d_in[18];
    const float* bu  = (const float*)d_in[19];
    const float* Wc  = (const float*)d_in[20];
    const float* bc  = (const float*)d_in[21];
    float* out = (float*)d_out;

    const int SZ_RU = (64 * 132 + 64 * 33 + 64 * 132 + 2 * 132 * 36 + 2 * 32 * 34 + 16) * 4;
    const int SZ_C  = (64 * 132 + 64 * 33 + 64 * 132 + 132 * 36 + 32 * 34 + 16) * 4;

    cudaFuncSetAttribute(k_qkv,      cudaFuncAttributeMaxDynamicSharedMemorySize, SMEM_QKV);
    cudaFuncSetAttribute(k_attn_mma, cudaFuncAttributeMaxDynamicSharedMemorySize, SMEM_ATT);
    cudaFuncSetAttribute(k_mlp,      cudaFuncAttributeMaxDynamicSharedMemorySize, SMEM_MLP);
    cudaFuncSetAttribute(k_gate_ru,  cudaFuncAttributeMaxDynamicSharedMemorySize, SZ_RU);
    cudaFuncSetAttribute(k_gate_c,   cudaFuncAttributeMaxDynamicSharedMemorySize, SZ_C);

    k_combined<<<(ROWS * Cc + 255) / 256, 256>>>(x, h);
    k_adjpack<<<(Nn * Nn) / 256, 256>>>(adj);
    k_qkv<<<dim3(128, 4), 256, SMEM_QKV>>>(Wv, bv, Wq, bq, Wk, bk);
    k_attn_mma<<<dim3(8, 8, 4), 256, SMEM_ATT>>>();
    k_mlp<<<128, 256, SMEM_MLP>>>(W1, b1, W2, b2);
    k_gate_ru<<<dim3(64, 2), 512, SZ_RU>>>(qv, nb, nn, Wr, br, Wu, bu, x, h);
    k_gate_c<<<dim3(64, 2), 256, SZ_C>>>(qv, Wc, bc, out);
}

// round 10
// speedup vs baseline: 3.8398x; 1.3358x over previous
#include <cuda_runtime.h>
#include <cuda_bf16.h>
#include <cstdint>
#include <math.h>

#define Bb   8
#define Nn   1024
#define Dd   64
#define Hh   4
#define Cc   129
#define Kk   16
#define Mm   4096
#define ROWS 8192   // B*N

// ---------------- helpers ----------------
__device__ __forceinline__ uint32_t cvt_bf16x2(float hi, float lo) {
    uint32_t r;
    asm("cvt.rn.bf16x2.f32 %0, %1, %2;" : "=r"(r) : "f"(hi), "f"(lo));
    return r;
}
__device__ __forceinline__ uint32_t to_tf32(float f) {
    uint32_t r;
    asm("cvt.rna.tf32.f32 %0, %1;" : "=r"(r) : "f"(f));
    return r;
}
__device__ __forceinline__ void mma_bf16(float c[4], uint32_t a0, uint32_t a1, uint32_t a2, uint32_t a3,
                                         uint32_t b0, uint32_t b1) {
    asm volatile("mma.sync.aligned.m16n8k16.row.col.f32.bf16.bf16.f32 "
                 "{%0,%1,%2,%3}, {%4,%5,%6,%7}, {%8,%9}, {%0,%1,%2,%3};"
                 : "+f"(c[0]), "+f"(c[1]), "+f"(c[2]), "+f"(c[3])
                 : "r"(a0), "r"(a1), "r"(a2), "r"(a3), "r"(b0), "r"(b1));
}
__device__ __forceinline__ void mma_tf32(float c[4], uint32_t a0, uint32_t a1, uint32_t a2, uint32_t a3,
                                         uint32_t b0, uint32_t b1) {
    asm volatile("mma.sync.aligned.m16n8k8.row.col.f32.tf32.tf32.f32 "
                 "{%0,%1,%2,%3}, {%4,%5,%6,%7}, {%8,%9}, {%0,%1,%2,%3};"
                 : "+f"(c[0]), "+f"(c[1]), "+f"(c[2]), "+f"(c[3])
                 : "r"(a0), "r"(a1), "r"(a2), "r"(a3), "r"(b0), "r"(b1));
}
__device__ __forceinline__ float expleaky(float s, uint32_t bit) {
    s *= 0.25f;
    s = s > 0.f ? s : 0.2f * s;
    return bit ? __expf(s) : 0.f;
}

// ================= scratch =================
__device__ float g_combined[ROWS * Cc];
__device__ __nv_bfloat16 g_qb[Hh * ROWS * Kk];
__device__ __nv_bfloat16 g_kb[Hh * ROWS * Kk];
__device__ __nv_bfloat16 g_vtb[Hh * Bb * 128 * 1024];   // [h*8+b][c<128][m]
__device__ float g_v128[Hh * Bb * 1024];                // v col 128
__device__ uint32_t g_adjbits[Nn * 32];
__device__ float g_hp[ROWS * 4 * 132];                  // [row][h][132 padded], normalized
__device__ float g_hn[Mm * Dd];
__device__ float g_u[Mm * Dd];
__device__ float g_sel2[Mm * Cc];

// ---------------- K0: combined = concat(x, h) ----------------
__global__ void k_combined(const float* __restrict__ x, const float* __restrict__ h) {
    int idx = blockIdx.x * 256 + threadIdx.x;
    if (idx >= ROWS * Cc) return;
    int row = idx / Cc, c = idx - row * Cc;
    g_combined[idx] = (c < 65) ? x[row * 65 + c] : h[row * 64 + (c - 65)];
}

// ---------------- K0b: pack adjacency bits ----------------
__global__ void k_adjpack(const int* __restrict__ adj) {
    int idx = blockIdx.x * 256 + threadIdx.x;
    uint32_t bits = __ballot_sync(0xFFFFFFFFu, adj[idx] != 0);
    if ((idx & 31) == 0) g_adjbits[idx >> 5] = bits;
}

// ---------------- K1: fused q/k/v projections via bf16 mma ----------------
#define QKV_AB_OFF 0
#define QKV_WT_OFF 19456
#define QKV_BS_OFF (19456 + 53504)
#define SMEM_QKV (QKV_BS_OFF + 176 * 4)

__global__ void __launch_bounds__(256, 2) k_qkv(const float* __restrict__ Wv, const float* __restrict__ bv,
                                                const float* __restrict__ Wq, const float* __restrict__ bq,
                                                const float* __restrict__ Wk, const float* __restrict__ bk) {
    extern __shared__ char smc[];
    uint32_t* Ab = (uint32_t*)(smc + QKV_AB_OFF);
    uint32_t* Wt = (uint32_t*)(smc + QKV_WT_OFF);
    float* bias_s = (float*)(smc + QKV_BS_OFF);
    int tile = blockIdx.x, hh = blockIdx.y, tid = threadIdx.x;
    int w = tid >> 5, lane = tid & 31, g = lane >> 2, t = lane & 3;
    int wm = w & 3, wn = w >> 2;
    int m0 = wm * 16;

    const float* comb = g_combined + (size_t)(tile * 64) * Cc;
    for (int e = tid; e < 64 * 76; e += 256) {
        int r = e / 76, u = e - r * 76;
        uint32_t val = 0;
        if (u < 64)       val = cvt_bf16x2(comb[r * Cc + 2 * u + 1], comb[r * Cc + 2 * u]);
        else if (u == 64) val = cvt_bf16x2(0.f, comb[r * Cc + 128]);
        Ab[e] = val;
    }
    const float* wvh = Wv + (size_t)hh * 129 * 129;
    const float* wqh = Wq + (size_t)hh * 129 * 16;
    const float* wkh = Wk + (size_t)hh * 129 * 16;
    for (int e = tid; e < 76 * 176; e += 256) {
        int u = e / 176, n = e - u * 176;
        float w0 = 0.f, w1 = 0.f;
        if (u < 65) {
            int k0 = 2 * u, k1 = 2 * u + 1;
            if (n < 129) {
                w0 = wvh[k0 * 129 + n];
                if (k1 < 129) w1 = wvh[k1 * 129 + n];
            } else if (n >= 136 && n < 152) {
                int kk = n - 136;
                w0 = wqh[k0 * 16 + kk];
                if (k1 < 129) w1 = wqh[k1 * 16 + kk];
            } else if (n >= 152 && n < 168) {
                int kk = n - 152;
                w0 = wkh[k0 * 16 + kk];
                if (k1 < 129) w1 = wkh[k1 * 16 + kk];
            }
        }
        Wt[n * 76 + u] = cvt_bf16x2(w1, w0);
    }
    for (int e = tid; e < 176; e += 256) {
        float bval = 0.f;
        if (e < 129) bval = bv[hh * 129 + e];
        else if (e >= 136 && e < 152) bval = bq[hh * 16 + e - 136];
        else if (e >= 152 && e < 168) bval = bk[hh * 16 + e - 152];
        bias_s[e] = bval;
    }
    __syncthreads();

    float acc[11][4];
    #pragma unroll
    for (int i = 0; i < 11; i++) { acc[i][0] = acc[i][1] = acc[i][2] = acc[i][3] = 0.f; }
    int ntb = wn * 11;

    #pragma unroll
    for (int ks = 0; ks < 9; ks++) {
        uint32_t a0 = Ab[(m0 + g) * 76 + 8 * ks + t];
        uint32_t a1 = Ab[(m0 + g + 8) * 76 + 8 * ks + t];
        uint32_t a2 = Ab[(m0 + g) * 76 + 8 * ks + t + 4];
        uint32_t a3 = Ab[(m0 + g + 8) * 76 + 8 * ks + t + 4];
        #pragma unroll
        for (int i = 0; i < 11; i++) {
            int nt = ntb + i;
            uint32_t b0 = Wt[(8 * nt + g) * 76 + 8 * ks + t];
            uint32_t b1 = Wt[(8 * nt + g) * 76 + 8 * ks + t + 4];
            mma_bf16(acc[i], a0, a1, a2, a3, b0, b1);
        }
    }

    size_t rowbase = (size_t)hh * ROWS + tile * 64 + m0;
    if (wn == 1) {
        #pragma unroll
        for (int i = 6; i < 10; i++) {
            int nt = 11 + i;
            bool isq = nt < 19;
            int col = (nt - (isq ? 17 : 19)) * 8 + 2 * t;
            float b0v = bias_s[(isq ? 136 : 152) + col];
            float b1v = bias_s[(isq ? 136 : 152) + col + 1];
            __nv_bfloat16* dst = isq ? g_qb : g_kb;
            *(uint32_t*)&dst[(rowbase + g) * 16 + col] =
                cvt_bf16x2(acc[i][1] + b1v, acc[i][0] + b0v);
            *(uint32_t*)&dst[(rowbase + g + 8) * 16 + col] =
                cvt_bf16x2(acc[i][3] + b1v, acc[i][2] + b0v);
        }
    }
    __syncthreads();
    float* vtile = (float*)smc;
    #pragma unroll
    for (int i = 0; i < 11; i++) {
        int nt = ntb + i;
        if (nt > 16) break;
        int col = 8 * nt + 2 * t;
        if (col <= 128) {
            float bb = bias_s[col];
            vtile[(m0 + g) * 132 + col]     = acc[i][0] + bb;
            vtile[(m0 + g + 8) * 132 + col] = acc[i][2] + bb;
        }
        if (col + 1 <= 128) {
            float bb = bias_s[col + 1];
            vtile[(m0 + g) * 132 + col + 1]     = acc[i][1] + bb;
            vtile[(m0 + g + 8) * 132 + col + 1] = acc[i][3] + bb;
        }
    }
    __syncthreads();

    int b_idx = tile >> 4;
    int mbase = (tile & 15) * 64;
    size_t hb = hh * 8 + b_idx;
    for (int e = tid; e < 128 * 32; e += 256) {
        int c = e >> 5, mp = e & 31;
        float f0 = vtile[(mp * 2) * 132 + c];
        float f1 = vtile[(mp * 2 + 1) * 132 + c];
        *(__nv_bfloat162*)&g_vtb[(hb * 128 + c) * 1024 + mbase + mp * 2] =
            __float22bfloat162_rn(make_float2(f0, f1));
    }
    if (tid < 64)
        g_v128[hb * 1024 + mbase + tid] = vtile[tid * 132 + 128];
}

// ---------------- K3: HMMA flash attention, 64-row CTAs, 2 CTA/SM ----------------
#define AKS_OFF 0
#define AVT_OFF 6144
#define AV1_OFF (6144 + 34816)
#define SMEM_ATT (AV1_OFF + 512)

__global__ void __launch_bounds__(128, 2) k_attn_mma() {
    extern __shared__ char smc[];
    uint32_t* Ks  = (uint32_t*)(smc + AKS_OFF);
    uint32_t* VTs = (uint32_t*)(smc + AVT_OFF);
    float*    v1s = (float*)(smc + AV1_OFF);
    int tid = threadIdx.x, w = tid >> 5, lane = tid & 31;
    int g = lane >> 2, t = lane & 3;
    int rblk = blockIdx.x, b = blockIdx.y, hh = blockIdx.z;
    size_t hb = hh * 8 + b;
    int brow = b * 1024 + rblk * 64;

    const __nv_bfloat16* qsrc = g_qb + ((size_t)hh * ROWS + brow + 16 * w) * 16;
    uint32_t qa0 = *(const uint32_t*)(qsrc + g * 16 + 2 * t);
    uint32_t qa1 = *(const uint32_t*)(qsrc + (g + 8) * 16 + 2 * t);
    uint32_t qa2 = *(const uint32_t*)(qsrc + g * 16 + 2 * t + 8);
    uint32_t qa3 = *(const uint32_t*)(qsrc + (g + 8) * 16 + 2 * t + 8);

    int nrow0 = rblk * 64 + 16 * w + g;
    int nrow1 = nrow0 + 8;

    float O[16][4];
    #pragma unroll
    for (int i = 0; i < 16; i++) { O[i][0] = O[i][1] = O[i][2] = O[i][3] = 0.f; }
    float rs0 = 0.f, rs1 = 0.f, ax0 = 0.f, ax1 = 0.f;

    const uint32_t* kbase = (const uint32_t*)(g_kb + ((size_t)hh * ROWS + b * 1024) * 16);
    const __nv_bfloat16* vbase = g_vtb + hb * 131072;

    for (int j = 0; j < 8; j++) {
        __syncthreads();
        const uint32_t* ks = kbase + j * 128 * 8;
        #pragma unroll
        for (int it = 0; it < 8; it++) {
            int e = tid + 128 * it;
            int r = e >> 3, c8 = e & 7;
            Ks[r * 12 + c8] = ks[e];
        }
        #pragma unroll
        for (int it = 0; it < 16; it++) {
            int e = tid + 128 * it;
            int c = e >> 4, q = e & 15;
            ((uint4*)(smc + AVT_OFF + c * 272))[q] =
                ((const uint4*)(vbase + (size_t)c * 1024 + j * 128))[q];
        }
        v1s[tid] = g_v128[hb * 1024 + j * 128 + tid];
        uint4 A0 = ((const uint4*)g_adjbits)[nrow0 * 8 + j];
        uint4 A1 = ((const uint4*)g_adjbits)[nrow1 * 8 + j];
        __syncthreads();

        uint32_t af[8][4];
        #pragma unroll
        for (int nt = 0; nt < 16; nt++) {
            uint32_t b0 = Ks[(8 * nt + g) * 12 + t];
            uint32_t b1 = Ks[(8 * nt + g) * 12 + t + 4];
            float c[4] = {0.f, 0.f, 0.f, 0.f};
            mma_bf16(c, qa0, qa1, qa2, qa3, b0, b1);
            uint32_t wA = (nt < 4) ? A0.x : (nt < 8) ? A0.y : (nt < 12) ? A0.z : A0.w;
            uint32_t wB = (nt < 4) ? A1.x : (nt < 8) ? A1.y : (nt < 12) ? A1.z : A1.w;
            int bitb = ((nt & 3) << 3) + 2 * t;
            float p00 = expleaky(c[0], (wA >> bitb) & 1);
            float p01 = expleaky(c[1], (wA >> (bitb + 1)) & 1);
            float p10 = expleaky(c[2], (wB >> bitb) & 1);
            float p11 = expleaky(c[3], (wB >> (bitb + 1)) & 1);
            rs0 += p00 + p01; rs1 += p10 + p11;
            float2 v2 = *(const float2*)&v1s[8 * nt + 2 * t];
            ax0 += p00 * v2.x + p01 * v2.y;
            ax1 += p10 * v2.x + p11 * v2.y;
            int kc = nt >> 1;
            if ((nt & 1) == 0) {
                af[kc][0] = cvt_bf16x2(p01, p00);
                af[kc][1] = cvt_bf16x2(p11, p10);
            } else {
                af[kc][2] = cvt_bf16x2(p01, p00);
                af[kc][3] = cvt_bf16x2(p11, p10);
            }
        }
        #pragma unroll
        for (int kc = 0; kc < 8; kc++) {
            #pragma unroll
            for (int nt2 = 0; nt2 < 16; nt2++) {
                uint32_t b0 = VTs[(8 * nt2 + g) * 68 + 8 * kc + t];
                uint32_t b1 = VTs[(8 * nt2 + g) * 68 + 8 * kc + t + 4];
                mma_bf16(O[nt2], af[kc][0], af[kc][1], af[kc][2], af[kc][3], b0, b1);
            }
        }
    }

    rs0 += __shfl_xor_sync(0xFFFFFFFFu, rs0, 1); rs0 += __shfl_xor_sync(0xFFFFFFFFu, rs0, 2);
    rs1 += __shfl_xor_sync(0xFFFFFFFFu, rs1, 1); rs1 += __shfl_xor_sync(0xFFFFFFFFu, rs1, 2);
    ax0 += __shfl_xor_sync(0xFFFFFFFFu, ax0, 1); ax0 += __shfl_xor_sync(0xFFFFFFFFu, ax0, 2);
    ax1 += __shfl_xor_sync(0xFFFFFFFFu, ax1, 1); ax1 += __shfl_xor_sync(0xFFFFFFFFu, ax1, 2);
    float inv0 = 1.f / rs0, inv1 = 1.f / rs1;

    float* d0 = g_hp + ((size_t)(brow + 16 * w + g) * 4 + hh) * 132;
    float* d1 = d0 + 8 * 4 * 132;
    #pragma unroll
    for (int nt2 = 0; nt2 < 16; nt2++) {
        *(float2*)&d0[8 * nt2 + 2 * t] = make_float2(O[nt2][0] * inv0, O[nt2][1] * inv0);
        *(float2*)&d1[8 * nt2 + 2 * t] = make_float2(O[nt2][2] * inv1, O[nt2][3] * inv1);
    }
    if (t == 0) { d0[128] = ax0 * inv0; d1[128] = ax1 * inv1; }
}

// ---------------- K4: attention MLP + skip via tf32 mma ----------------
#define MLP_A_OFF 0
#define MLP_W_OFF 35840
#define MLP_H_OFF (35840 + 80640)
#define MLP_B_OFF (MLP_H_OFF + 35840)
#define SMEM_MLP (MLP_B_OFF + 272 * 4)

__global__ void __launch_bounds__(256) k_mlp(const float* __restrict__ W1, const float* __restrict__ b1,
                                             const float* __restrict__ W2, const float* __restrict__ b2) {
    extern __shared__ char smc[];
    uint32_t* As = (uint32_t*)(smc + MLP_A_OFF);
    uint32_t* Ws = (uint32_t*)(smc + MLP_W_OFF);
    uint32_t* Hs = (uint32_t*)(smc + MLP_H_OFF);
    float* bias_s = (float*)(smc + MLP_B_OFF);
    int blk = blockIdx.x, tid = threadIdx.x;
    int w = tid >> 5, lane = tid & 31, g = lane >> 2, t = lane & 3;
    int wm = w & 3, wn = w >> 2;
    int m0 = wm * 16;

    for (int e = tid; e < 64 * 140; e += 256) Hs[e] = 0;
    for (int e = tid; e < 272; e += 256) {
        float bval = 0.f;
        if (e < 129) bval = b1[e];
        else if (e >= 136 && e < 265) bval = b2[e - 136];
        bias_s[e] = bval;
    }

    float acc[9][4];
    #pragma unroll
    for (int i = 0; i < 9; i++) { acc[i][0] = acc[i][1] = acc[i][2] = acc[i][3] = 0.f; }

    for (int kc = 0; kc < 4; kc++) {
        __syncthreads();
        for (int e = tid; e < 64 * 140; e += 256) {
            int r = e / 140, u = e - r * 140;
            As[e] = (u < 129) ? to_tf32(g_hp[((size_t)(blk * 64 + r) * 4 + kc) * 132 + u]) : 0;
        }
        for (int e = tid; e < 140 * 144; e += 256) {
            int u = e / 144, n = e - u * 144;
            Ws[n * 140 + u] = (u < 129 && n < 129)
                ? to_tf32(W1[((size_t)kc * 129 + u) * 129 + n]) : 0;
        }
        __syncthreads();
        #pragma unroll
        for (int ks = 0; ks < 17; ks++) {
            uint32_t a0 = As[(m0 + g) * 140 + 8 * ks + t];
            uint32_t a1 = As[(m0 + g + 8) * 140 + 8 * ks + t];
            uint32_t a2 = As[(m0 + g) * 140 + 8 * ks + t + 4];
            uint32_t a3 = As[(m0 + g + 8) * 140 + 8 * ks + t + 4];
            #pragma unroll
            for (int i = 0; i < 9; i++) {
                int nt = wn * 9 + i;
                uint32_t b0 = Ws[(8 * nt + g) * 140 + 8 * ks + t];
                uint32_t b1r = Ws[(8 * nt + g) * 140 + 8 * ks + t + 4];
                mma_tf32(acc[i], a0, a1, a2, a3, b0, b1r);
            }
        }
    }
    #pragma unroll
    for (int i = 0; i < 9; i++) {
        int nt = wn * 9 + i;
        int col = 8 * nt + 2 * t;
        if (col <= 128) {
            Hs[(m0 + g) * 140 + col]     = to_tf32(fmaxf(acc[i][0] + bias_s[col], 0.f));
            Hs[(m0 + g + 8) * 140 + col] = to_tf32(fmaxf(acc[i][2] + bias_s[col], 0.f));
        }
        if (col + 1 <= 128) {
            Hs[(m0 + g) * 140 + col + 1]     = to_tf32(fmaxf(acc[i][1] + bias_s[col + 1], 0.f));
            Hs[(m0 + g + 8) * 140 + col + 1] = to_tf32(fmaxf(acc[i][3] + bias_s[col + 1], 0.f));
        }
        acc[i][0] = acc[i][1] = acc[i][2] = acc[i][3] = 0.f;
    }
    __syncthreads();
    for (int e = tid; e < 140 * 144; e += 256) {
        int u = e / 144, n = e - u * 144;
        Ws[n * 140 + u] = (u < 129 && n < 129) ? to_tf32(W2[(size_t)u * 129 + n]) : 0;
    }
    __syncthreads();
    #pragma unroll
    for (int ks = 0; ks < 17; ks++) {
        uint32_t a0 = Hs[(m0 + g) * 140 + 8 * ks + t];
        uint32_t a1 = Hs[(m0 + g + 8) * 140 + 8 * ks + t];
        uint32_t a2 = Hs[(m0 + g) * 140 + 8 * ks + t + 4];
        uint32_t a3 = Hs[(m0 + g + 8) * 140 + 8 * ks + t + 4];
        #pragma unroll
        for (int i = 0; i < 9; i++) {
            int nt = wn * 9 + i;
            uint32_t b0 = Ws[(8 * nt + g) * 140 + 8 * ks + t];
            uint32_t b1r = Ws[(8 * nt + g) * 140 + 8 * ks + t + 4];
            mma_tf32(acc[i], a0, a1, a2, a3, b0, b1r);
        }
    }
    #pragma unroll
    for (int i = 0; i < 9; i++) {
        int nt = wn * 9 + i;
        int col = 8 * nt + 2 * t;
        if (col <= 128) {
            int idx = (blk * 64 + m0 + g) * Cc + col;
            g_combined[idx]          += acc[i][0] + bias_s[136 + col];
            g_combined[idx + 8 * Cc] += acc[i][2] + bias_s[136 + col];
        }
        if (col + 1 <= 128) {
            int idx = (blk * 64 + m0 + g) * Cc + col + 1;
            g_combined[idx]          += acc[i][1] + bias_s[137 + col];
            g_combined[idx + 8 * Cc] += acc[i][3] + bias_s[137 + col];
        }
    }
}

// ---------------- K5: r,u gates via tf32 mma, W-prefetch pipelined ----------------
__global__ void __launch_bounds__(512) k_gate_ru(const float* __restrict__ qv,
                                                 const int* __restrict__ nodes_b, const int* __restrict__ nodes_n,
                                                 const float* __restrict__ Wr, const float* __restrict__ br,
                                                 const float* __restrict__ Wu, const float* __restrict__ bu,
                                                 const float* __restrict__ x, const float* __restrict__ hin) {
    extern __shared__ float sm[];
    float*    sel_s = sm;                              // [64][132]
    float*    qv_s  = sel_s + 64 * 132;                // [64][33]
    uint32_t* Zs    = (uint32_t*)(qv_s + 64 * 33);     // [64][132] tf32
    uint32_t* Ws    = Zs + 64 * 132;                   // [2][132][36] tf32
    float*    bs    = (float*)(Ws + 2 * 132 * 36);     // [2][32][34]
    int blk = blockIdx.x, nh = blockIdx.y, tid = threadIdx.x;
    int ob = nh * 32;
    int w = tid >> 5, lane = tid & 31;
    int g = lane >> 2, t = lane & 3;
    int mt = w & 3, mat = (w >> 2) & 1, nsub = w >> 3;
    int m0 = mt * 16, n0l = nsub * 16;

    for (int e = tid; e < 64 * 132; e += 512) {
        int lm = e / 132, i = e - lm * 132;
        int gm = blk * 64 + lm;
        int node = nodes_b[gm] * Nn + nodes_n[gm];
        sel_s[e] = (i < Cc) ? g_combined[node * Cc + i] : 0.f;
    }
    for (int e = tid; e < 64 * 32; e += 512) {
        int lm = e >> 5, d = e & 31;
        qv_s[lm * 33 + d] = qv[(blk * 64 + lm) * 32 + d];
    }
    for (int e = tid; e < 2048; e += 512) {
        int m2 = e >> 10, r2 = e & 1023;
        int d2 = r2 >> 5, o = r2 & 31;
        bs[m2 * 1088 + d2 * 34 + o] = (m2 ? bu : br)[d2 * 64 + ob + o];
    }
    __syncthreads();

    float wreg[17];
    auto ldW = [&](int d) {
        #pragma unroll
        for (int it = 0; it < 17; it++) {
            int e = tid + 512 * it;
            if (e < 8256) {
                int m2 = (e >= 4128);
                int e2 = e - m2 * 4128;
                int k = e2 >> 5, o = e2 & 31;
                wreg[it] = (m2 ? Wu : Wr)[((size_t)d * Cc + k) * 64 + ob + o];
            }
        }
    };
    auto stW = [&]() {
        #pragma unroll
        for (int it = 0; it < 17; it++) {
            int e = tid + 512 * it;
            if (e < 8256) {
                int m2 = (e >= 4128);
                int e2 = e - m2 * 4128;
                int k = e2 >> 5, o = e2 & 31;
                Ws[m2 * 4752 + k * 36 + o] = to_tf32(wreg[it]);
            }
        }
    };
    auto bldZ = [&](int d) {
        for (int e = tid; e < 64 * 132; e += 512) {
            int lm = e / 132;
            Zs[e] = to_tf32(qv_s[lm * 33 + d] * sel_s[e]);
        }
    };

    ldW(0);
    stW();
    bldZ(0);
    __syncthreads();

    float acc[2][4] = {};
    const uint32_t* Wm = Ws + mat * 4752;

    for (int d = 0; d < 32; d++) {
        if (d < 31) ldW(d + 1);
        #pragma unroll 4
        for (int ks = 0; ks < 16; ks++) {
            int k0 = ks * 8;
            uint32_t a0 = Zs[(m0 + g) * 132 + k0 + t];
            uint32_t a1 = Zs[(m0 + g + 8) * 132 + k0 + t];
            uint32_t a2 = Zs[(m0 + g) * 132 + k0 + t + 4];
            uint32_t a3 = Zs[(m0 + g + 8) * 132 + k0 + t + 4];
            #pragma unroll
            for (int cn = 0; cn < 2; cn++) {
                uint32_t b0 = Wm[(k0 + t) * 36 + n0l + cn * 8 + g];
                uint32_t b1 = Wm[(k0 + t + 4) * 36 + n0l + cn * 8 + g];
                mma_tf32(acc[cn], a0, a1, a2, a3, b0, b1);
            }
        }
        float z0 = __uint_as_float(Zs[(m0 + g) * 132 + 128]);
        float z1 = __uint_as_float(Zs[(m0 + g + 8) * 132 + 128]);
        #pragma unroll
        for (int cn = 0; cn < 2; cn++) {
            float w0 = __uint_as_float(Wm[128 * 36 + n0l + cn * 8 + 2 * t]);
            float w1 = __uint_as_float(Wm[128 * 36 + n0l + cn * 8 + 2 * t + 1]);
            acc[cn][0] += z0 * w0; acc[cn][1] += z0 * w1;
            acc[cn][2] += z1 * w0; acc[cn][3] += z1 * w1;
        }
        __syncthreads();
        if (d < 31) {
            stW();
            bldZ(d + 1);
            __syncthreads();
        }
    }

    const float* bm = bs + mat * 1088;
    #pragma unroll 4
    for (int d = 0; d < 32; d++) {
        float q0 = qv_s[(m0 + g) * 33 + d];
        float q1 = qv_s[(m0 + g + 8) * 33 + d];
        #pragma unroll
        for (int cn = 0; cn < 2; cn++) {
            float w0 = bm[d * 34 + n0l + cn * 8 + 2 * t];
            float w1 = bm[d * 34 + n0l + cn * 8 + 2 * t + 1];
            acc[cn][0] += q0 * w0; acc[cn][1] += q0 * w1;
            acc[cn][2] += q1 * w0; acc[cn][3] += q1 * w1;
        }
    }

    __syncthreads();
    float* stg = (float*)Zs;
    int cb = mat * 40;
    #pragma unroll
    for (int cn = 0; cn < 2; cn++) {
        int col = cb + n0l + cn * 8 + 2 * t;
        stg[(m0 + g) * 132 + col]     = acc[cn][0];
        stg[(m0 + g) * 132 + col + 1] = acc[cn][1];
        stg[(m0 + g + 8) * 132 + col]     = acc[cn][2];
        stg[(m0 + g + 8) * 132 + col + 1] = acc[cn][3];
    }
    __syncthreads();

    for (int e = tid; e < 64 * 32; e += 512) {
        int lm = e >> 5, o = e & 31;
        int gm = blk * 64 + lm;
        int node = nodes_b[gm] * Nn + nodes_n[gm];
        float ar = stg[lm * 132 + o];
        float au = stg[lm * 132 + 40 + o];
        float hv = hin[node * 64 + ob + o];
        float r = 1.f / (1.f + __expf(-ar));
        float u = 1.f / (1.f + __expf(-au));
        float hn = r * hv;
        g_hn[gm * 64 + ob + o] = hn;
        g_u[gm * 64 + ob + o] = u;
        g_sel2[gm * Cc + 65 + ob + o] = hn;
    }
    if (nh == 0) {
        for (int e = tid; e < 64 * 65; e += 512) {
            int lm = e / 65, i = e - lm * 65;
            int gm = blk * 64 + lm;
            int node = nodes_b[gm] * Nn + nodes_n[gm];
            g_sel2[gm * Cc + i] = x[node * 65 + i];
        }
    }
}

// ---------------- K6: cand gate via tf32 mma, pipelined + final update ----------------
__global__ void __launch_bounds__(256) k_gate_c(const float* __restrict__ qv,
                                                const float* __restrict__ Wc, const float* __restrict__ bc,
                                                float* __restrict__ out) {
    extern __shared__ float sm[];
    float*    sel_s = sm;
    float*    qv_s  = sel_s + 64 * 132;
    uint32_t* Zs    = (uint32_t*)(qv_s + 64 * 33);
    uint32_t* Ws    = Zs + 64 * 132;
    float*    bs    = (float*)(Ws + 132 * 36);
    int blk = blockIdx.x, nh = blockIdx.y, tid = threadIdx.x;
    int ob = nh * 32;
    int w = tid >> 5, lane = tid & 31;
    int g = lane >> 2, t = lane & 3;
    int mt = w & 3, nsub = w >> 2;
    int m0 = mt * 16, n0l = nsub * 16;

    for (int e = tid; e < 64 * 132; e += 256) {
        int lm = e / 132, i = e - lm * 132;
        sel_s[e] = (i < Cc) ? g_sel2[(blk * 64 + lm) * Cc + i] : 0.f;
    }
    for (int e = tid; e < 64 * 32; e += 256) {
        int lm = e >> 5, d = e & 31;
        qv_s[lm * 33 + d] = qv[(blk * 64 + lm) * 32 + d];
    }
    for (int e = tid; e < 1024; e += 256) {
        int d2 = e >> 5, o = e & 31;
        bs[d2 * 34 + o] = bc[d2 * 64 + ob + o];
    }
    __syncthreads();

    float wreg[17];
    auto ldW = [&](int d) {
        #pragma unroll
        for (int it = 0; it < 17; it++) {
            int e = tid + 256 * it;
            if (e < 4128) {
                int k = e >> 5, o = e & 31;
                wreg[it] = Wc[((size_t)d * Cc + k) * 64 + ob + o];
            }
        }
    };
    auto stW = [&]() {
        #pragma unroll
        for (int it = 0; it < 17; it++) {
            int e = tid + 256 * it;
            if (e < 4128) {
                int k = e >> 5, o = e & 31;
                Ws[k * 36 + o] = to_tf32(wreg[it]);
            }
        }
    };
    auto bldZ = [&](int d) {
        for (int e = tid; e < 64 * 132; e += 256) {
            int lm = e / 132;
            Zs[e] = to_tf32(qv_s[lm * 33 + d] * sel_s[e]);
        }
    };

    ldW(0);
    stW();
    bldZ(0);
    __syncthreads();

    float acc[2][4] = {};

    for (int d = 0; d < 32; d++) {
        if (d < 31) ldW(d + 1);
        #pragma unroll 4
        for (int ks = 0; ks < 16; ks++) {
            int k0 = ks * 8;
            uint32_t a0 = Zs[(m0 + g) * 132 + k0 + t];
            uint32_t a1 = Zs[(m0 + g + 8) * 132 + k0 + t];
            uint32_t a2 = Zs[(m0 + g) * 132 + k0 + t + 4];
            uint32_t a3 = Zs[(m0 + g + 8) * 132 + k0 + t + 4];
            #pragma unroll
            for (int cn = 0; cn < 2; cn++) {
                uint32_t b0 = Ws[(k0 + t) * 36 + n0l + cn * 8 + g];
                uint32_t b1 = Ws[(k0 + t + 4) * 36 + n0l + cn * 8 + g];
                mma_tf32(acc[cn], a0, a1, a2, a3, b0, b1);
            }
        }
        float z0 = __uint_as_float(Zs[(m0 + g) * 132 + 128]);
        float z1 = __uint_as_float(Zs[(m0 + g + 8) * 132 + 128]);
        #pragma unroll
        for (int cn = 0; cn < 2; cn++) {
            float w0 = __uint_as_float(Ws[128 * 36 + n0l + cn * 8 + 2 * t]);
            float w1 = __uint_as_float(Ws[128 * 36 + n0l + cn * 8 + 2 * t + 1]);
            acc[cn][0] += z0 * w0; acc[cn][1] += z0 * w1;
            acc[cn][2] += z1 * w0; acc[cn][3] += z1 * w1;
        }
        __syncthreads();
        if (d < 31) {
            stW();
            bldZ(d + 1);
            __syncthreads();
        }
    }

    #pragma unroll 4
    for (int d = 0; d < 32; d++) {
        float q0 = qv_s[(m0 + g) * 33 + d];
        float q1 = qv_s[(m0 + g + 8) * 33 + d];
        #pragma unroll
        for (int cn = 0; cn < 2; cn++) {
            float w0 = bs[d * 34 + n0l + cn * 8 + 2 * t];
            float w1 = bs[d * 34 + n0l + cn * 8 + 2 * t + 1];
            acc[cn][0] += q0 * w0; acc[cn][1] += q0 * w1;
            acc[cn][2] += q1 * w0; acc[cn][3] += q1 * w1;
        }
    }

    int gm0 = blk * 64 + m0 + g;
    int gm1 = gm0 + 8;
    #pragma unroll
    for (int cn = 0; cn < 2; cn++) {
        int col = ob + n0l + cn * 8 + 2 * t;
        #pragma unroll
        for (int jj = 0; jj < 2; jj++) {
            int gm = jj ? gm1 : gm0;
            float c0 = acc[cn][2 * jj], c1 = acc[cn][2 * jj + 1];
            float u0 = g_u[gm * 64 + col],     hn0 = g_hn[gm * 64 + col];
            float u1 = g_u[gm * 64 + col + 1], hn1 = g_hn[gm * 64 + col + 1];
            out[gm * 64 + col]     = (1.f - u0) * hn0 + u0 * tanhf(c0);
            out[gm * 64 + col + 1] = (1.f - u1) * hn1 + u1 * tanhf(c1);
        }
    }
}

// ---------------- launch ----------------
extern "C" void kernel_launch(void* const* d_in, const int* in_sizes, int n_in,
                              void* d_out, int out_size) {
    const float* x   = (const float*)d_in[0];
    const float* h   = (const float*)d_in[1];
    const float* qv  = (const float*)d_in[2];
    const int*   adj = (const int*)  d_in[3];
    const int*   nb  = (const int*)  d_in[4];
    const int*   nn  = (const int*)  d_in[5];
    const float* Wq  = (const float*)d_in[6];
    const float* bq  = (const float*)d_in[7];
    const float* Wk  = (const float*)d_in[8];
    const float* bk  = (const float*)d_in[9];
    const float* Wv  = (const float*)d_in[10];
    const float* bv  = (const float*)d_in[11];
    const float* W1  = (const float*)d_in[12];
    const float* b1  = (const float*)d_in[13];
    const float* W2  = (const float*)d_in[14];
    const float* b2  = (const float*)d_in[15];
    const float* Wr  = (const float*)d_in[16];
    const float* br  = (const float*)d_in[17];
    const float* Wu  = (const float*)d_in[18];
    const float* bu  = (const float*)d_in[19];
    const float* Wc  = (const float*)d_in[20];
    const float* bc  = (const float*)d_in[21];
    float* out = (float*)d_out;

    const int SZ_RU = (64 * 132 + 64 * 33 + 64 * 132 + 2 * 132 * 36 + 2 * 32 * 34 + 16) * 4;
    const int SZ_C  = (64 * 132 + 64 * 33 + 64 * 132 + 132 * 36 + 32 * 34 + 16) * 4;

    cudaFuncSetAttribute(k_qkv,      cudaFuncAttributeMaxDynamicSharedMemorySize, SMEM_QKV);
    cudaFuncSetAttribute(k_attn_mma, cudaFuncAttributeMaxDynamicSharedMemorySize, SMEM_ATT);
    cudaFuncSetAttribute(k_mlp,      cudaFuncAttributeMaxDynamicSharedMemorySize, SMEM_MLP);
    cudaFuncSetAttribute(k_gate_ru,  cudaFuncAttributeMaxDynamicSharedMemorySize, SZ_RU);
    cudaFuncSetAttribute(k_gate_c,   cudaFuncAttributeMaxDynamicSharedMemorySize, SZ_C);

    k_combined<<<(ROWS * Cc + 255) / 256, 256>>>(x, h);
    k_adjpack<<<(Nn * Nn) / 256, 256>>>(adj);
    k_qkv<<<dim3(128, 4), 256, SMEM_QKV>>>(Wv, bv, Wq, bq, Wk, bk);
    k_attn_mma<<<dim3(16, 8, 4), 128, SMEM_ATT>>>();
    k_mlp<<<128, 256, SMEM_MLP>>>(W1, b1, W2, b2);
    k_gate_ru<<<dim3(64, 2), 512, SZ_RU>>>(qv, nb, nn, Wr, br, Wu, bu, x, h);
    k_gate_c<<<dim3(64, 2), 256, SZ_C>>>(qv, Wc, bc, out);
}

// round 11
// speedup vs baseline: 4.1803x; 1.0887x over previous
#include <cuda_runtime.h>
#include <cuda_bf16.h>
#include <cstdint>
#include <math.h>

#define Bb   8
#define Nn   1024
#define Dd   64
#define Hh   4
#define Cc   129
#define Kk   16
#define Mm   4096
#define ROWS 8192   // B*N

// ---------------- helpers ----------------
__device__ __forceinline__ uint32_t cvt_bf16x2(float hi, float lo) {
    uint32_t r;
    asm("cvt.rn.bf16x2.f32 %0, %1, %2;" : "=r"(r) : "f"(hi), "f"(lo));
    return r;
}
__device__ __forceinline__ uint32_t to_tf32(float f) {
    uint32_t r;
    asm("cvt.rna.tf32.f32 %0, %1;" : "=r"(r) : "f"(f));
    return r;
}
__device__ __forceinline__ void mma_bf16(float c[4], uint32_t a0, uint32_t a1, uint32_t a2, uint32_t a3,
                                         uint32_t b0, uint32_t b1) {
    asm volatile("mma.sync.aligned.m16n8k16.row.col.f32.bf16.bf16.f32 "
                 "{%0,%1,%2,%3}, {%4,%5,%6,%7}, {%8,%9}, {%0,%1,%2,%3};"
                 : "+f"(c[0]), "+f"(c[1]), "+f"(c[2]), "+f"(c[3])
                 : "r"(a0), "r"(a1), "r"(a2), "r"(a3), "r"(b0), "r"(b1));
}
__device__ __forceinline__ void mma_tf32(float c[4], uint32_t a0, uint32_t a1, uint32_t a2, uint32_t a3,
                                         uint32_t b0, uint32_t b1) {
    asm volatile("mma.sync.aligned.m16n8k8.row.col.f32.tf32.tf32.f32 "
                 "{%0,%1,%2,%3}, {%4,%5,%6,%7}, {%8,%9}, {%0,%1,%2,%3};"
                 : "+f"(c[0]), "+f"(c[1]), "+f"(c[2]), "+f"(c[3])
                 : "r"(a0), "r"(a1), "r"(a2), "r"(a3), "r"(b0), "r"(b1));
}
__device__ __forceinline__ float expleaky(float s, uint32_t bit) {
    s *= 0.25f;
    s = s > 0.f ? s : 0.2f * s;
    return bit ? __expf(s) : 0.f;
}

// ================= scratch =================
__device__ float g_combined[ROWS * Cc];
__device__ __nv_bfloat16 g_qb[Hh * ROWS * Kk];
__device__ __nv_bfloat16 g_kb[Hh * ROWS * Kk];
__device__ __nv_bfloat16 g_vtb[Hh * Bb * 128 * 1024];   // [h*8+b][c<128][m]
__device__ float g_v128[Hh * Bb * 1024];                // v col 128
__device__ uint32_t g_adjbits[Nn * 32];
__device__ float g_hp[ROWS * 4 * 132];                  // [row][h][132 padded], normalized
__device__ float g_hn[Mm * Dd];
__device__ float g_u[Mm * Dd];
__device__ float g_sel2[Mm * Cc];

// ---------------- K0: combined = concat(x, h) ----------------
__global__ void k_combined(const float* __restrict__ x, const float* __restrict__ h) {
    int idx = blockIdx.x * 256 + threadIdx.x;
    if (idx >= ROWS * Cc) return;
    int row = idx / Cc, c = idx - row * Cc;
    g_combined[idx] = (c < 65) ? x[row * 65 + c] : h[row * 64 + (c - 65)];
}

// ---------------- K0b: pack adjacency bits ----------------
__global__ void k_adjpack(const int* __restrict__ adj) {
    int idx = blockIdx.x * 256 + threadIdx.x;
    uint32_t bits = __ballot_sync(0xFFFFFFFFu, adj[idx] != 0);
    if ((idx & 31) == 0) g_adjbits[idx >> 5] = bits;
}

// ---------------- K1: fused q/k/v projections via bf16 mma ----------------
#define QKV_AB_OFF 0
#define QKV_WT_OFF 19456
#define QKV_BS_OFF (19456 + 53504)
#define SMEM_QKV (QKV_BS_OFF + 176 * 4)

__global__ void __launch_bounds__(256, 2) k_qkv(const float* __restrict__ Wv, const float* __restrict__ bv,
                                                const float* __restrict__ Wq, const float* __restrict__ bq,
                                                const float* __restrict__ Wk, const float* __restrict__ bk) {
    extern __shared__ char smc[];
    uint32_t* Ab = (uint32_t*)(smc + QKV_AB_OFF);
    uint32_t* Wt = (uint32_t*)(smc + QKV_WT_OFF);
    float* bias_s = (float*)(smc + QKV_BS_OFF);
    int tile = blockIdx.x, hh = blockIdx.y, tid = threadIdx.x;
    int w = tid >> 5, lane = tid & 31, g = lane >> 2, t = lane & 3;
    int wm = w & 3, wn = w >> 2;
    int m0 = wm * 16;

    const float* comb = g_combined + (size_t)(tile * 64) * Cc;
    for (int e = tid; e < 64 * 76; e += 256) {
        int r = e / 76, u = e - r * 76;
        uint32_t val = 0;
        if (u < 64)       val = cvt_bf16x2(comb[r * Cc + 2 * u + 1], comb[r * Cc + 2 * u]);
        else if (u == 64) val = cvt_bf16x2(0.f, comb[r * Cc + 128]);
        Ab[e] = val;
    }
    const float* wvh = Wv + (size_t)hh * 129 * 129;
    const float* wqh = Wq + (size_t)hh * 129 * 16;
    const float* wkh = Wk + (size_t)hh * 129 * 16;
    for (int e = tid; e < 76 * 176; e += 256) {
        int u = e / 176, n = e - u * 176;
        float w0 = 0.f, w1 = 0.f;
        if (u < 65) {
            int k0 = 2 * u, k1 = 2 * u + 1;
            if (n < 129) {
                w0 = wvh[k0 * 129 + n];
                if (k1 < 129) w1 = wvh[k1 * 129 + n];
            } else if (n >= 136 && n < 152) {
                int kk = n - 136;
                w0 = wqh[k0 * 16 + kk];
                if (k1 < 129) w1 = wqh[k1 * 16 + kk];
            } else if (n >= 152 && n < 168) {
                int kk = n - 152;
                w0 = wkh[k0 * 16 + kk];
                if (k1 < 129) w1 = wkh[k1 * 16 + kk];
            }
        }
        Wt[n * 76 + u] = cvt_bf16x2(w1, w0);
    }
    for (int e = tid; e < 176; e += 256) {
        float bval = 0.f;
        if (e < 129) bval = bv[hh * 129 + e];
        else if (e >= 136 && e < 152) bval = bq[hh * 16 + e - 136];
        else if (e >= 152 && e < 168) bval = bk[hh * 16 + e - 152];
        bias_s[e] = bval;
    }
    __syncthreads();

    float acc[11][4];
    #pragma unroll
    for (int i = 0; i < 11; i++) { acc[i][0] = acc[i][1] = acc[i][2] = acc[i][3] = 0.f; }
    int ntb = wn * 11;

    #pragma unroll
    for (int ks = 0; ks < 9; ks++) {
        uint32_t a0 = Ab[(m0 + g) * 76 + 8 * ks + t];
        uint32_t a1 = Ab[(m0 + g + 8) * 76 + 8 * ks + t];
        uint32_t a2 = Ab[(m0 + g) * 76 + 8 * ks + t + 4];
        uint32_t a3 = Ab[(m0 + g + 8) * 76 + 8 * ks + t + 4];
        #pragma unroll
        for (int i = 0; i < 11; i++) {
            int nt = ntb + i;
            uint32_t b0 = Wt[(8 * nt + g) * 76 + 8 * ks + t];
            uint32_t b1 = Wt[(8 * nt + g) * 76 + 8 * ks + t + 4];
            mma_bf16(acc[i], a0, a1, a2, a3, b0, b1);
        }
    }

    size_t rowbase = (size_t)hh * ROWS + tile * 64 + m0;
    if (wn == 1) {
        #pragma unroll
        for (int i = 6; i < 10; i++) {
            int nt = 11 + i;
            bool isq = nt < 19;
            int col = (nt - (isq ? 17 : 19)) * 8 + 2 * t;
            float b0v = bias_s[(isq ? 136 : 152) + col];
            float b1v = bias_s[(isq ? 136 : 152) + col + 1];
            __nv_bfloat16* dst = isq ? g_qb : g_kb;
            *(uint32_t*)&dst[(rowbase + g) * 16 + col] =
                cvt_bf16x2(acc[i][1] + b1v, acc[i][0] + b0v);
            *(uint32_t*)&dst[(rowbase + g + 8) * 16 + col] =
                cvt_bf16x2(acc[i][3] + b1v, acc[i][2] + b0v);
        }
    }
    __syncthreads();
    float* vtile = (float*)smc;
    #pragma unroll
    for (int i = 0; i < 11; i++) {
        int nt = ntb + i;
        if (nt > 16) break;
        int col = 8 * nt + 2 * t;
        if (col <= 128) {
            float bb = bias_s[col];
            vtile[(m0 + g) * 132 + col]     = acc[i][0] + bb;
            vtile[(m0 + g + 8) * 132 + col] = acc[i][2] + bb;
        }
        if (col + 1 <= 128) {
            float bb = bias_s[col + 1];
            vtile[(m0 + g) * 132 + col + 1]     = acc[i][1] + bb;
            vtile[(m0 + g + 8) * 132 + col + 1] = acc[i][3] + bb;
        }
    }
    __syncthreads();

    int b_idx = tile >> 4;
    int mbase = (tile & 15) * 64;
    size_t hb = hh * 8 + b_idx;
    for (int e = tid; e < 128 * 32; e += 256) {
        int c = e >> 5, mp = e & 31;
        float f0 = vtile[(mp * 2) * 132 + c];
        float f1 = vtile[(mp * 2 + 1) * 132 + c];
        *(__nv_bfloat162*)&g_vtb[(hb * 128 + c) * 1024 + mbase + mp * 2] =
            __float22bfloat162_rn(make_float2(f0, f1));
    }
    if (tid < 64)
        g_v128[hb * 1024 + mbase + tid] = vtile[tid * 132 + 128];
}

// ---------------- K3: HMMA flash attention, 64-row CTAs, 2 CTA/SM ----------------
#define AKS_OFF 0
#define AVT_OFF 6144
#define AV1_OFF (6144 + 34816)
#define SMEM_ATT (AV1_OFF + 512)

__global__ void __launch_bounds__(128, 2) k_attn_mma() {
    extern __shared__ char smc[];
    uint32_t* Ks  = (uint32_t*)(smc + AKS_OFF);
    uint32_t* VTs = (uint32_t*)(smc + AVT_OFF);
    float*    v1s = (float*)(smc + AV1_OFF);
    int tid = threadIdx.x, w = tid >> 5, lane = tid & 31;
    int g = lane >> 2, t = lane & 3;
    int rblk = blockIdx.x, b = blockIdx.y, hh = blockIdx.z;
    size_t hb = hh * 8 + b;
    int brow = b * 1024 + rblk * 64;

    const __nv_bfloat16* qsrc = g_qb + ((size_t)hh * ROWS + brow + 16 * w) * 16;
    uint32_t qa0 = *(const uint32_t*)(qsrc + g * 16 + 2 * t);
    uint32_t qa1 = *(const uint32_t*)(qsrc + (g + 8) * 16 + 2 * t);
    uint32_t qa2 = *(const uint32_t*)(qsrc + g * 16 + 2 * t + 8);
    uint32_t qa3 = *(const uint32_t*)(qsrc + (g + 8) * 16 + 2 * t + 8);

    int nrow0 = rblk * 64 + 16 * w + g;
    int nrow1 = nrow0 + 8;

    float O[16][4];
    #pragma unroll
    for (int i = 0; i < 16; i++) { O[i][0] = O[i][1] = O[i][2] = O[i][3] = 0.f; }
    float rs0 = 0.f, rs1 = 0.f, ax0 = 0.f, ax1 = 0.f;

    const uint32_t* kbase = (const uint32_t*)(g_kb + ((size_t)hh * ROWS + b * 1024) * 16);
    const __nv_bfloat16* vbase = g_vtb + hb * 131072;

    for (int j = 0; j < 8; j++) {
        __syncthreads();
        const uint32_t* ks = kbase + j * 128 * 8;
        #pragma unroll
        for (int it = 0; it < 8; it++) {
            int e = tid + 128 * it;
            int r = e >> 3, c8 = e & 7;
            Ks[r * 12 + c8] = ks[e];
        }
        #pragma unroll
        for (int it = 0; it < 16; it++) {
            int e = tid + 128 * it;
            int c = e >> 4, q = e & 15;
            ((uint4*)(smc + AVT_OFF + c * 272))[q] =
                ((const uint4*)(vbase + (size_t)c * 1024 + j * 128))[q];
        }
        v1s[tid] = g_v128[hb * 1024 + j * 128 + tid];
        uint4 A0 = ((const uint4*)g_adjbits)[nrow0 * 8 + j];
        uint4 A1 = ((const uint4*)g_adjbits)[nrow1 * 8 + j];
        __syncthreads();

        uint32_t af[8][4];
        #pragma unroll
        for (int nt = 0; nt < 16; nt++) {
            uint32_t b0 = Ks[(8 * nt + g) * 12 + t];
            uint32_t b1 = Ks[(8 * nt + g) * 12 + t + 4];
            float c[4] = {0.f, 0.f, 0.f, 0.f};
            mma_bf16(c, qa0, qa1, qa2, qa3, b0, b1);
            uint32_t wA = (nt < 4) ? A0.x : (nt < 8) ? A0.y : (nt < 12) ? A0.z : A0.w;
            uint32_t wB = (nt < 4) ? A1.x : (nt < 8) ? A1.y : (nt < 12) ? A1.z : A1.w;
            int bitb = ((nt & 3) << 3) + 2 * t;
            float p00 = expleaky(c[0], (wA >> bitb) & 1);
            float p01 = expleaky(c[1], (wA >> (bitb + 1)) & 1);
            float p10 = expleaky(c[2], (wB >> bitb) & 1);
            float p11 = expleaky(c[3], (wB >> (bitb + 1)) & 1);
            rs0 += p00 + p01; rs1 += p10 + p11;
            float2 v2 = *(const float2*)&v1s[8 * nt + 2 * t];
            ax0 += p00 * v2.x + p01 * v2.y;
            ax1 += p10 * v2.x + p11 * v2.y;
            int kc = nt >> 1;
            if ((nt & 1) == 0) {
                af[kc][0] = cvt_bf16x2(p01, p00);
                af[kc][1] = cvt_bf16x2(p11, p10);
            } else {
                af[kc][2] = cvt_bf16x2(p01, p00);
                af[kc][3] = cvt_bf16x2(p11, p10);
            }
        }
        #pragma unroll
        for (int kc = 0; kc < 8; kc++) {
            #pragma unroll
            for (int nt2 = 0; nt2 < 16; nt2++) {
                uint32_t b0 = VTs[(8 * nt2 + g) * 68 + 8 * kc + t];
                uint32_t b1 = VTs[(8 * nt2 + g) * 68 + 8 * kc + t + 4];
                mma_bf16(O[nt2], af[kc][0], af[kc][1], af[kc][2], af[kc][3], b0, b1);
            }
        }
    }

    rs0 += __shfl_xor_sync(0xFFFFFFFFu, rs0, 1); rs0 += __shfl_xor_sync(0xFFFFFFFFu, rs0, 2);
    rs1 += __shfl_xor_sync(0xFFFFFFFFu, rs1, 1); rs1 += __shfl_xor_sync(0xFFFFFFFFu, rs1, 2);
    ax0 += __shfl_xor_sync(0xFFFFFFFFu, ax0, 1); ax0 += __shfl_xor_sync(0xFFFFFFFFu, ax0, 2);
    ax1 += __shfl_xor_sync(0xFFFFFFFFu, ax1, 1); ax1 += __shfl_xor_sync(0xFFFFFFFFu, ax1, 2);
    float inv0 = 1.f / rs0, inv1 = 1.f / rs1;

    float* d0 = g_hp + ((size_t)(brow + 16 * w + g) * 4 + hh) * 132;
    float* d1 = d0 + 8 * 4 * 132;
    #pragma unroll
    for (int nt2 = 0; nt2 < 16; nt2++) {
        *(float2*)&d0[8 * nt2 + 2 * t] = make_float2(O[nt2][0] * inv0, O[nt2][1] * inv0);
        *(float2*)&d1[8 * nt2 + 2 * t] = make_float2(O[nt2][2] * inv1, O[nt2][3] * inv1);
    }
    if (t == 0) { d0[128] = ax0 * inv0; d1[128] = ax1 * inv1; }
}

// ---------------- K4: attention MLP + skip via tf32 mma, 2 CTA/SM ----------------
// Hidden buffer aliases As; n-tiles split 9/8 so Ws is [136][140].
#define MLP_A_OFF 0                         // u32[64*140]  = 35840 (aliased as Hs after GEMM1)
#define MLP_W_OFF 35840                     // u32[136*140] = 76160
#define MLP_B_OFF (35840 + 76160)           // f32[272]
#define SMEM_MLP (MLP_B_OFF + 272 * 4)

__global__ void __launch_bounds__(256, 2) k_mlp(const float* __restrict__ W1, const float* __restrict__ b1,
                                                const float* __restrict__ W2, const float* __restrict__ b2) {
    extern __shared__ char smc[];
    uint32_t* As = (uint32_t*)(smc + MLP_A_OFF);
    uint32_t* Ws = (uint32_t*)(smc + MLP_W_OFF);
    float* bias_s = (float*)(smc + MLP_B_OFF);
    int blk = blockIdx.x, tid = threadIdx.x;
    int w = tid >> 5, lane = tid & 31, g = lane >> 2, t = lane & 3;
    int wm = w & 3, wn = w >> 2;
    int m0 = wm * 16;
    int NT = wn ? 8 : 9;          // wn0: nt 0..8, wn1: nt 9..16
    int ntb = wn * 9;

    for (int e = tid; e < 272; e += 256) {
        float bval = 0.f;
        if (e < 129) bval = b1[e];
        else if (e >= 136 && e < 265) bval = b2[e - 136];
        bias_s[e] = bval;
    }

    float acc[9][4];
    #pragma unroll
    for (int i = 0; i < 9; i++) { acc[i][0] = acc[i][1] = acc[i][2] = acc[i][3] = 0.f; }

    for (int kc = 0; kc < 4; kc++) {
        __syncthreads();
        for (int e = tid; e < 64 * 140; e += 256) {
            int r = e / 140, u = e - r * 140;
            As[e] = (u < 129) ? to_tf32(g_hp[((size_t)(blk * 64 + r) * 4 + kc) * 132 + u]) : 0;
        }
        for (int e = tid; e < 136 * 140; e += 256) {
            int n = e / 140, u = e - n * 140;
            Ws[e] = (u < 129 && n < 129)
                ? to_tf32(W1[((size_t)kc * 129 + u) * 129 + n]) : 0;
        }
        __syncthreads();
        #pragma unroll
        for (int ks = 0; ks < 17; ks++) {
            uint32_t a0 = As[(m0 + g) * 140 + 8 * ks + t];
            uint32_t a1 = As[(m0 + g + 8) * 140 + 8 * ks + t];
            uint32_t a2 = As[(m0 + g) * 140 + 8 * ks + t + 4];
            uint32_t a3 = As[(m0 + g + 8) * 140 + 8 * ks + t + 4];
            #pragma unroll
            for (int i = 0; i < 9; i++) {
                if (i >= NT) break;
                int nt = ntb + i;
                uint32_t b0 = Ws[(8 * nt + g) * 140 + 8 * ks + t];
                uint32_t b1r = Ws[(8 * nt + g) * 140 + 8 * ks + t + 4];
                mma_tf32(acc[i], a0, a1, a2, a3, b0, b1r);
            }
        }
    }
    __syncthreads();   // all GEMM1 reads of As done; reuse As as hidden
    uint32_t* Hs = As;
    // zero pad region of Hs first (cols 129..139 must be 0 for GEMM2 reads)
    for (int e = tid; e < 64 * 140; e += 256) {
        int u = e - (e / 140) * 140;
        if (u >= 129) Hs[e] = 0;
    }
    #pragma unroll
    for (int i = 0; i < 9; i++) {
        if (i >= NT) break;
        int nt = ntb + i;
        int col = 8 * nt + 2 * t;
        if (col <= 128) {
            Hs[(m0 + g) * 140 + col]     = to_tf32(fmaxf(acc[i][0] + bias_s[col], 0.f));
            Hs[(m0 + g + 8) * 140 + col] = to_tf32(fmaxf(acc[i][2] + bias_s[col], 0.f));
        }
        if (col + 1 <= 128) {
            Hs[(m0 + g) * 140 + col + 1]     = to_tf32(fmaxf(acc[i][1] + bias_s[col + 1], 0.f));
            Hs[(m0 + g + 8) * 140 + col + 1] = to_tf32(fmaxf(acc[i][3] + bias_s[col + 1], 0.f));
        }
        acc[i][0] = acc[i][1] = acc[i][2] = acc[i][3] = 0.f;
    }
    __syncthreads();
    for (int e = tid; e < 136 * 140; e += 256) {
        int n = e / 140, u = e - n * 140;
        Ws[e] = (u < 129 && n < 129) ? to_tf32(W2[(size_t)u * 129 + n]) : 0;
    }
    __syncthreads();
    #pragma unroll
    for (int ks = 0; ks < 17; ks++) {
        uint32_t a0 = Hs[(m0 + g) * 140 + 8 * ks + t];
        uint32_t a1 = Hs[(m0 + g + 8) * 140 + 8 * ks + t];
        uint32_t a2 = Hs[(m0 + g) * 140 + 8 * ks + t + 4];
        uint32_t a3 = Hs[(m0 + g + 8) * 140 + 8 * ks + t + 4];
        #pragma unroll
        for (int i = 0; i < 9; i++) {
            if (i >= NT) break;
            int nt = ntb + i;
            uint32_t b0 = Ws[(8 * nt + g) * 140 + 8 * ks + t];
            uint32_t b1r = Ws[(8 * nt + g) * 140 + 8 * ks + t + 4];
            mma_tf32(acc[i], a0, a1, a2, a3, b0, b1r);
        }
    }
    #pragma unroll
    for (int i = 0; i < 9; i++) {
        if (i >= NT) break;
        int nt = ntb + i;
        int col = 8 * nt + 2 * t;
        if (col <= 128) {
            int idx = (blk * 64 + m0 + g) * Cc + col;
            g_combined[idx]          += acc[i][0] + bias_s[136 + col];
            g_combined[idx + 8 * Cc] += acc[i][2] + bias_s[136 + col];
        }
        if (col + 1 <= 128) {
            int idx = (blk * 64 + m0 + g) * Cc + col + 1;
            g_combined[idx]          += acc[i][1] + bias_s[137 + col];
            g_combined[idx + 8 * Cc] += acc[i][3] + bias_s[137 + col];
        }
    }
}

// ---------------- K5: r,u gates via tf32 mma; 32-row blocks, 2 CTA/SM ----------------
// grid (128 mblk, 2 n-half), 256 threads = 8 warps: mt(2) x mat(2) x nsub(2)
__global__ void __launch_bounds__(256, 2) k_gate_ru(const float* __restrict__ qv,
                                                    const int* __restrict__ nodes_b, const int* __restrict__ nodes_n,
                                                    const float* __restrict__ Wr, const float* __restrict__ br,
                                                    const float* __restrict__ Wu, const float* __restrict__ bu,
                                                    const float* __restrict__ x, const float* __restrict__ hin) {
    extern __shared__ float sm[];
    float*    sel_s = sm;                              // [32][132]
    float*    qv_s  = sel_s + 32 * 132;                // [32][33]
    uint32_t* Zs    = (uint32_t*)(qv_s + 32 * 33);     // [32][132] tf32
    uint32_t* Ws    = Zs + 32 * 132;                   // [2][129][36] tf32
    float*    bs    = (float*)(Ws + 2 * 129 * 36);     // [2][32][34]
    int blk = blockIdx.x, nh = blockIdx.y, tid = threadIdx.x;
    int ob = nh * 32;
    int w = tid >> 5, lane = tid & 31;
    int g = lane >> 2, t = lane & 3;
    int mt = w & 1, mat = (w >> 1) & 1, nsub = w >> 2;
    int m0 = mt * 16, n0l = nsub * 16;

    for (int e = tid; e < 32 * 132; e += 256) {
        int lm = e / 132, i = e - lm * 132;
        int gm = blk * 32 + lm;
        int node = nodes_b[gm] * Nn + nodes_n[gm];
        sel_s[e] = (i < Cc) ? g_combined[node * Cc + i] : 0.f;
    }
    for (int e = tid; e < 32 * 32; e += 256) {
        int lm = e >> 5, d = e & 31;
        qv_s[lm * 33 + d] = qv[(blk * 32 + lm) * 32 + d];
    }
    for (int e = tid; e < 2048; e += 256) {
        int m2 = e >> 10, r2 = e & 1023;
        int d2 = r2 >> 5, o = r2 & 31;
        bs[m2 * 1088 + d2 * 34 + o] = (m2 ? bu : br)[d2 * 64 + ob + o];
    }
    __syncthreads();

    float wreg[33];
    auto ldW = [&](int d) {
        #pragma unroll
        for (int it = 0; it < 33; it++) {
            int e = tid + 256 * it;
            if (e < 8256) {
                int m2 = (e >= 4128);
                int e2 = e - m2 * 4128;
                int k = e2 >> 5, o = e2 & 31;
                wreg[it] = (m2 ? Wu : Wr)[((size_t)d * Cc + k) * 64 + ob + o];
            }
        }
    };
    auto stW = [&]() {
        #pragma unroll
        for (int it = 0; it < 33; it++) {
            int e = tid + 256 * it;
            if (e < 8256) {
                int m2 = (e >= 4128);
                int e2 = e - m2 * 4128;
                int k = e2 >> 5, o = e2 & 31;
                Ws[m2 * 4644 + k * 36 + o] = to_tf32(wreg[it]);
            }
        }
    };
    auto bldZ = [&](int d) {
        for (int e = tid; e < 32 * 132; e += 256) {
            int lm = e / 132;
            Zs[e] = to_tf32(qv_s[lm * 33 + d] * sel_s[e]);
        }
    };

    ldW(0);
    stW();
    bldZ(0);
    __syncthreads();

    float acc[2][4] = {};
    const uint32_t* Wm = Ws + mat * 4644;

    for (int d = 0; d < 32; d++) {
        if (d < 31) ldW(d + 1);
        #pragma unroll 4
        for (int ks = 0; ks < 16; ks++) {
            int k0 = ks * 8;
            uint32_t a0 = Zs[(m0 + g) * 132 + k0 + t];
            uint32_t a1 = Zs[(m0 + g + 8) * 132 + k0 + t];
            uint32_t a2 = Zs[(m0 + g) * 132 + k0 + t + 4];
            uint32_t a3 = Zs[(m0 + g + 8) * 132 + k0 + t + 4];
            #pragma unroll
            for (int cn = 0; cn < 2; cn++) {
                uint32_t b0 = Wm[(k0 + t) * 36 + n0l + cn * 8 + g];
                uint32_t b1 = Wm[(k0 + t + 4) * 36 + n0l + cn * 8 + g];
                mma_tf32(acc[cn], a0, a1, a2, a3, b0, b1);
            }
        }
        float z0 = __uint_as_float(Zs[(m0 + g) * 132 + 128]);
        float z1 = __uint_as_float(Zs[(m0 + g + 8) * 132 + 128]);
        #pragma unroll
        for (int cn = 0; cn < 2; cn++) {
            float w0 = __uint_as_float(Wm[128 * 36 + n0l + cn * 8 + 2 * t]);
            float w1 = __uint_as_float(Wm[128 * 36 + n0l + cn * 8 + 2 * t + 1]);
            acc[cn][0] += z0 * w0; acc[cn][1] += z0 * w1;
            acc[cn][2] += z1 * w0; acc[cn][3] += z1 * w1;
        }
        __syncthreads();
        if (d < 31) {
            stW();
            bldZ(d + 1);
            __syncthreads();
        }
    }

    const float* bm = bs + mat * 1088;
    #pragma unroll 4
    for (int d = 0; d < 32; d++) {
        float q0 = qv_s[(m0 + g) * 33 + d];
        float q1 = qv_s[(m0 + g + 8) * 33 + d];
        #pragma unroll
        for (int cn = 0; cn < 2; cn++) {
            float w0 = bm[d * 34 + n0l + cn * 8 + 2 * t];
            float w1 = bm[d * 34 + n0l + cn * 8 + 2 * t + 1];
            acc[cn][0] += q0 * w0; acc[cn][1] += q0 * w1;
            acc[cn][2] += q1 * w0; acc[cn][3] += q1 * w1;
        }
    }

    __syncthreads();
    float* stg = (float*)Zs;
    int cb = mat * 40;
    #pragma unroll
    for (int cn = 0; cn < 2; cn++) {
        int col = cb + n0l + cn * 8 + 2 * t;
        stg[(m0 + g) * 132 + col]     = acc[cn][0];
        stg[(m0 + g) * 132 + col + 1] = acc[cn][1];
        stg[(m0 + g + 8) * 132 + col]     = acc[cn][2];
        stg[(m0 + g + 8) * 132 + col + 1] = acc[cn][3];
    }
    __syncthreads();

    for (int e = tid; e < 32 * 32; e += 256) {
        int lm = e >> 5, o = e & 31;
        int gm = blk * 32 + lm;
        int node = nodes_b[gm] * Nn + nodes_n[gm];
        float ar = stg[lm * 132 + o];
        float au = stg[lm * 132 + 40 + o];
        float hv = hin[node * 64 + ob + o];
        float r = 1.f / (1.f + __expf(-ar));
        float u = 1.f / (1.f + __expf(-au));
        float hn = r * hv;
        g_hn[gm * 64 + ob + o] = hn;
        g_u[gm * 64 + ob + o] = u;
        g_sel2[gm * Cc + 65 + ob + o] = hn;
    }
    if (nh == 0) {
        for (int e = tid; e < 32 * 65; e += 256) {
            int lm = e / 65, i = e - lm * 65;
            int gm = blk * 32 + lm;
            int node = nodes_b[gm] * Nn + nodes_n[gm];
            g_sel2[gm * Cc + i] = x[node * 65 + i];
        }
    }
}

// ---------------- K6: cand gate via tf32 mma; 32-row blocks, 3 CTA/SM ----------------
// grid (128, 2), 128 threads = 4 warps: mt(2) x nsub(2)
__global__ void __launch_bounds__(128, 3) k_gate_c(const float* __restrict__ qv,
                                                   const float* __restrict__ Wc, const float* __restrict__ bc,
                                                   float* __restrict__ out) {
    extern __shared__ float sm[];
    float*    sel_s = sm;                              // [32][132]
    float*    qv_s  = sel_s + 32 * 132;                // [32][33]
    uint32_t* Zs    = (uint32_t*)(qv_s + 32 * 33);     // [32][132]
    uint32_t* Ws    = Zs + 32 * 132;                   // [129][36]
    float*    bs    = (float*)(Ws + 129 * 36);         // [32][34]
    int blk = blockIdx.x, nh = blockIdx.y, tid = threadIdx.x;
    int ob = nh * 32;
    int w = tid >> 5, lane = tid & 31;
    int g = lane >> 2, t = lane & 3;
    int mt = w & 1, nsub = w >> 1;
    int m0 = mt * 16, n0l = nsub * 16;

    for (int e = tid; e < 32 * 132; e += 128) {
        int lm = e / 132, i = e - lm * 132;
        sel_s[e] = (i < Cc) ? g_sel2[(blk * 32 + lm) * Cc + i] : 0.f;
    }
    for (int e = tid; e < 32 * 32; e += 128) {
        int lm = e >> 5, d = e & 31;
        qv_s[lm * 33 + d] = qv[(blk * 32 + lm) * 32 + d];
    }
    for (int e = tid; e < 1024; e += 128) {
        int d2 = e >> 5, o = e & 31;
        bs[d2 * 34 + o] = bc[d2 * 64 + ob + o];
    }
    __syncthreads();

    float wreg[33];
    auto ldW = [&](int d) {
        #pragma unroll
        for (int it = 0; it < 33; it++) {
            int e = tid + 128 * it;
            if (e < 4128) {
                int k = e >> 5, o = e & 31;
                wreg[it] = Wc[((size_t)d * Cc + k) * 64 + ob + o];
            }
        }
    };
    auto stW = [&]() {
        #pragma unroll
        for (int it = 0; it < 33; it++) {
            int e = tid + 128 * it;
            if (e < 4128) {
                int k = e >> 5, o = e & 31;
                Ws[k * 36 + o] = to_tf32(wreg[it]);
            }
        }
    };
    auto bldZ = [&](int d) {
        for (int e = tid; e < 32 * 132; e += 128) {
            int lm = e / 132;
            Zs[e] = to_tf32(qv_s[lm * 33 + d] * sel_s[e]);
        }
    };

    ldW(0);
    stW();
    bldZ(0);
    __syncthreads();

    float acc[2][4] = {};

    for (int d = 0; d < 32; d++) {
        if (d < 31) ldW(d + 1);
        #pragma unroll 4
        for (int ks = 0; ks < 16; ks++) {
            int k0 = ks * 8;
            uint32_t a0 = Zs[(m0 + g) * 132 + k0 + t];
            uint32_t a1 = Zs[(m0 + g + 8) * 132 + k0 + t];
            uint32_t a2 = Zs[(m0 + g) * 132 + k0 + t + 4];
            uint32_t a3 = Zs[(m0 + g + 8) * 132 + k0 + t + 4];
            #pragma unroll
            for (int cn = 0; cn < 2; cn++) {
                uint32_t b0 = Ws[(k0 + t) * 36 + n0l + cn * 8 + g];
                uint32_t b1 = Ws[(k0 + t + 4) * 36 + n0l + cn * 8 + g];
                mma_tf32(acc[cn], a0, a1, a2, a3, b0, b1);
            }
        }
        float z0 = __uint_as_float(Zs[(m0 + g) * 132 + 128]);
        float z1 = __uint_as_float(Zs[(m0 + g + 8) * 132 + 128]);
        #pragma unroll
        for (int cn = 0; cn < 2; cn++) {
            float w0 = __uint_as_float(Ws[128 * 36 + n0l + cn * 8 + 2 * t]);
            float w1 = __uint_as_float(Ws[128 * 36 + n0l + cn * 8 + 2 * t + 1]);
            acc[cn][0] += z0 * w0; acc[cn][1] += z0 * w1;
            acc[cn][2] += z1 * w0; acc[cn][3] += z1 * w1;
        }
        __syncthreads();
        if (d < 31) {
            stW();
            bldZ(d + 1);
            __syncthreads();
        }
    }

    #pragma unroll 4
    for (int d = 0; d < 32; d++) {
        float q0 = qv_s[(m0 + g) * 33 + d];
        float q1 = qv_s[(m0 + g + 8) * 33 + d];
        #pragma unroll
        for (int cn = 0; cn < 2; cn++) {
            float w0 = bs[d * 34 + n0l + cn * 8 + 2 * t];
            float w1 = bs[d * 34 + n0l + cn * 8 + 2 * t + 1];
            acc[cn][0] += q0 * w0; acc[cn][1] += q0 * w1;
            acc[cn][2] += q1 * w0; acc[cn][3] += q1 * w1;
        }
    }

    int gm0 = blk * 32 + m0 + g;
    int gm1 = gm0 + 8;
    #pragma unroll
    for (int cn = 0; cn < 2; cn++) {
        int col = ob + n0l + cn * 8 + 2 * t;
        #pragma unroll
        for (int jj = 0; jj < 2; jj++) {
            int gm = jj ? gm1 : gm0;
            float c0 = acc[cn][2 * jj], c1 = acc[cn][2 * jj + 1];
            float u0 = g_u[gm * 64 + col],     hn0 = g_hn[gm * 64 + col];
            float u1 = g_u[gm * 64 + col + 1], hn1 = g_hn[gm * 64 + col + 1];
            out[gm * 64 + col]     = (1.f - u0) * hn0 + u0 * tanhf(c0);
            out[gm * 64 + col + 1] = (1.f - u1) * hn1 + u1 * tanhf(c1);
        }
    }
}

// ---------------- launch ----------------
extern "C" void kernel_launch(void* const* d_in, const int* in_sizes, int n_in,
                              void* d_out, int out_size) {
    const float* x   = (const float*)d_in[0];
    const float* h   = (const float*)d_in[1];
    const float* qv  = (const float*)d_in[2];
    const int*   adj = (const int*)  d_in[3];
    const int*   nb  = (const int*)  d_in[4];
    const int*   nn  = (const int*)  d_in[5];
    const float* Wq  = (const float*)d_in[6];
    const float* bq  = (const float*)d_in[7];
    const float* Wk  = (const float*)d_in[8];
    const float* bk  = (const float*)d_in[9];
    const float* Wv  = (const float*)d_in[10];
    const float* bv  = (const float*)d_in[11];
    const float* W1  = (const float*)d_in[12];
    const float* b1  = (const float*)d_in[13];
    const float* W2  = (const float*)d_in[14];
    const float* b2  = (const float*)d_in[15];
    const float* Wr  = (const float*)d_in[16];
    const float* br  = (const float*)d_in[17];
    const float* Wu  = (const float*)d_in[18];
    const float* bu  = (const float*)d_in[19];
    const float* Wc  = (const float*)d_in[20];
    const float* bc  = (const float*)d_in[21];
    float* out = (float*)d_out;

    const int SZ_RU = (32 * 132 + 32 * 33 + 32 * 132 + 2 * 129 * 36 + 2 * 32 * 34 + 16) * 4;
    const int SZ_C  = (32 * 132 + 32 * 33 + 32 * 132 + 129 * 36 + 32 * 34 + 16) * 4;

    cudaFuncSetAttribute(k_qkv,      cudaFuncAttributeMaxDynamicSharedMemorySize, SMEM_QKV);
    cudaFuncSetAttribute(k_attn_mma, cudaFuncAttributeMaxDynamicSharedMemorySize, SMEM_ATT);
    cudaFuncSetAttribute(k_mlp,      cudaFuncAttributeMaxDynamicSharedMemorySize, SMEM_MLP);
    cudaFuncSetAttribute(k_gate_ru,  cudaFuncAttributeMaxDynamicSharedMemorySize, SZ_RU);
    cudaFuncSetAttribute(k_gate_c,   cudaFuncAttributeMaxDynamicSharedMemorySize, SZ_C);

    k_combined<<<(ROWS * Cc + 255) / 256, 256>>>(x, h);
    k_adjpack<<<(Nn * Nn) / 256, 256>>>(adj);
    k_qkv<<<dim3(128, 4), 256, SMEM_QKV>>>(Wv, bv, Wq, bq, Wk, bk);
    k_attn_mma<<<dim3(16, 8, 4), 128, SMEM_ATT>>>();
    k_mlp<<<128, 256, SMEM_MLP>>>(W1, b1, W2, b2);
    k_gate_ru<<<dim3(128, 2), 256, SZ_RU>>>(qv, nb, nn, Wr, br, Wu, bu, x, h);
    k_gate_c<<<dim3(128, 2), 128, SZ_C>>>(qv, Wc, bc, out);
}

// round 12
// speedup vs baseline: 4.2275x; 1.0113x over previous
#include <cuda_runtime.h>
#include <cuda_bf16.h>
#include <cstdint>
#include <math.h>

#define Bb   8
#define Nn   1024
#define Dd   64
#define Hh   4
#define Cc   129
#define Kk   16
#define Mm   4096
#define ROWS 8192   // B*N

// ---------------- helpers ----------------
__device__ __forceinline__ uint32_t cvt_bf16x2(float hi, float lo) {
    uint32_t r;
    asm("cvt.rn.bf16x2.f32 %0, %1, %2;" : "=r"(r) : "f"(hi), "f"(lo));
    return r;
}
__device__ __forceinline__ uint32_t to_tf32(float f) {
    uint32_t r;
    asm("cvt.rna.tf32.f32 %0, %1;" : "=r"(r) : "f"(f));
    return r;
}
__device__ __forceinline__ void mma_bf16(float c[4], uint32_t a0, uint32_t a1, uint32_t a2, uint32_t a3,
                                         uint32_t b0, uint32_t b1) {
    asm volatile("mma.sync.aligned.m16n8k16.row.col.f32.bf16.bf16.f32 "
                 "{%0,%1,%2,%3}, {%4,%5,%6,%7}, {%8,%9}, {%0,%1,%2,%3};"
                 : "+f"(c[0]), "+f"(c[1]), "+f"(c[2]), "+f"(c[3])
                 : "r"(a0), "r"(a1), "r"(a2), "r"(a3), "r"(b0), "r"(b1));
}
__device__ __forceinline__ void mma_tf32(float c[4], uint32_t a0, uint32_t a1, uint32_t a2, uint32_t a3,
                                         uint32_t b0, uint32_t b1) {
    asm volatile("mma.sync.aligned.m16n8k8.row.col.f32.tf32.tf32.f32 "
                 "{%0,%1,%2,%3}, {%4,%5,%6,%7}, {%8,%9}, {%0,%1,%2,%3};"
                 : "+f"(c[0]), "+f"(c[1]), "+f"(c[2]), "+f"(c[3])
                 : "r"(a0), "r"(a1), "r"(a2), "r"(a3), "r"(b0), "r"(b1));
}
__device__ __forceinline__ float expleaky(float s, uint32_t bit) {
    s *= 0.25f;
    s = s > 0.f ? s : 0.2f * s;
    return bit ? __expf(s) : 0.f;
}

// ================= scratch =================
__device__ float g_combined[ROWS * Cc];
__device__ __nv_bfloat16 g_qb[Hh * ROWS * Kk];
__device__ __nv_bfloat16 g_kb[Hh * ROWS * Kk];
__device__ __nv_bfloat16 g_vtb[Hh * Bb * 128 * 1024];   // [h*8+b][c<128][m]
__device__ float g_v128[Hh * Bb * 1024];                // v col 128
__device__ uint32_t g_adjbits[Nn * 32];
__device__ float g_hp[ROWS * 4 * 132];                  // [row][h][132 padded], normalized
__device__ float g_hn[Mm * Dd];
__device__ float g_u[Mm * Dd];
__device__ float g_sel2[Mm * Cc];

// ---------------- K0b: pack adjacency bits ----------------
__global__ void k_adjpack(const int* __restrict__ adj) {
    int idx = blockIdx.x * 256 + threadIdx.x;
    uint32_t bits = __ballot_sync(0xFFFFFFFFu, adj[idx] != 0);
    if ((idx & 31) == 0) g_adjbits[idx >> 5] = bits;
}

// ---------------- K1: fused concat + q/k/v projections via bf16 mma ----------------
#define QKV_AB_OFF 0
#define QKV_WT_OFF 19456
#define QKV_BS_OFF (19456 + 53504)
#define SMEM_QKV (QKV_BS_OFF + 176 * 4)

__global__ void __launch_bounds__(256, 2) k_qkv(const float* __restrict__ x, const float* __restrict__ h,
                                                const float* __restrict__ Wv, const float* __restrict__ bv,
                                                const float* __restrict__ Wq, const float* __restrict__ bq,
                                                const float* __restrict__ Wk, const float* __restrict__ bk) {
    extern __shared__ char smc[];
    uint32_t* Ab = (uint32_t*)(smc + QKV_AB_OFF);
    uint32_t* Wt = (uint32_t*)(smc + QKV_WT_OFF);
    float* bias_s = (float*)(smc + QKV_BS_OFF);
    int tile = blockIdx.x, hh = blockIdx.y, tid = threadIdx.x;
    int w = tid >> 5, lane = tid & 31, g = lane >> 2, t = lane & 3;
    int wm = w & 3, wn = w >> 2;
    int m0 = wm * 16;

    // A tile built directly from x|h (concat fused); hh==0 also materializes g_combined
    for (int e = tid; e < 64 * 76; e += 256) {
        int r = e / 76, u = e - r * 76;
        int row = tile * 64 + r;
        uint32_t val = 0;
        if (u < 65) {
            int c0 = 2 * u, c1 = 2 * u + 1;
            float f0 = (c0 < 65) ? x[row * 65 + c0] : h[row * 64 + (c0 - 65)];
            float f1 = 0.f;
            if (c1 < 129) f1 = (c1 < 65) ? x[row * 65 + c1] : h[row * 64 + (c1 - 65)];
            val = cvt_bf16x2(f1, f0);
            if (hh == 0) {
                g_combined[row * Cc + c0] = f0;
                if (c1 < 129) g_combined[row * Cc + c1] = f1;
            }
        }
        Ab[e] = val;
    }
    const float* wvh = Wv + (size_t)hh * 129 * 129;
    const float* wqh = Wq + (size_t)hh * 129 * 16;
    const float* wkh = Wk + (size_t)hh * 129 * 16;
    for (int e = tid; e < 76 * 176; e += 256) {
        int u = e / 176, n = e - u * 176;
        float w0 = 0.f, w1 = 0.f;
        if (u < 65) {
            int k0 = 2 * u, k1 = 2 * u + 1;
            if (n < 129) {
                w0 = wvh[k0 * 129 + n];
                if (k1 < 129) w1 = wvh[k1 * 129 + n];
            } else if (n >= 136 && n < 152) {
                int kk = n - 136;
                w0 = wqh[k0 * 16 + kk];
                if (k1 < 129) w1 = wqh[k1 * 16 + kk];
            } else if (n >= 152 && n < 168) {
                int kk = n - 152;
                w0 = wkh[k0 * 16 + kk];
                if (k1 < 129) w1 = wkh[k1 * 16 + kk];
            }
        }
        Wt[n * 76 + u] = cvt_bf16x2(w1, w0);
    }
    for (int e = tid; e < 176; e += 256) {
        float bval = 0.f;
        if (e < 129) bval = bv[hh * 129 + e];
        else if (e >= 136 && e < 152) bval = bq[hh * 16 + e - 136];
        else if (e >= 152 && e < 168) bval = bk[hh * 16 + e - 152];
        bias_s[e] = bval;
    }
    __syncthreads();

    float acc[11][4];
    #pragma unroll
    for (int i = 0; i < 11; i++) { acc[i][0] = acc[i][1] = acc[i][2] = acc[i][3] = 0.f; }
    int ntb = wn * 11;

    #pragma unroll
    for (int ks = 0; ks < 9; ks++) {
        uint32_t a0 = Ab[(m0 + g) * 76 + 8 * ks + t];
        uint32_t a1 = Ab[(m0 + g + 8) * 76 + 8 * ks + t];
        uint32_t a2 = Ab[(m0 + g) * 76 + 8 * ks + t + 4];
        uint32_t a3 = Ab[(m0 + g + 8) * 76 + 8 * ks + t + 4];
        #pragma unroll
        for (int i = 0; i < 11; i++) {
            int nt = ntb + i;
            uint32_t b0 = Wt[(8 * nt + g) * 76 + 8 * ks + t];
            uint32_t b1 = Wt[(8 * nt + g) * 76 + 8 * ks + t + 4];
            mma_bf16(acc[i], a0, a1, a2, a3, b0, b1);
        }
    }

    size_t rowbase = (size_t)hh * ROWS + tile * 64 + m0;
    if (wn == 1) {
        #pragma unroll
        for (int i = 6; i < 10; i++) {
            int nt = 11 + i;
            bool isq = nt < 19;
            int col = (nt - (isq ? 17 : 19)) * 8 + 2 * t;
            float b0v = bias_s[(isq ? 136 : 152) + col];
            float b1v = bias_s[(isq ? 136 : 152) + col + 1];
            __nv_bfloat16* dst = isq ? g_qb : g_kb;
            *(uint32_t*)&dst[(rowbase + g) * 16 + col] =
                cvt_bf16x2(acc[i][1] + b1v, acc[i][0] + b0v);
            *(uint32_t*)&dst[(rowbase + g + 8) * 16 + col] =
                cvt_bf16x2(acc[i][3] + b1v, acc[i][2] + b0v);
        }
    }
    __syncthreads();
    float* vtile = (float*)smc;
    #pragma unroll
    for (int i = 0; i < 11; i++) {
        int nt = ntb + i;
        if (nt > 16) break;
        int col = 8 * nt + 2 * t;
        if (col <= 128) {
            float bb = bias_s[col];
            vtile[(m0 + g) * 132 + col]     = acc[i][0] + bb;
            vtile[(m0 + g + 8) * 132 + col] = acc[i][2] + bb;
        }
        if (col + 1 <= 128) {
            float bb = bias_s[col + 1];
            vtile[(m0 + g) * 132 + col + 1]     = acc[i][1] + bb;
            vtile[(m0 + g + 8) * 132 + col + 1] = acc[i][3] + bb;
        }
    }
    __syncthreads();

    int b_idx = tile >> 4;
    int mbase = (tile & 15) * 64;
    size_t hb = hh * 8 + b_idx;
    for (int e = tid; e < 128 * 32; e += 256) {
        int c = e >> 5, mp = e & 31;
        float f0 = vtile[(mp * 2) * 132 + c];
        float f1 = vtile[(mp * 2 + 1) * 132 + c];
        *(__nv_bfloat162*)&g_vtb[(hb * 128 + c) * 1024 + mbase + mp * 2] =
            __float22bfloat162_rn(make_float2(f0, f1));
    }
    if (tid < 64)
        g_v128[hb * 1024 + mbase + tid] = vtile[tid * 132 + 128];
}

// ---------------- K3: HMMA flash attention, 64-row CTAs, 2 CTA/SM ----------------
#define AKS_OFF 0
#define AVT_OFF 6144
#define AV1_OFF (6144 + 34816)
#define SMEM_ATT (AV1_OFF + 512)

__global__ void __launch_bounds__(128, 2) k_attn_mma() {
    extern __shared__ char smc[];
    uint32_t* Ks  = (uint32_t*)(smc + AKS_OFF);
    uint32_t* VTs = (uint32_t*)(smc + AVT_OFF);
    float*    v1s = (float*)(smc + AV1_OFF);
    int tid = threadIdx.x, w = tid >> 5, lane = tid & 31;
    int g = lane >> 2, t = lane & 3;
    int rblk = blockIdx.x, b = blockIdx.y, hh = blockIdx.z;
    size_t hb = hh * 8 + b;
    int brow = b * 1024 + rblk * 64;

    const __nv_bfloat16* qsrc = g_qb + ((size_t)hh * ROWS + brow + 16 * w) * 16;
    uint32_t qa0 = *(const uint32_t*)(qsrc + g * 16 + 2 * t);
    uint32_t qa1 = *(const uint32_t*)(qsrc + (g + 8) * 16 + 2 * t);
    uint32_t qa2 = *(const uint32_t*)(qsrc + g * 16 + 2 * t + 8);
    uint32_t qa3 = *(const uint32_t*)(qsrc + (g + 8) * 16 + 2 * t + 8);

    int nrow0 = rblk * 64 + 16 * w + g;
    int nrow1 = nrow0 + 8;

    float O[16][4];
    #pragma unroll
    for (int i = 0; i < 16; i++) { O[i][0] = O[i][1] = O[i][2] = O[i][3] = 0.f; }
    float rs0 = 0.f, rs1 = 0.f, ax0 = 0.f, ax1 = 0.f;

    const uint32_t* kbase = (const uint32_t*)(g_kb + ((size_t)hh * ROWS + b * 1024) * 16);
    const __nv_bfloat16* vbase = g_vtb + hb * 131072;

    for (int j = 0; j < 8; j++) {
        __syncthreads();
        const uint32_t* ks = kbase + j * 128 * 8;
        #pragma unroll
        for (int it = 0; it < 8; it++) {
            int e = tid + 128 * it;
            int r = e >> 3, c8 = e & 7;
            Ks[r * 12 + c8] = ks[e];
        }
        #pragma unroll
        for (int it = 0; it < 16; it++) {
            int e = tid + 128 * it;
            int c = e >> 4, q = e & 15;
            ((uint4*)(smc + AVT_OFF + c * 272))[q] =
                ((const uint4*)(vbase + (size_t)c * 1024 + j * 128))[q];
        }
        v1s[tid] = g_v128[hb * 1024 + j * 128 + tid];
        uint4 A0 = ((const uint4*)g_adjbits)[nrow0 * 8 + j];
        uint4 A1 = ((const uint4*)g_adjbits)[nrow1 * 8 + j];
        __syncthreads();

        uint32_t af[8][4];
        #pragma unroll
        for (int nt = 0; nt < 16; nt++) {
            uint32_t b0 = Ks[(8 * nt + g) * 12 + t];
            uint32_t b1 = Ks[(8 * nt + g) * 12 + t + 4];
            float c[4] = {0.f, 0.f, 0.f, 0.f};
            mma_bf16(c, qa0, qa1, qa2, qa3, b0, b1);
            uint32_t wA = (nt < 4) ? A0.x : (nt < 8) ? A0.y : (nt < 12) ? A0.z : A0.w;
            uint32_t wB = (nt < 4) ? A1.x : (nt < 8) ? A1.y : (nt < 12) ? A1.z : A1.w;
            int bitb = ((nt & 3) << 3) + 2 * t;
            float p00 = expleaky(c[0], (wA >> bitb) & 1);
            float p01 = expleaky(c[1], (wA >> (bitb + 1)) & 1);
            float p10 = expleaky(c[2], (wB >> bitb) & 1);
            float p11 = expleaky(c[3], (wB >> (bitb + 1)) & 1);
            rs0 += p00 + p01; rs1 += p10 + p11;
            float2 v2 = *(const float2*)&v1s[8 * nt + 2 * t];
            ax0 += p00 * v2.x + p01 * v2.y;
            ax1 += p10 * v2.x + p11 * v2.y;
            int kc = nt >> 1;
            if ((nt & 1) == 0) {
                af[kc][0] = cvt_bf16x2(p01, p00);
                af[kc][1] = cvt_bf16x2(p11, p10);
            } else {
                af[kc][2] = cvt_bf16x2(p01, p00);
                af[kc][3] = cvt_bf16x2(p11, p10);
            }
        }
        #pragma unroll
        for (int kc = 0; kc < 8; kc++) {
            #pragma unroll
            for (int nt2 = 0; nt2 < 16; nt2++) {
                uint32_t b0 = VTs[(8 * nt2 + g) * 68 + 8 * kc + t];
                uint32_t b1 = VTs[(8 * nt2 + g) * 68 + 8 * kc + t + 4];
                mma_bf16(O[nt2], af[kc][0], af[kc][1], af[kc][2], af[kc][3], b0, b1);
            }
        }
    }

    rs0 += __shfl_xor_sync(0xFFFFFFFFu, rs0, 1); rs0 += __shfl_xor_sync(0xFFFFFFFFu, rs0, 2);
    rs1 += __shfl_xor_sync(0xFFFFFFFFu, rs1, 1); rs1 += __shfl_xor_sync(0xFFFFFFFFu, rs1, 2);
    ax0 += __shfl_xor_sync(0xFFFFFFFFu, ax0, 1); ax0 += __shfl_xor_sync(0xFFFFFFFFu, ax0, 2);
    ax1 += __shfl_xor_sync(0xFFFFFFFFu, ax1, 1); ax1 += __shfl_xor_sync(0xFFFFFFFFu, ax1, 2);
    float inv0 = 1.f / rs0, inv1 = 1.f / rs1;

    float* d0 = g_hp + ((size_t)(brow + 16 * w + g) * 4 + hh) * 132;
    float* d1 = d0 + 8 * 4 * 132;
    #pragma unroll
    for (int nt2 = 0; nt2 < 16; nt2++) {
        *(float2*)&d0[8 * nt2 + 2 * t] = make_float2(O[nt2][0] * inv0, O[nt2][1] * inv0);
        *(float2*)&d1[8 * nt2 + 2 * t] = make_float2(O[nt2][2] * inv1, O[nt2][3] * inv1);
    }
    if (t == 0) { d0[128] = ax0 * inv0; d1[128] = ax1 * inv1; }
}

// ---------------- K4: attention MLP + skip via tf32 mma; 32-row tiles, grid 256 ----------------
#define MLP_A_OFF 0                         // u32[32*140] = 17920 (aliased as Hs after GEMM1)
#define MLP_W_OFF 17920                     // u32[136*140] = 76160
#define MLP_B_OFF (17920 + 76160)           // f32[272]
#define SMEM_MLP (MLP_B_OFF + 272 * 4)

__global__ void __launch_bounds__(256, 2) k_mlp(const float* __restrict__ W1, const float* __restrict__ b1,
                                                const float* __restrict__ W2, const float* __restrict__ b2) {
    extern __shared__ char smc[];
    uint32_t* As = (uint32_t*)(smc + MLP_A_OFF);
    uint32_t* Ws = (uint32_t*)(smc + MLP_W_OFF);
    float* bias_s = (float*)(smc + MLP_B_OFF);
    int blk = blockIdx.x, tid = threadIdx.x;
    int w = tid >> 5, lane = tid & 31, g = lane >> 2, t = lane & 3;
    int wm = w & 1, wn = w >> 1;          // 2 m-tiles x 4 n-groups
    int m0 = wm * 16;
    int NT = wn ? 4 : 5;
    int ntb = wn ? (4 * wn + 1) : 0;      // 0,5,9,13

    for (int e = tid; e < 272; e += 256) {
        float bval = 0.f;
        if (e < 129) bval = b1[e];
        else if (e >= 136 && e < 265) bval = b2[e - 136];
        bias_s[e] = bval;
    }

    float acc[5][4];
    #pragma unroll
    for (int i = 0; i < 5; i++) { acc[i][0] = acc[i][1] = acc[i][2] = acc[i][3] = 0.f; }

    for (int kc = 0; kc < 4; kc++) {
        __syncthreads();
        for (int e = tid; e < 32 * 140; e += 256) {
            int r = e / 140, u = e - r * 140;
            As[e] = (u < 129) ? to_tf32(g_hp[((size_t)(blk * 32 + r) * 4 + kc) * 132 + u]) : 0;
        }
        for (int e = tid; e < 136 * 140; e += 256) {
            int n = e / 140, u = e - n * 140;
            Ws[e] = (u < 129 && n < 129)
                ? to_tf32(W1[((size_t)kc * 129 + u) * 129 + n]) : 0;
        }
        __syncthreads();
        #pragma unroll
        for (int ks = 0; ks < 17; ks++) {
            uint32_t a0 = As[(m0 + g) * 140 + 8 * ks + t];
            uint32_t a1 = As[(m0 + g + 8) * 140 + 8 * ks + t];
            uint32_t a2 = As[(m0 + g) * 140 + 8 * ks + t + 4];
            uint32_t a3 = As[(m0 + g + 8) * 140 + 8 * ks + t + 4];
            #pragma unroll
            for (int i = 0; i < 5; i++) {
                if (i >= NT) break;
                int nt = ntb + i;
                uint32_t b0 = Ws[(8 * nt + g) * 140 + 8 * ks + t];
                uint32_t b1r = Ws[(8 * nt + g) * 140 + 8 * ks + t + 4];
                mma_tf32(acc[i], a0, a1, a2, a3, b0, b1r);
            }
        }
    }
    __syncthreads();
    uint32_t* Hs = As;
    for (int e = tid; e < 32 * 140; e += 256) {
        int u = e - (e / 140) * 140;
        if (u >= 129) Hs[e] = 0;
    }
    #pragma unroll
    for (int i = 0; i < 5; i++) {
        if (i >= NT) break;
        int nt = ntb + i;
        int col = 8 * nt + 2 * t;
        if (col <= 128) {
            Hs[(m0 + g) * 140 + col]     = to_tf32(fmaxf(acc[i][0] + bias_s[col], 0.f));
            Hs[(m0 + g + 8) * 140 + col] = to_tf32(fmaxf(acc[i][2] + bias_s[col], 0.f));
        }
        if (col + 1 <= 128) {
            Hs[(m0 + g) * 140 + col + 1]     = to_tf32(fmaxf(acc[i][1] + bias_s[col + 1], 0.f));
            Hs[(m0 + g + 8) * 140 + col + 1] = to_tf32(fmaxf(acc[i][3] + bias_s[col + 1], 0.f));
        }
        acc[i][0] = acc[i][1] = acc[i][2] = acc[i][3] = 0.f;
    }
    __syncthreads();
    for (int e = tid; e < 136 * 140; e += 256) {
        int n = e / 140, u = e - n * 140;
        Ws[e] = (u < 129 && n < 129) ? to_tf32(W2[(size_t)u * 129 + n]) : 0;
    }
    __syncthreads();
    #pragma unroll
    for (int ks = 0; ks < 17; ks++) {
        uint32_t a0 = Hs[(m0 + g) * 140 + 8 * ks + t];
        uint32_t a1 = Hs[(m0 + g + 8) * 140 + 8 * ks + t];
        uint32_t a2 = Hs[(m0 + g) * 140 + 8 * ks + t + 4];
        uint32_t a3 = Hs[(m0 + g + 8) * 140 + 8 * ks + t + 4];
        #pragma unroll
        for (int i = 0; i < 5; i++) {
            if (i >= NT) break;
            int nt = ntb + i;
            uint32_t b0 = Ws[(8 * nt + g) * 140 + 8 * ks + t];
            uint32_t b1r = Ws[(8 * nt + g) * 140 + 8 * ks + t + 4];
            mma_tf32(acc[i], a0, a1, a2, a3, b0, b1r);
        }
    }
    #pragma unroll
    for (int i = 0; i < 5; i++) {
        if (i >= NT) break;
        int nt = ntb + i;
        int col = 8 * nt + 2 * t;
        if (col <= 128) {
            int idx = (blk * 32 + m0 + g) * Cc + col;
            g_combined[idx]          += acc[i][0] + bias_s[136 + col];
            g_combined[idx + 8 * Cc] += acc[i][2] + bias_s[136 + col];
        }
        if (col + 1 <= 128) {
            int idx = (blk * 32 + m0 + g) * Cc + col + 1;
            g_combined[idx]          += acc[i][1] + bias_s[137 + col];
            g_combined[idx + 8 * Cc] += acc[i][3] + bias_s[137 + col];
        }
    }
}

// ---------------- K5: r,u gates via tf32 mma; 32-row blocks, 2 CTA/SM ----------------
__global__ void __launch_bounds__(256, 2) k_gate_ru(const float* __restrict__ qv,
                                                    const int* __restrict__ nodes_b, const int* __restrict__ nodes_n,
                                                    const float* __restrict__ Wr, const float* __restrict__ br,
                                                    const float* __restrict__ Wu, const float* __restrict__ bu,
                                                    const float* __restrict__ x, const float* __restrict__ hin) {
    extern __shared__ float sm[];
    float*    sel_s = sm;                              // [32][132]
    float*    qv_s  = sel_s + 32 * 132;                // [32][33]
    uint32_t* Zs    = (uint32_t*)(qv_s + 32 * 33);     // [32][132] tf32
    uint32_t* Ws    = Zs + 32 * 132;                   // [2][129][36] tf32
    float*    bs    = (float*)(Ws + 2 * 129 * 36);     // [2][32][34]
    int blk = blockIdx.x, nh = blockIdx.y, tid = threadIdx.x;
    int ob = nh * 32;
    int w = tid >> 5, lane = tid & 31;
    int g = lane >> 2, t = lane & 3;
    int mt = w & 1, mat = (w >> 1) & 1, nsub = w >> 2;
    int m0 = mt * 16, n0l = nsub * 16;

    for (int e = tid; e < 32 * 132; e += 256) {
        int lm = e / 132, i = e - lm * 132;
        int gm = blk * 32 + lm;
        int node = nodes_b[gm] * Nn + nodes_n[gm];
        sel_s[e] = (i < Cc) ? g_combined[node * Cc + i] : 0.f;
    }
    for (int e = tid; e < 32 * 32; e += 256) {
        int lm = e >> 5, d = e & 31;
        qv_s[lm * 33 + d] = qv[(blk * 32 + lm) * 32 + d];
    }
    for (int e = tid; e < 2048; e += 256) {
        int m2 = e >> 10, r2 = e & 1023;
        int d2 = r2 >> 5, o = r2 & 31;
        bs[m2 * 1088 + d2 * 34 + o] = (m2 ? bu : br)[d2 * 64 + ob + o];
    }
    __syncthreads();

    float wreg[33];
    auto ldW = [&](int d) {
        #pragma unroll
        for (int it = 0; it < 33; it++) {
            int e = tid + 256 * it;
            if (e < 8256) {
                int m2 = (e >= 4128);
                int e2 = e - m2 * 4128;
                int k = e2 >> 5, o = e2 & 31;
                wreg[it] = (m2 ? Wu : Wr)[((size_t)d * Cc + k) * 64 + ob + o];
            }
        }
    };
    auto stW = [&]() {
        #pragma unroll
        for (int it = 0; it < 33; it++) {
            int e = tid + 256 * it;
            if (e < 8256) {
                int m2 = (e >= 4128);
                int e2 = e - m2 * 4128;
                int k = e2 >> 5, o = e2 & 31;
                Ws[m2 * 4644 + k * 36 + o] = to_tf32(wreg[it]);
            }
        }
    };
    auto bldZ = [&](int d) {
        for (int e = tid; e < 32 * 132; e += 256) {
            int lm = e / 132;
            Zs[e] = to_tf32(qv_s[lm * 33 + d] * sel_s[e]);
        }
    };

    ldW(0);
    stW();
    bldZ(0);
    __syncthreads();

    float acc[2][4] = {};
    const uint32_t* Wm = Ws + mat * 4644;

    for (int d = 0; d < 32; d++) {
        if (d < 31) ldW(d + 1);
        #pragma unroll 4
        for (int ks = 0; ks < 16; ks++) {
            int k0 = ks * 8;
            uint32_t a0 = Zs[(m0 + g) * 132 + k0 + t];
            uint32_t a1 = Zs[(m0 + g + 8) * 132 + k0 + t];
            uint32_t a2 = Zs[(m0 + g) * 132 + k0 + t + 4];
            uint32_t a3 = Zs[(m0 + g + 8) * 132 + k0 + t + 4];
            #pragma unroll
            for (int cn = 0; cn < 2; cn++) {
                uint32_t b0 = Wm[(k0 + t) * 36 + n0l + cn * 8 + g];
                uint32_t b1 = Wm[(k0 + t + 4) * 36 + n0l + cn * 8 + g];
                mma_tf32(acc[cn], a0, a1, a2, a3, b0, b1);
            }
        }
        float z0 = __uint_as_float(Zs[(m0 + g) * 132 + 128]);
        float z1 = __uint_as_float(Zs[(m0 + g + 8) * 132 + 128]);
        #pragma unroll
        for (int cn = 0; cn < 2; cn++) {
            float w0 = __uint_as_float(Wm[128 * 36 + n0l + cn * 8 + 2 * t]);
            float w1 = __uint_as_float(Wm[128 * 36 + n0l + cn * 8 + 2 * t + 1]);
            acc[cn][0] += z0 * w0; acc[cn][1] += z0 * w1;
            acc[cn][2] += z1 * w0; acc[cn][3] += z1 * w1;
        }
        __syncthreads();
        if (d < 31) {
            stW();
            bldZ(d + 1);
            __syncthreads();
        }
    }

    const float* bm = bs + mat * 1088;
    #pragma unroll 4
    for (int d = 0; d < 32; d++) {
        float q0 = qv_s[(m0 + g) * 33 + d];
        float q1 = qv_s[(m0 + g + 8) * 33 + d];
        #pragma unroll
        for (int cn = 0; cn < 2; cn++) {
            float w0 = bm[d * 34 + n0l + cn * 8 + 2 * t];
            float w1 = bm[d * 34 + n0l + cn * 8 + 2 * t + 1];
            acc[cn][0] += q0 * w0; acc[cn][1] += q0 * w1;
            acc[cn][2] += q1 * w0; acc[cn][3] += q1 * w1;
        }
    }

    __syncthreads();
    float* stg = (float*)Zs;
    int cb = mat * 40;
    #pragma unroll
    for (int cn = 0; cn < 2; cn++) {
        int col = cb + n0l + cn * 8 + 2 * t;
        stg[(m0 + g) * 132 + col]     = acc[cn][0];
        stg[(m0 + g) * 132 + col + 1] = acc[cn][1];
        stg[(m0 + g + 8) * 132 + col]     = acc[cn][2];
        stg[(m0 + g + 8) * 132 + col + 1] = acc[cn][3];
    }
    __syncthreads();

    for (int e = tid; e < 32 * 32; e += 256) {
        int lm = e >> 5, o = e & 31;
        int gm = blk * 32 + lm;
        int node = nodes_b[gm] * Nn + nodes_n[gm];
        float ar = stg[lm * 132 + o];
        float au = stg[lm * 132 + 40 + o];
        float hv = hin[node * 64 + ob + o];
        float r = 1.f / (1.f + __expf(-ar));
        float u = 1.f / (1.f + __expf(-au));
        float hn = r * hv;
        g_hn[gm * 64 + ob + o] = hn;
        g_u[gm * 64 + ob + o] = u;
        g_sel2[gm * Cc + 65 + ob + o] = hn;
    }
    if (nh == 0) {
        for (int e = tid; e < 32 * 65; e += 256) {
            int lm = e / 65, i = e - lm * 65;
            int gm = blk * 32 + lm;
            int node = nodes_b[gm] * Nn + nodes_n[gm];
            g_sel2[gm * Cc + i] = x[node * 65 + i];
        }
    }
}

// ---------------- K6: cand gate via tf32 mma; 32-row blocks, 3 CTA/SM ----------------
__global__ void __launch_bounds__(128, 3) k_gate_c(const float* __restrict__ qv,
                                                   const float* __restrict__ Wc, const float* __restrict__ bc,
                                                   float* __restrict__ out) {
    extern __shared__ float sm[];
    float*    sel_s = sm;                              // [32][132]
    float*    qv_s  = sel_s + 32 * 132;                // [32][33]
    uint32_t* Zs    = (uint32_t*)(qv_s + 32 * 33);     // [32][132]
    uint32_t* Ws    = Zs + 32 * 132;                   // [129][36]
    float*    bs    = (float*)(Ws + 129 * 36);         // [32][34]
    int blk = blockIdx.x, nh = blockIdx.y, tid = threadIdx.x;
    int ob = nh * 32;
    int w = tid >> 5, lane = tid & 31;
    int g = lane >> 2, t = lane & 3;
    int mt = w & 1, nsub = w >> 1;
    int m0 = mt * 16, n0l = nsub * 16;

    for (int e = tid; e < 32 * 132; e += 128) {
        int lm = e / 132, i = e - lm * 132;
        sel_s[e] = (i < Cc) ? g_sel2[(blk * 32 + lm) * Cc + i] : 0.f;
    }
    for (int e = tid; e < 32 * 32; e += 128) {
        int lm = e >> 5, d = e & 31;
        qv_s[lm * 33 + d] = qv[(blk * 32 + lm) * 32 + d];
    }
    for (int e = tid; e < 1024; e += 128) {
        int d2 = e >> 5, o = e & 31;
        bs[d2 * 34 + o] = bc[d2 * 64 + ob + o];
    }
    __syncthreads();

    float wreg[33];
    auto ldW = [&](int d) {
        #pragma unroll
        for (int it = 0; it < 33; it++) {
            int e = tid + 128 * it;
            if (e < 4128) {
                int k = e >> 5, o = e & 31;
                wreg[it] = Wc[((size_t)d * Cc + k) * 64 + ob + o];
            }
        }
    };
    auto stW = [&]() {
        #pragma unroll
        for (int it = 0; it < 33; it++) {
            int e = tid + 128 * it;
            if (e < 4128) {
                int k = e >> 5, o = e & 31;
                Ws[k * 36 + o] = to_tf32(wreg[it]);
            }
        }
    };
    auto bldZ = [&](int d) {
        for (int e = tid; e < 32 * 132; e += 128) {
            int lm = e / 132;
            Zs[e] = to_tf32(qv_s[lm * 33 + d] * sel_s[e]);
        }
    };

    ldW(0);
    stW();
    bldZ(0);
    __syncthreads();

    float acc[2][4] = {};

    for (int d = 0; d < 32; d++) {
        if (d < 31) ldW(d + 1);
        #pragma unroll 4
        for (int ks = 0; ks < 16; ks++) {
            int k0 = ks * 8;
            uint32_t a0 = Zs[(m0 + g) * 132 + k0 + t];
            uint32_t a1 = Zs[(m0 + g + 8) * 132 + k0 + t];
            uint32_t a2 = Zs[(m0 + g) * 132 + k0 + t + 4];
            uint32_t a3 = Zs[(m0 + g + 8) * 132 + k0 + t + 4];
            #pragma unroll
            for (int cn = 0; cn < 2; cn++) {
                uint32_t b0 = Ws[(k0 + t) * 36 + n0l + cn * 8 + g];
                uint32_t b1 = Ws[(k0 + t + 4) * 36 + n0l + cn * 8 + g];
                mma_tf32(acc[cn], a0, a1, a2, a3, b0, b1);
            }
        }
        float z0 = __uint_as_float(Zs[(m0 + g) * 132 + 128]);
        float z1 = __uint_as_float(Zs[(m0 + g + 8) * 132 + 128]);
        #pragma unroll
        for (int cn = 0; cn < 2; cn++) {
            float w0 = __uint_as_float(Ws[128 * 36 + n0l + cn * 8 + 2 * t]);
            float w1 = __uint_as_float(Ws[128 * 36 + n0l + cn * 8 + 2 * t + 1]);
            acc[cn][0] += z0 * w0; acc[cn][1] += z0 * w1;
            acc[cn][2] += z1 * w0; acc[cn][3] += z1 * w1;
        }
        __syncthreads();
        if (d < 31) {
            stW();
            bldZ(d + 1);
            __syncthreads();
        }
    }

    #pragma unroll 4
    for (int d = 0; d < 32; d++) {
        float q0 = qv_s[(m0 + g) * 33 + d];
        float q1 = qv_s[(m0 + g + 8) * 33 + d];
        #pragma unroll
        for (int cn = 0; cn < 2; cn++) {
            float w0 = bs[d * 34 + n0l + cn * 8 + 2 * t];
            float w1 = bs[d * 34 + n0l + cn * 8 + 2 * t + 1];
            acc[cn][0] += q0 * w0; acc[cn][1] += q0 * w1;
            acc[cn][2] += q1 * w0; acc[cn][3] += q1 * w1;
        }
    }

    int gm0 = blk * 32 + m0 + g;
    int gm1 = gm0 + 8;
    #pragma unroll
    for (int cn = 0; cn < 2; cn++) {
        int col = ob + n0l + cn * 8 + 2 * t;
        #pragma unroll
        for (int jj = 0; jj < 2; jj++) {
            int gm = jj ? gm1 : gm0;
            float c0 = acc[cn][2 * jj], c1 = acc[cn][2 * jj + 1];
            float u0 = g_u[gm * 64 + col],     hn0 = g_hn[gm * 64 + col];
            float u1 = g_u[gm * 64 + col + 1], hn1 = g_hn[gm * 64 + col + 1];
            out[gm * 64 + col]     = (1.f - u0) * hn0 + u0 * tanhf(c0);
            out[gm * 64 + col + 1] = (1.f - u1) * hn1 + u1 * tanhf(c1);
        }
    }
}

// ---------------- launch ----------------
extern "C" void kernel_launch(void* const* d_in, const int* in_sizes, int n_in,
                              void* d_out, int out_size) {
    const float* x   = (const float*)d_in[0];
    const float* h   = (const float*)d_in[1];
    const float* qv  = (const float*)d_in[2];
    const int*   adj = (const int*)  d_in[3];
    const int*   nb  = (const int*)  d_in[4];
    const int*   nn  = (const int*)  d_in[5];
    const float* Wq  = (const float*)d_in[6];
    const float* bq  = (const float*)d_in[7];
    const float* Wk  = (const float*)d_in[8];
    const float* bk  = (const float*)d_in[9];
    const float* Wv  = (const float*)d_in[10];
    const float* bv  = (const float*)d_in[11];
    const float* W1  = (const float*)d_in[12];
    const float* b1  = (const float*)d_in[13];
    const float* W2  = (const float*)d_in[14];
    const float* b2  = (const float*)d_in[15];
    const float* Wr  = (const float*)d_in[16];
    const float* br  = (const float*)d_in[17];
    const float* Wu  = (const float*)d_in[18];
    const float* bu  = (const float*)d_in[19];
    const float* Wc  = (const float*)d_in[20];
    const float* bc  = (const float*)d_in[21];
    float* out = (float*)d_out;

    const int SZ_RU = (32 * 132 + 32 * 33 + 32 * 132 + 2 * 129 * 36 + 2 * 32 * 34 + 16) * 4;
    const int SZ_C  = (32 * 132 + 32 * 33 + 32 * 132 + 129 * 36 + 32 * 34 + 16) * 4;

    cudaFuncSetAttribute(k_qkv,      cudaFuncAttributeMaxDynamicSharedMemorySize, SMEM_QKV);
    cudaFuncSetAttribute(k_attn_mma, cudaFuncAttributeMaxDynamicSharedMemorySize, SMEM_ATT);
    cudaFuncSetAttribute(k_mlp,      cudaFuncAttributeMaxDynamicSharedMemorySize, SMEM_MLP);
    cudaFuncSetAttribute(k_gate_ru,  cudaFuncAttributeMaxDynamicSharedMemorySize, SZ_RU);
    cudaFuncSetAttribute(k_gate_c,   cudaFuncAttributeMaxDynamicSharedMemorySize, SZ_C);

    k_adjpack<<<(Nn * Nn) / 256, 256>>>(adj);
    k_qkv<<<dim3(128, 4), 256, SMEM_QKV>>>(x, h, Wv, bv, Wq, bq, Wk, bk);
    k_attn_mma<<<dim3(16, 8, 4), 128, SMEM_ATT>>>();
    k_mlp<<<256, 256, SMEM_MLP>>>(W1, b1, W2, b2);
    k_gate_ru<<<dim3(128, 2), 256, SZ_RU>>>(qv, nb, nn, Wr, br, Wu, bu, x, h);
    k_gate_c<<<dim3(128, 2), 128, SZ_C>>>(qv, Wc, bc, out);
}

// round 13
// speedup vs baseline: 4.8464x; 1.1464x over previous
#include <cuda_runtime.h>
#include <cuda_bf16.h>
#include <cstdint>
#include <math.h>

#define Bb   8
#define Nn   1024
#define Dd   64
#define Hh   4
#define Cc   129
#define Kk   16
#define Mm   4096
#define ROWS 8192   // B*N

// ---------------- helpers ----------------
__device__ __forceinline__ uint32_t cvt_bf16x2(float hi, float lo) {
    uint32_t r;
    asm("cvt.rn.bf16x2.f32 %0, %1, %2;" : "=r"(r) : "f"(hi), "f"(lo));
    return r;
}
__device__ __forceinline__ uint32_t to_tf32(float f) {
    uint32_t r;
    asm("cvt.rna.tf32.f32 %0, %1;" : "=r"(r) : "f"(f));
    return r;
}
__device__ __forceinline__ void mma_bf16(float c[4], uint32_t a0, uint32_t a1, uint32_t a2, uint32_t a3,
                                         uint32_t b0, uint32_t b1) {
    asm volatile("mma.sync.aligned.m16n8k16.row.col.f32.bf16.bf16.f32 "
                 "{%0,%1,%2,%3}, {%4,%5,%6,%7}, {%8,%9}, {%0,%1,%2,%3};"
                 : "+f"(c[0]), "+f"(c[1]), "+f"(c[2]), "+f"(c[3])
                 : "r"(a0), "r"(a1), "r"(a2), "r"(a3), "r"(b0), "r"(b1));
}
__device__ __forceinline__ void mma_tf32(float c[4], uint32_t a0, uint32_t a1, uint32_t a2, uint32_t a3,
                                         uint32_t b0, uint32_t b1) {
    asm volatile("mma.sync.aligned.m16n8k8.row.col.f32.tf32.tf32.f32 "
                 "{%0,%1,%2,%3}, {%4,%5,%6,%7}, {%8,%9}, {%0,%1,%2,%3};"
                 : "+f"(c[0]), "+f"(c[1]), "+f"(c[2]), "+f"(c[3])
                 : "r"(a0), "r"(a1), "r"(a2), "r"(a3), "r"(b0), "r"(b1));
}
__device__ __forceinline__ float expleaky(float s, uint32_t bit) {
    s *= 0.25f;
    s = s > 0.f ? s : 0.2f * s;
    return bit ? __expf(s) : 0.f;
}

// ================= scratch =================
__device__ float g_combined[ROWS * Cc];
__device__ __nv_bfloat16 g_qb[Hh * ROWS * Kk];
__device__ __nv_bfloat16 g_kb[Hh * ROWS * Kk];
__device__ __nv_bfloat16 g_vtb[Hh * Bb * 128 * 1024];   // [h*8+b][c<128][m]
__device__ float g_v128[Hh * Bb * 1024];                // v col 128
__device__ uint32_t g_adjbits[Nn * 32];
__device__ float g_hp[ROWS * 4 * 132];                  // [row][h][132 padded], normalized
__device__ float g_hn[Mm * Dd];
__device__ float g_u[Mm * Dd];
__device__ float g_sel2[Mm * Cc];

// ---------------- K0b: pack adjacency bits ----------------
__global__ void k_adjpack(const int* __restrict__ adj) {
    int idx = blockIdx.x * 256 + threadIdx.x;
    uint32_t bits = __ballot_sync(0xFFFFFFFFu, adj[idx] != 0);
    if ((idx & 31) == 0) g_adjbits[idx >> 5] = bits;
}

// ---------------- K1: fused concat + q/k/v projections via bf16 mma ----------------
#define QKV_AB_OFF 0
#define QKV_WT_OFF 19456
#define QKV_BS_OFF (19456 + 53504)
#define SMEM_QKV (QKV_BS_OFF + 176 * 4)

__global__ void __launch_bounds__(256, 2) k_qkv(const float* __restrict__ x, const float* __restrict__ h,
                                                const float* __restrict__ Wv, const float* __restrict__ bv,
                                                const float* __restrict__ Wq, const float* __restrict__ bq,
                                                const float* __restrict__ Wk, const float* __restrict__ bk) {
    extern __shared__ char smc[];
    uint32_t* Ab = (uint32_t*)(smc + QKV_AB_OFF);
    uint32_t* Wt = (uint32_t*)(smc + QKV_WT_OFF);
    float* bias_s = (float*)(smc + QKV_BS_OFF);
    int tile = blockIdx.x, hh = blockIdx.y, tid = threadIdx.x;
    int w = tid >> 5, lane = tid & 31, g = lane >> 2, t = lane & 3;
    int wm = w & 3, wn = w >> 2;
    int m0 = wm * 16;

    for (int e = tid; e < 64 * 76; e += 256) {
        int r = e / 76, u = e - r * 76;
        int row = tile * 64 + r;
        uint32_t val = 0;
        if (u < 65) {
            int c0 = 2 * u, c1 = 2 * u + 1;
            float f0 = (c0 < 65) ? x[row * 65 + c0] : h[row * 64 + (c0 - 65)];
            float f1 = 0.f;
            if (c1 < 129) f1 = (c1 < 65) ? x[row * 65 + c1] : h[row * 64 + (c1 - 65)];
            val = cvt_bf16x2(f1, f0);
            if (hh == 0) {
                g_combined[row * Cc + c0] = f0;
                if (c1 < 129) g_combined[row * Cc + c1] = f1;
            }
        }
        Ab[e] = val;
    }
    const float* wvh = Wv + (size_t)hh * 129 * 129;
    const float* wqh = Wq + (size_t)hh * 129 * 16;
    const float* wkh = Wk + (size_t)hh * 129 * 16;
    for (int e = tid; e < 76 * 176; e += 256) {
        int u = e / 176, n = e - u * 176;
        float w0 = 0.f, w1 = 0.f;
        if (u < 65) {
            int k0 = 2 * u, k1 = 2 * u + 1;
            if (n < 129) {
                w0 = wvh[k0 * 129 + n];
                if (k1 < 129) w1 = wvh[k1 * 129 + n];
            } else if (n >= 136 && n < 152) {
                int kk = n - 136;
                w0 = wqh[k0 * 16 + kk];
                if (k1 < 129) w1 = wqh[k1 * 16 + kk];
            } else if (n >= 152 && n < 168) {
                int kk = n - 152;
                w0 = wkh[k0 * 16 + kk];
                if (k1 < 129) w1 = wkh[k1 * 16 + kk];
            }
        }
        Wt[n * 76 + u] = cvt_bf16x2(w1, w0);
    }
    for (int e = tid; e < 176; e += 256) {
        float bval = 0.f;
        if (e < 129) bval = bv[hh * 129 + e];
        else if (e >= 136 && e < 152) bval = bq[hh * 16 + e - 136];
        else if (e >= 152 && e < 168) bval = bk[hh * 16 + e - 152];
        bias_s[e] = bval;
    }
    __syncthreads();

    float acc[11][4];
    #pragma unroll
    for (int i = 0; i < 11; i++) { acc[i][0] = acc[i][1] = acc[i][2] = acc[i][3] = 0.f; }
    int ntb = wn * 11;

    #pragma unroll
    for (int ks = 0; ks < 9; ks++) {
        uint32_t a0 = Ab[(m0 + g) * 76 + 8 * ks + t];
        uint32_t a1 = Ab[(m0 + g + 8) * 76 + 8 * ks + t];
        uint32_t a2 = Ab[(m0 + g) * 76 + 8 * ks + t + 4];
        uint32_t a3 = Ab[(m0 + g + 8) * 76 + 8 * ks + t + 4];
        #pragma unroll
        for (int i = 0; i < 11; i++) {
            int nt = ntb + i;
            uint32_t b0 = Wt[(8 * nt + g) * 76 + 8 * ks + t];
            uint32_t b1 = Wt[(8 * nt + g) * 76 + 8 * ks + t + 4];
            mma_bf16(acc[i], a0, a1, a2, a3, b0, b1);
        }
    }

    size_t rowbase = (size_t)hh * ROWS + tile * 64 + m0;
    if (wn == 1) {
        #pragma unroll
        for (int i = 6; i < 10; i++) {
            int nt = 11 + i;
            bool isq = nt < 19;
            int col = (nt - (isq ? 17 : 19)) * 8 + 2 * t;
            float b0v = bias_s[(isq ? 136 : 152) + col];
            float b1v = bias_s[(isq ? 136 : 152) + col + 1];
            __nv_bfloat16* dst = isq ? g_qb : g_kb;
            *(uint32_t*)&dst[(rowbase + g) * 16 + col] =
                cvt_bf16x2(acc[i][1] + b1v, acc[i][0] + b0v);
            *(uint32_t*)&dst[(rowbase + g + 8) * 16 + col] =
                cvt_bf16x2(acc[i][3] + b1v, acc[i][2] + b0v);
        }
    }
    __syncthreads();
    float* vtile = (float*)smc;
    #pragma unroll
    for (int i = 0; i < 11; i++) {
        int nt = ntb + i;
        if (nt > 16) break;
        int col = 8 * nt + 2 * t;
        if (col <= 128) {
            float bb = bias_s[col];
            vtile[(m0 + g) * 132 + col]     = acc[i][0] + bb;
            vtile[(m0 + g + 8) * 132 + col] = acc[i][2] + bb;
        }
        if (col + 1 <= 128) {
            float bb = bias_s[col + 1];
            vtile[(m0 + g) * 132 + col + 1]     = acc[i][1] + bb;
            vtile[(m0 + g + 8) * 132 + col + 1] = acc[i][3] + bb;
        }
    }
    __syncthreads();

    int b_idx = tile >> 4;
    int mbase = (tile & 15) * 64;
    size_t hb = hh * 8 + b_idx;
    for (int e = tid; e < 128 * 32; e += 256) {
        int c = e >> 5, mp = e & 31;
        float f0 = vtile[(mp * 2) * 132 + c];
        float f1 = vtile[(mp * 2 + 1) * 132 + c];
        *(__nv_bfloat162*)&g_vtb[(hb * 128 + c) * 1024 + mbase + mp * 2] =
            __float22bfloat162_rn(make_float2(f0, f1));
    }
    if (tid < 64)
        g_v128[hb * 1024 + mbase + tid] = vtile[tid * 132 + 128];
}

// ---------------- K3: HMMA flash attention, 64-row CTAs, 2 CTA/SM ----------------
#define AKS_OFF 0
#define AVT_OFF 6144
#define AV1_OFF (6144 + 34816)
#define SMEM_ATT (AV1_OFF + 512)

__global__ void __launch_bounds__(128, 2) k_attn_mma() {
    extern __shared__ char smc[];
    uint32_t* Ks  = (uint32_t*)(smc + AKS_OFF);
    uint32_t* VTs = (uint32_t*)(smc + AVT_OFF);
    float*    v1s = (float*)(smc + AV1_OFF);
    int tid = threadIdx.x, w = tid >> 5, lane = tid & 31;
    int g = lane >> 2, t = lane & 3;
    int rblk = blockIdx.x, b = blockIdx.y, hh = blockIdx.z;
    size_t hb = hh * 8 + b;
    int brow = b * 1024 + rblk * 64;

    const __nv_bfloat16* qsrc = g_qb + ((size_t)hh * ROWS + brow + 16 * w) * 16;
    uint32_t qa0 = *(const uint32_t*)(qsrc + g * 16 + 2 * t);
    uint32_t qa1 = *(const uint32_t*)(qsrc + (g + 8) * 16 + 2 * t);
    uint32_t qa2 = *(const uint32_t*)(qsrc + g * 16 + 2 * t + 8);
    uint32_t qa3 = *(const uint32_t*)(qsrc + (g + 8) * 16 + 2 * t + 8);

    int nrow0 = rblk * 64 + 16 * w + g;
    int nrow1 = nrow0 + 8;

    float O[16][4];
    #pragma unroll
    for (int i = 0; i < 16; i++) { O[i][0] = O[i][1] = O[i][2] = O[i][3] = 0.f; }
    float rs0 = 0.f, rs1 = 0.f, ax0 = 0.f, ax1 = 0.f;

    const uint32_t* kbase = (const uint32_t*)(g_kb + ((size_t)hh * ROWS + b * 1024) * 16);
    const __nv_bfloat16* vbase = g_vtb + hb * 131072;

    for (int j = 0; j < 8; j++) {
        __syncthreads();
        const uint32_t* ks = kbase + j * 128 * 8;
        #pragma unroll
        for (int it = 0; it < 8; it++) {
            int e = tid + 128 * it;
            int r = e >> 3, c8 = e & 7;
            Ks[r * 12 + c8] = ks[e];
        }
        #pragma unroll
        for (int it = 0; it < 16; it++) {
            int e = tid + 128 * it;
            int c = e >> 4, q = e & 15;
            ((uint4*)(smc + AVT_OFF + c * 272))[q] =
                ((const uint4*)(vbase + (size_t)c * 1024 + j * 128))[q];
        }
        v1s[tid] = g_v128[hb * 1024 + j * 128 + tid];
        uint4 A0 = ((const uint4*)g_adjbits)[nrow0 * 8 + j];
        uint4 A1 = ((const uint4*)g_adjbits)[nrow1 * 8 + j];
        __syncthreads();

        uint32_t af[8][4];
        #pragma unroll
        for (int nt = 0; nt < 16; nt++) {
            uint32_t b0 = Ks[(8 * nt + g) * 12 + t];
            uint32_t b1 = Ks[(8 * nt + g) * 12 + t + 4];
            float c[4] = {0.f, 0.f, 0.f, 0.f};
            mma_bf16(c, qa0, qa1, qa2, qa3, b0, b1);
            uint32_t wA = (nt < 4) ? A0.x : (nt < 8) ? A0.y : (nt < 12) ? A0.z : A0.w;
            uint32_t wB = (nt < 4) ? A1.x : (nt < 8) ? A1.y : (nt < 12) ? A1.z : A1.w;
            int bitb = ((nt & 3) << 3) + 2 * t;
            float p00 = expleaky(c[0], (wA >> bitb) & 1);
            float p01 = expleaky(c[1], (wA >> (bitb + 1)) & 1);
            float p10 = expleaky(c[2], (wB >> bitb) & 1);
            float p11 = expleaky(c[3], (wB >> (bitb + 1)) & 1);
            rs0 += p00 + p01; rs1 += p10 + p11;
            float2 v2 = *(const float2*)&v1s[8 * nt + 2 * t];
            ax0 += p00 * v2.x + p01 * v2.y;
            ax1 += p10 * v2.x + p11 * v2.y;
            int kc = nt >> 1;
            if ((nt & 1) == 0) {
                af[kc][0] = cvt_bf16x2(p01, p00);
                af[kc][1] = cvt_bf16x2(p11, p10);
            } else {
                af[kc][2] = cvt_bf16x2(p01, p00);
                af[kc][3] = cvt_bf16x2(p11, p10);
            }
        }
        #pragma unroll
        for (int kc = 0; kc < 8; kc++) {
            #pragma unroll
            for (int nt2 = 0; nt2 < 16; nt2++) {
                uint32_t b0 = VTs[(8 * nt2 + g) * 68 + 8 * kc + t];
                uint32_t b1 = VTs[(8 * nt2 + g) * 68 + 8 * kc + t + 4];
                mma_bf16(O[nt2], af[kc][0], af[kc][1], af[kc][2], af[kc][3], b0, b1);
            }
        }
    }

    rs0 += __shfl_xor_sync(0xFFFFFFFFu, rs0, 1); rs0 += __shfl_xor_sync(0xFFFFFFFFu, rs0, 2);
    rs1 += __shfl_xor_sync(0xFFFFFFFFu, rs1, 1); rs1 += __shfl_xor_sync(0xFFFFFFFFu, rs1, 2);
    ax0 += __shfl_xor_sync(0xFFFFFFFFu, ax0, 1); ax0 += __shfl_xor_sync(0xFFFFFFFFu, ax0, 2);
    ax1 += __shfl_xor_sync(0xFFFFFFFFu, ax1, 1); ax1 += __shfl_xor_sync(0xFFFFFFFFu, ax1, 2);
    float inv0 = 1.f / rs0, inv1 = 1.f / rs1;

    float* d0 = g_hp + ((size_t)(brow + 16 * w + g) * 4 + hh) * 132;
    float* d1 = d0 + 8 * 4 * 132;
    #pragma unroll
    for (int nt2 = 0; nt2 < 16; nt2++) {
        *(float2*)&d0[8 * nt2 + 2 * t] = make_float2(O[nt2][0] * inv0, O[nt2][1] * inv0);
        *(float2*)&d1[8 * nt2 + 2 * t] = make_float2(O[nt2][2] * inv1, O[nt2][3] * inv1);
    }
    if (t == 0) { d0[128] = ax0 * inv0; d1[128] = ax1 * inv1; }
}

// ---------------- K4: attention MLP + skip via tf32 mma; 32-row, A-prefetch ----------------
#define MLP_A_OFF 0                         // u32[32*140] = 17920 (aliased as Hs after GEMM1)
#define MLP_W_OFF 17920                     // u32[136*140] = 76160
#define MLP_B_OFF (17920 + 76160)           // f32[272]
#define SMEM_MLP (MLP_B_OFF + 272 * 4)

__global__ void __launch_bounds__(256, 2) k_mlp(const float* __restrict__ W1, const float* __restrict__ b1,
                                                const float* __restrict__ W2, const float* __restrict__ b2) {
    extern __shared__ char smc[];
    uint32_t* As = (uint32_t*)(smc + MLP_A_OFF);
    uint32_t* Ws = (uint32_t*)(smc + MLP_W_OFF);
    float* bias_s = (float*)(smc + MLP_B_OFF);
    int blk = blockIdx.x, tid = threadIdx.x;
    int w = tid >> 5, lane = tid & 31, g = lane >> 2, t = lane & 3;
    int wm = w & 1, wn = w >> 1;
    int m0 = wm * 16;
    int NT = wn ? 4 : 5;
    int ntb = wn ? (4 * wn + 1) : 0;

    for (int e = tid; e < 272; e += 256) {
        float bval = 0.f;
        if (e < 129) bval = b1[e];
        else if (e >= 136 && e < 265) bval = b2[e - 136];
        bias_s[e] = bval;
    }
    // zero-pad As cols >=129 once (persists through all kc and Hs phase)
    for (int e = tid; e < 32 * 140; e += 256) {
        int u = e - (e / 140) * 140;
        if (u >= 129) As[e] = 0;
    }

    float areg[17];
    auto ldA = [&](int kc) {
        #pragma unroll
        for (int it = 0; it < 17; it++) {
            int e = tid + 256 * it;
            if (e < 4128) {
                int r = e / 129, u = e - r * 129;
                areg[it] = g_hp[((size_t)(blk * 32 + r) * 4 + kc) * 132 + u];
            }
        }
    };
    auto stA = [&]() {
        #pragma unroll
        for (int it = 0; it < 17; it++) {
            int e = tid + 256 * it;
            if (e < 4128) {
                int r = e / 129, u = e - r * 129;
                As[r * 140 + u] = to_tf32(areg[it]);
            }
        }
    };
    auto fillW1 = [&](int kc) {
        for (int e = tid; e < 136 * 140; e += 256) {
            int n = e / 140, u = e - n * 140;
            Ws[e] = (u < 129 && n < 129)
                ? to_tf32(W1[((size_t)kc * 129 + u) * 129 + n]) : 0;
        }
    };

    float acc[5][4];
    #pragma unroll
    for (int i = 0; i < 5; i++) { acc[i][0] = acc[i][1] = acc[i][2] = acc[i][3] = 0.f; }

    ldA(0);
    stA();
    fillW1(0);
    __syncthreads();

    for (int kc = 0; kc < 4; kc++) {
        if (kc < 3) ldA(kc + 1);
        #pragma unroll
        for (int ks = 0; ks < 17; ks++) {
            uint32_t a0 = As[(m0 + g) * 140 + 8 * ks + t];
            uint32_t a1 = As[(m0 + g + 8) * 140 + 8 * ks + t];
            uint32_t a2 = As[(m0 + g) * 140 + 8 * ks + t + 4];
            uint32_t a3 = As[(m0 + g + 8) * 140 + 8 * ks + t + 4];
            #pragma unroll
            for (int i = 0; i < 5; i++) {
                if (i >= NT) break;
                int nt = ntb + i;
                uint32_t b0 = Ws[(8 * nt + g) * 140 + 8 * ks + t];
                uint32_t b1r = Ws[(8 * nt + g) * 140 + 8 * ks + t + 4];
                mma_tf32(acc[i], a0, a1, a2, a3, b0, b1r);
            }
        }
        __syncthreads();
        if (kc < 3) {
            stA();
            fillW1(kc + 1);
            __syncthreads();
        }
    }
    // hidden = relu(acc + b1) -> tf32 into Hs (= As; pad cols already zero)
    uint32_t* Hs = As;
    #pragma unroll
    for (int i = 0; i < 5; i++) {
        if (i >= NT) break;
        int nt = ntb + i;
        int col = 8 * nt + 2 * t;
        if (col <= 128) {
            Hs[(m0 + g) * 140 + col]     = to_tf32(fmaxf(acc[i][0] + bias_s[col], 0.f));
            Hs[(m0 + g + 8) * 140 + col] = to_tf32(fmaxf(acc[i][2] + bias_s[col], 0.f));
        }
        if (col + 1 <= 128) {
            Hs[(m0 + g) * 140 + col + 1]     = to_tf32(fmaxf(acc[i][1] + bias_s[col + 1], 0.f));
            Hs[(m0 + g + 8) * 140 + col + 1] = to_tf32(fmaxf(acc[i][3] + bias_s[col + 1], 0.f));
        }
        acc[i][0] = acc[i][1] = acc[i][2] = acc[i][3] = 0.f;
    }
    __syncthreads();
    for (int e = tid; e < 136 * 140; e += 256) {
        int n = e / 140, u = e - n * 140;
        Ws[e] = (u < 129 && n < 129) ? to_tf32(W2[(size_t)u * 129 + n]) : 0;
    }
    __syncthreads();
    #pragma unroll
    for (int ks = 0; ks < 17; ks++) {
        uint32_t a0 = Hs[(m0 + g) * 140 + 8 * ks + t];
        uint32_t a1 = Hs[(m0 + g + 8) * 140 + 8 * ks + t];
        uint32_t a2 = Hs[(m0 + g) * 140 + 8 * ks + t + 4];
        uint32_t a3 = Hs[(m0 + g + 8) * 140 + 8 * ks + t + 4];
        #pragma unroll
        for (int i = 0; i < 5; i++) {
            if (i >= NT) break;
            int nt = ntb + i;
            uint32_t b0 = Ws[(8 * nt + g) * 140 + 8 * ks + t];
            uint32_t b1r = Ws[(8 * nt + g) * 140 + 8 * ks + t + 4];
            mma_tf32(acc[i], a0, a1, a2, a3, b0, b1r);
        }
    }
    #pragma unroll
    for (int i = 0; i < 5; i++) {
        if (i >= NT) break;
        int nt = ntb + i;
        int col = 8 * nt + 2 * t;
        if (col <= 128) {
            int idx = (blk * 32 + m0 + g) * Cc + col;
            g_combined[idx]          += acc[i][0] + bias_s[136 + col];
            g_combined[idx + 8 * Cc] += acc[i][2] + bias_s[136 + col];
        }
        if (col + 1 <= 128) {
            int idx = (blk * 32 + m0 + g) * Cc + col + 1;
            g_combined[idx]          += acc[i][1] + bias_s[137 + col];
            g_combined[idx + 8 * Cc] += acc[i][3] + bias_s[137 + col];
        }
    }
}

// ---------------- K5: r,u gates; on-the-fly A, double-buffered W, 1 sync/iter ----------------
__global__ void __launch_bounds__(256, 2) k_gate_ru(const float* __restrict__ qv,
                                                    const int* __restrict__ nodes_b, const int* __restrict__ nodes_n,
                                                    const float* __restrict__ Wr, const float* __restrict__ br,
                                                    const float* __restrict__ Wu, const float* __restrict__ bu,
                                                    const float* __restrict__ x, const float* __restrict__ hin) {
    extern __shared__ float sm[];
    float*    sel_s = sm;                              // [32][132]
    float*    qv_s  = sel_s + 32 * 132;                // [32][33]
    uint32_t* Ws    = (uint32_t*)(qv_s + 32 * 33);     // [2 buf][2 mat][129][36]
    float*    bs    = (float*)(Ws + 2 * 2 * 129 * 36); // [2][32][34]
    int blk = blockIdx.x, nh = blockIdx.y, tid = threadIdx.x;
    int ob = nh * 32;
    int w = tid >> 5, lane = tid & 31;
    int g = lane >> 2, t = lane & 3;
    int mt = w & 1, mat = (w >> 1) & 1, nsub = w >> 2;
    int m0 = mt * 16, n0l = nsub * 16;

    for (int e = tid; e < 32 * 132; e += 256) {
        int lm = e / 132, i = e - lm * 132;
        int gm = blk * 32 + lm;
        int node = nodes_b[gm] * Nn + nodes_n[gm];
        sel_s[e] = (i < Cc) ? g_combined[node * Cc + i] : 0.f;
    }
    for (int e = tid; e < 32 * 32; e += 256) {
        int lm = e >> 5, d = e & 31;
        qv_s[lm * 33 + d] = qv[(blk * 32 + lm) * 32 + d];
    }
    for (int e = tid; e < 2048; e += 256) {
        int m2 = e >> 10, r2 = e & 1023;
        int d2 = r2 >> 5, o = r2 & 31;
        bs[m2 * 1088 + d2 * 34 + o] = (m2 ? bu : br)[d2 * 64 + ob + o];
    }

    float wreg[33];
    auto ldW = [&](int d) {
        #pragma unroll
        for (int it = 0; it < 33; it++) {
            int e = tid + 256 * it;
            if (e < 8256) {
                int m2 = (e >= 4128);
                int e2 = e - m2 * 4128;
                int k = e2 >> 5, o = e2 & 31;
                wreg[it] = (m2 ? Wu : Wr)[((size_t)d * Cc + k) * 64 + ob + o];
            }
        }
    };
    auto stW = [&](int buf) {
        #pragma unroll
        for (int it = 0; it < 33; it++) {
            int e = tid + 256 * it;
            if (e < 8256) {
                int m2 = (e >= 4128);
                int e2 = e - m2 * 4128;
                int k = e2 >> 5, o = e2 & 31;
                Ws[buf * 9288 + m2 * 4644 + k * 36 + o] = to_tf32(wreg[it]);
            }
        }
    };

    ldW(0);
    stW(0);
    __syncthreads();

    float acc[2][4] = {};
    const int selr0 = (m0 + g) * 132, selr1 = (m0 + g + 8) * 132;
    const int qvr0 = (m0 + g) * 33,  qvr1 = (m0 + g + 8) * 33;

    for (int d = 0; d < 32; d++) {
        if (d < 31) ldW(d + 1);
        float q0 = qv_s[qvr0 + d];
        float q1 = qv_s[qvr1 + d];
        const uint32_t* Wm = Ws + (d & 1) * 9288 + mat * 4644;
        #pragma unroll 4
        for (int ks = 0; ks < 16; ks++) {
            int k0 = ks * 8;
            uint32_t a0 = to_tf32(q0 * sel_s[selr0 + k0 + t]);
            uint32_t a1 = to_tf32(q1 * sel_s[selr1 + k0 + t]);
            uint32_t a2 = to_tf32(q0 * sel_s[selr0 + k0 + t + 4]);
            uint32_t a3 = to_tf32(q1 * sel_s[selr1 + k0 + t + 4]);
            #pragma unroll
            for (int cn = 0; cn < 2; cn++) {
                uint32_t b0 = Wm[(k0 + t) * 36 + n0l + cn * 8 + g];
                uint32_t b1 = Wm[(k0 + t + 4) * 36 + n0l + cn * 8 + g];
                mma_tf32(acc[cn], a0, a1, a2, a3, b0, b1);
            }
        }
        float z0 = q0 * sel_s[selr0 + 128];
        float z1 = q1 * sel_s[selr1 + 128];
        #pragma unroll
        for (int cn = 0; cn < 2; cn++) {
            float w0 = __uint_as_float(Wm[128 * 36 + n0l + cn * 8 + 2 * t]);
            float w1 = __uint_as_float(Wm[128 * 36 + n0l + cn * 8 + 2 * t + 1]);
            acc[cn][0] += z0 * w0; acc[cn][1] += z0 * w1;
            acc[cn][2] += z1 * w0; acc[cn][3] += z1 * w1;
        }
        if (d < 31) stW((d + 1) & 1);
        __syncthreads();
    }

    const float* bm = bs + mat * 1088;
    #pragma unroll 4
    for (int d = 0; d < 32; d++) {
        float q0 = qv_s[qvr0 + d];
        float q1 = qv_s[qvr1 + d];
        #pragma unroll
        for (int cn = 0; cn < 2; cn++) {
            float w0 = bm[d * 34 + n0l + cn * 8 + 2 * t];
            float w1 = bm[d * 34 + n0l + cn * 8 + 2 * t + 1];
            acc[cn][0] += q0 * w0; acc[cn][1] += q0 * w1;
            acc[cn][2] += q1 * w0; acc[cn][3] += q1 * w1;
        }
    }

    __syncthreads();
    float* stg = sel_s;   // sel no longer needed
    int cb = mat * 40;
    #pragma unroll
    for (int cn = 0; cn < 2; cn++) {
        int col = cb + n0l + cn * 8 + 2 * t;
        stg[(m0 + g) * 132 + col]     = acc[cn][0];
        stg[(m0 + g) * 132 + col + 1] = acc[cn][1];
        stg[(m0 + g + 8) * 132 + col]     = acc[cn][2];
        stg[(m0 + g + 8) * 132 + col + 1] = acc[cn][3];
    }
    __syncthreads();

    for (int e = tid; e < 32 * 32; e += 256) {
        int lm = e >> 5, o = e & 31;
        int gm = blk * 32 + lm;
        int node = nodes_b[gm] * Nn + nodes_n[gm];
        float ar = stg[lm * 132 + o];
        float au = stg[lm * 132 + 40 + o];
        float hv = hin[node * 64 + ob + o];
        float r = 1.f / (1.f + __expf(-ar));
        float u = 1.f / (1.f + __expf(-au));
        float hn = r * hv;
        g_hn[gm * 64 + ob + o] = hn;
        g_u[gm * 64 + ob + o] = u;
        g_sel2[gm * Cc + 65 + ob + o] = hn;
    }
    if (nh == 0) {
        for (int e = tid; e < 32 * 65; e += 256) {
            int lm = e / 65, i = e - lm * 65;
            int gm = blk * 32 + lm;
            int node = nodes_b[gm] * Nn + nodes_n[gm];
            g_sel2[gm * Cc + i] = x[node * 65 + i];
        }
    }
}

// ---------------- K6: cand gate; on-the-fly A, double-buffered W, 1 sync/iter ----------------
__global__ void __launch_bounds__(128, 3) k_gate_c(const float* __restrict__ qv,
                                                   const float* __restrict__ Wc, const float* __restrict__ bc,
                                                   float* __restrict__ out) {
    extern __shared__ float sm[];
    float*    sel_s = sm;                              // [32][132]
    float*    qv_s  = sel_s + 32 * 132;                // [32][33]
    uint32_t* Ws    = (uint32_t*)(qv_s + 32 * 33);     // [2 buf][129][36]
    float*    bs    = (float*)(Ws + 2 * 129 * 36);     // [32][34]
    int blk = blockIdx.x, nh = blockIdx.y, tid = threadIdx.x;
    int ob = nh * 32;
    int w = tid >> 5, lane = tid & 31;
    int g = lane >> 2, t = lane & 3;
    int mt = w & 1, nsub = w >> 1;
    int m0 = mt * 16, n0l = nsub * 16;

    for (int e = tid; e < 32 * 132; e += 128) {
        int lm = e / 132, i = e - lm * 132;
        sel_s[e] = (i < Cc) ? g_sel2[(blk * 32 + lm) * Cc + i] : 0.f;
    }
    for (int e = tid; e < 32 * 32; e += 128) {
        int lm = e >> 5, d = e & 31;
        qv_s[lm * 33 + d] = qv[(blk * 32 + lm) * 32 + d];
    }
    for (int e = tid; e < 1024; e += 128) {
        int d2 = e >> 5, o = e & 31;
        bs[d2 * 34 + o] = bc[d2 * 64 + ob + o];
    }

    float wreg[33];
    auto ldW = [&](int d) {
        #pragma unroll
        for (int it = 0; it < 33; it++) {
            int e = tid + 128 * it;
            if (e < 4128) {
                int k = e >> 5, o = e & 31;
                wreg[it] = Wc[((size_t)d * Cc + k) * 64 + ob + o];
            }
        }
    };
    auto stW = [&](int buf) {
        #pragma unroll
        for (int it = 0; it < 33; it++) {
            int e = tid + 128 * it;
            if (e < 4128) {
                int k = e >> 5, o = e & 31;
                Ws[buf * 4644 + k * 36 + o] = to_tf32(wreg[it]);
            }
        }
    };

    ldW(0);
    stW(0);
    __syncthreads();

    float acc[2][4] = {};
    const int selr0 = (m0 + g) * 132, selr1 = (m0 + g + 8) * 132;
    const int qvr0 = (m0 + g) * 33,  qvr1 = (m0 + g + 8) * 33;

    for (int d = 0; d < 32; d++) {
        if (d < 31) ldW(d + 1);
        float q0 = qv_s[qvr0 + d];
        float q1 = qv_s[qvr1 + d];
        const uint32_t* Wm = Ws + (d & 1) * 4644;
        #pragma unroll 4
        for (int ks = 0; ks < 16; ks++) {
            int k0 = ks * 8;
            uint32_t a0 = to_tf32(q0 * sel_s[selr0 + k0 + t]);
            uint32_t a1 = to_tf32(q1 * sel_s[selr1 + k0 + t]);
            uint32_t a2 = to_tf32(q0 * sel_s[selr0 + k0 + t + 4]);
            uint32_t a3 = to_tf32(q1 * sel_s[selr1 + k0 + t + 4]);
            #pragma unroll
            for (int cn = 0; cn < 2; cn++) {
                uint32_t b0 = Wm[(k0 + t) * 36 + n0l + cn * 8 + g];
                uint32_t b1 = Wm[(k0 + t + 4) * 36 + n0l + cn * 8 + g];
                mma_tf32(acc[cn], a0, a1, a2, a3, b0, b1);
            }
        }
        float z0 = q0 * sel_s[selr0 + 128];
        float z1 = q1 * sel_s[selr1 + 128];
        #pragma unroll
        for (int cn = 0; cn < 2; cn++) {
            float w0 = __uint_as_float(Wm[128 * 36 + n0l + cn * 8 + 2 * t]);
            float w1 = __uint_as_float(Wm[128 * 36 + n0l + cn * 8 + 2 * t + 1]);
            acc[cn][0] += z0 * w0; acc[cn][1] += z0 * w1;
            acc[cn][2] += z1 * w0; acc[cn][3] += z1 * w1;
        }
        if (d < 31) stW((d + 1) & 1);
        __syncthreads();
    }

    #pragma unroll 4
    for (int d = 0; d < 32; d++) {
        float q0 = qv_s[qvr0 + d];
        float q1 = qv_s[qvr1 + d];
        #pragma unroll
        for (int cn = 0; cn < 2; cn++) {
            float w0 = bs[d * 34 + n0l + cn * 8 + 2 * t];
            float w1 = bs[d * 34 + n0l + cn * 8 + 2 * t + 1];
            acc[cn][0] += q0 * w0; acc[cn][1] += q0 * w1;
            acc[cn][2] += q1 * w0; acc[cn][3] += q1 * w1;
        }
    }

    int gm0 = blk * 32 + m0 + g;
    int gm1 = gm0 + 8;
    #pragma unroll
    for (int cn = 0; cn < 2; cn++) {
        int col = ob + n0l + cn * 8 + 2 * t;
        #pragma unroll
        for (int jj = 0; jj < 2; jj++) {
            int gm = jj ? gm1 : gm0;
            float c0 = acc[cn][2 * jj], c1 = acc[cn][2 * jj + 1];
            float u0 = g_u[gm * 64 + col],     hn0 = g_hn[gm * 64 + col];
            float u1 = g_u[gm * 64 + col + 1], hn1 = g_hn[gm * 64 + col + 1];
            out[gm * 64 + col]     = (1.f - u0) * hn0 + u0 * tanhf(c0);
            out[gm * 64 + col + 1] = (1.f - u1) * hn1 + u1 * tanhf(c1);
        }
    }
}

// ---------------- launch ----------------
extern "C" void kernel_launch(void* const* d_in, const int* in_sizes, int n_in,
                              void* d_out, int out_size) {
    const float* x   = (const float*)d_in[0];
    const float* h   = (const float*)d_in[1];
    const float* qv  = (const float*)d_in[2];
    const int*   adj = (const int*)  d_in[3];
    const int*   nb  = (const int*)  d_in[4];
    const int*   nn  = (const int*)  d_in[5];
    const float* Wq  = (const float*)d_in[6];
    const float* bq  = (const float*)d_in[7];
    const float* Wk  = (const float*)d_in[8];
    const float* bk  = (const float*)d_in[9];
    const float* Wv  = (const float*)d_in[10];
    const float* bv  = (const float*)d_in[11];
    const float* W1  = (const float*)d_in[12];
    const float* b1  = (const float*)d_in[13];
    const float* W2  = (const float*)d_in[14];
    const float* b2  = (const float*)d_in[15];
    const float* Wr  = (const float*)d_in[16];
    const float* br  = (const float*)d_in[17];
    const float* Wu  = (const float*)d_in[18];
    const float* bu  = (const float*)d_in[19];
    const float* Wc  = (const float*)d_in[20];
    const float* bc  = (const float*)d_in[21];
    float* out = (float*)d_out;

    const int SZ_RU = (32 * 132 + 32 * 33 + 2 * 2 * 129 * 36 + 2 * 32 * 34 + 16) * 4;
    const int SZ_C  = (32 * 132 + 32 * 33 + 2 * 129 * 36 + 32 * 34 + 16) * 4;

    cudaFuncSetAttribute(k_qkv,      cudaFuncAttributeMaxDynamicSharedMemorySize, SMEM_QKV);
    cudaFuncSetAttribute(k_attn_mma, cudaFuncAttributeMaxDynamicSharedMemorySize, SMEM_ATT);
    cudaFuncSetAttribute(k_mlp,      cudaFuncAttributeMaxDynamicSharedMemorySize, SMEM_MLP);
    cudaFuncSetAttribute(k_gate_ru,  cudaFuncAttributeMaxDynamicSharedMemorySize, SZ_RU);
    cudaFuncSetAttribute(k_gate_c,   cudaFuncAttributeMaxDynamicSharedMemorySize, SZ_C);

    k_adjpack<<<(Nn * Nn) / 256, 256>>>(adj);
    k_qkv<<<dim3(128, 4), 256, SMEM_QKV>>>(x, h, Wv, bv, Wq, bq, Wk, bk);
    k_attn_mma<<<dim3(16, 8, 4), 128, SMEM_ATT>>>();
    k_mlp<<<256, 256, SMEM_MLP>>>(W1, b1, W2, b2);
    k_gate_ru<<<dim3(128, 2), 256, SZ_RU>>>(qv, nb, nn, Wr, br, Wu, bu, x, h);
    k_gate_c<<<dim3(128, 2), 128, SZ_C>>>(qv, Wc, bc, out);
}

// round 14
// speedup vs baseline: 4.8641x; 1.0036x over previous
#include <cuda_runtime.h>
#include <cuda_bf16.h>
#include <cstdint>
#include <math.h>

#define Bb   8
#define Nn   1024
#define Dd   64
#define Hh   4
#define Cc   129
#define Kk   16
#define Mm   4096
#define ROWS 8192   // B*N

// ---------------- helpers ----------------
__device__ __forceinline__ uint32_t cvt_bf16x2(float hi, float lo) {
    uint32_t r;
    asm("cvt.rn.bf16x2.f32 %0, %1, %2;" : "=r"(r) : "f"(hi), "f"(lo));
    return r;
}
__device__ __forceinline__ uint32_t to_tf32(float f) {
    uint32_t r;
    asm("cvt.rna.tf32.f32 %0, %1;" : "=r"(r) : "f"(f));
    return r;
}
__device__ __forceinline__ void mma_bf16(float c[4], uint32_t a0, uint32_t a1, uint32_t a2, uint32_t a3,
                                         uint32_t b0, uint32_t b1) {
    asm volatile("mma.sync.aligned.m16n8k16.row.col.f32.bf16.bf16.f32 "
                 "{%0,%1,%2,%3}, {%4,%5,%6,%7}, {%8,%9}, {%0,%1,%2,%3};"
                 : "+f"(c[0]), "+f"(c[1]), "+f"(c[2]), "+f"(c[3])
                 : "r"(a0), "r"(a1), "r"(a2), "r"(a3), "r"(b0), "r"(b1));
}
__device__ __forceinline__ void mma_tf32(float c[4], uint32_t a0, uint32_t a1, uint32_t a2, uint32_t a3,
                                         uint32_t b0, uint32_t b1) {
    asm volatile("mma.sync.aligned.m16n8k8.row.col.f32.tf32.tf32.f32 "
                 "{%0,%1,%2,%3}, {%4,%5,%6,%7}, {%8,%9}, {%0,%1,%2,%3};"
                 : "+f"(c[0]), "+f"(c[1]), "+f"(c[2]), "+f"(c[3])
                 : "r"(a0), "r"(a1), "r"(a2), "r"(a3), "r"(b0), "r"(b1));
}
__device__ __forceinline__ float expleaky(float s, uint32_t bit) {
    s *= 0.25f;
    s = s > 0.f ? s : 0.2f * s;
    return bit ? __expf(s) : 0.f;
}

// ================= scratch =================
__device__ float g_combined[ROWS * Cc];
__device__ __nv_bfloat16 g_qb[Hh * ROWS * Kk];
__device__ __nv_bfloat16 g_kb[Hh * ROWS * Kk];
__device__ __nv_bfloat16 g_vtb[Hh * Bb * 128 * 1024];   // [h*8+b][c<128][m]
__device__ float g_v128[Hh * Bb * 1024];                // v col 128
__device__ uint32_t g_adjbits[Nn * 32];
__device__ float g_hp[ROWS * 4 * 132];                  // [row][h][132 padded], normalized
__device__ float g_hn[Mm * Dd];
__device__ float g_u[Mm * Dd];
__device__ float g_sel2[Mm * Cc];

// ---------------- K0b: pack adjacency bits ----------------
__global__ void k_adjpack(const int* __restrict__ adj) {
    int idx = blockIdx.x * 256 + threadIdx.x;
    uint32_t bits = __ballot_sync(0xFFFFFFFFu, adj[idx] != 0);
    if ((idx & 31) == 0) g_adjbits[idx >> 5] = bits;
}

// ---------------- K1: fused concat + q/k/v projections via bf16 mma ----------------
#define QKV_AB_OFF 0
#define QKV_WT_OFF 19456
#define QKV_BS_OFF (19456 + 53504)
#define SMEM_QKV (QKV_BS_OFF + 176 * 4)

__global__ void __launch_bounds__(256, 2) k_qkv(const float* __restrict__ x, const float* __restrict__ h,
                                                const float* __restrict__ Wv, const float* __restrict__ bv,
                                                const float* __restrict__ Wq, const float* __restrict__ bq,
                                                const float* __restrict__ Wk, const float* __restrict__ bk) {
    extern __shared__ char smc[];
    uint32_t* Ab = (uint32_t*)(smc + QKV_AB_OFF);
    uint32_t* Wt = (uint32_t*)(smc + QKV_WT_OFF);
    float* bias_s = (float*)(smc + QKV_BS_OFF);
    int tile = blockIdx.x, hh = blockIdx.y, tid = threadIdx.x;
    int w = tid >> 5, lane = tid & 31, g = lane >> 2, t = lane & 3;
    int wm = w & 3, wn = w >> 2;
    int m0 = wm * 16;

    for (int e = tid; e < 64 * 76; e += 256) {
        int r = e / 76, u = e - r * 76;
        int row = tile * 64 + r;
        uint32_t val = 0;
        if (u < 65) {
            int c0 = 2 * u, c1 = 2 * u + 1;
            float f0 = (c0 < 65) ? x[row * 65 + c0] : h[row * 64 + (c0 - 65)];
            float f1 = 0.f;
            if (c1 < 129) f1 = (c1 < 65) ? x[row * 65 + c1] : h[row * 64 + (c1 - 65)];
            val = cvt_bf16x2(f1, f0);
            if (hh == 0) {
                g_combined[row * Cc + c0] = f0;
                if (c1 < 129) g_combined[row * Cc + c1] = f1;
            }
        }
        Ab[e] = val;
    }
    const float* wvh = Wv + (size_t)hh * 129 * 129;
    const float* wqh = Wq + (size_t)hh * 129 * 16;
    const float* wkh = Wk + (size_t)hh * 129 * 16;
    for (int e = tid; e < 76 * 176; e += 256) {
        int u = e / 176, n = e - u * 176;
        float w0 = 0.f, w1 = 0.f;
        if (u < 65) {
            int k0 = 2 * u, k1 = 2 * u + 1;
            if (n < 129) {
                w0 = wvh[k0 * 129 + n];
                if (k1 < 129) w1 = wvh[k1 * 129 + n];
            } else if (n >= 136 && n < 152) {
                int kk = n - 136;
                w0 = wqh[k0 * 16 + kk];
                if (k1 < 129) w1 = wqh[k1 * 16 + kk];
            } else if (n >= 152 && n < 168) {
                int kk = n - 152;
                w0 = wkh[k0 * 16 + kk];
                if (k1 < 129) w1 = wkh[k1 * 16 + kk];
            }
        }
        Wt[n * 76 + u] = cvt_bf16x2(w1, w0);
    }
    for (int e = tid; e < 176; e += 256) {
        float bval = 0.f;
        if (e < 129) bval = bv[hh * 129 + e];
        else if (e >= 136 && e < 152) bval = bq[hh * 16 + e - 136];
        else if (e >= 152 && e < 168) bval = bk[hh * 16 + e - 152];
        bias_s[e] = bval;
    }
    __syncthreads();

    float acc[11][4];
    #pragma unroll
    for (int i = 0; i < 11; i++) { acc[i][0] = acc[i][1] = acc[i][2] = acc[i][3] = 0.f; }
    int ntb = wn * 11;

    #pragma unroll
    for (int ks = 0; ks < 9; ks++) {
        uint32_t a0 = Ab[(m0 + g) * 76 + 8 * ks + t];
        uint32_t a1 = Ab[(m0 + g + 8) * 76 + 8 * ks + t];
        uint32_t a2 = Ab[(m0 + g) * 76 + 8 * ks + t + 4];
        uint32_t a3 = Ab[(m0 + g + 8) * 76 + 8 * ks + t + 4];
        #pragma unroll
        for (int i = 0; i < 11; i++) {
            int nt = ntb + i;
            uint32_t b0 = Wt[(8 * nt + g) * 76 + 8 * ks + t];
            uint32_t b1 = Wt[(8 * nt + g) * 76 + 8 * ks + t + 4];
            mma_bf16(acc[i], a0, a1, a2, a3, b0, b1);
        }
    }

    size_t rowbase = (size_t)hh * ROWS + tile * 64 + m0;
    if (wn == 1) {
        #pragma unroll
        for (int i = 6; i < 10; i++) {
            int nt = 11 + i;
            bool isq = nt < 19;
            int col = (nt - (isq ? 17 : 19)) * 8 + 2 * t;
            float b0v = bias_s[(isq ? 136 : 152) + col];
            float b1v = bias_s[(isq ? 136 : 152) + col + 1];
            __nv_bfloat16* dst = isq ? g_qb : g_kb;
            *(uint32_t*)&dst[(rowbase + g) * 16 + col] =
                cvt_bf16x2(acc[i][1] + b1v, acc[i][0] + b0v);
            *(uint32_t*)&dst[(rowbase + g + 8) * 16 + col] =
                cvt_bf16x2(acc[i][3] + b1v, acc[i][2] + b0v);
        }
    }
    __syncthreads();
    float* vtile = (float*)smc;
    #pragma unroll
    for (int i = 0; i < 11; i++) {
        int nt = ntb + i;
        if (nt > 16) break;
        int col = 8 * nt + 2 * t;
        if (col <= 128) {
            float bb = bias_s[col];
            vtile[(m0 + g) * 132 + col]     = acc[i][0] + bb;
            vtile[(m0 + g + 8) * 132 + col] = acc[i][2] + bb;
        }
        if (col + 1 <= 128) {
            float bb = bias_s[col + 1];
            vtile[(m0 + g) * 132 + col + 1]     = acc[i][1] + bb;
            vtile[(m0 + g + 8) * 132 + col + 1] = acc[i][3] + bb;
        }
    }
    __syncthreads();

    int b_idx = tile >> 4;
    int mbase = (tile & 15) * 64;
    size_t hb = hh * 8 + b_idx;
    for (int e = tid; e < 128 * 32; e += 256) {
        int c = e >> 5, mp = e & 31;
        float f0 = vtile[(mp * 2) * 132 + c];
        float f1 = vtile[(mp * 2 + 1) * 132 + c];
        *(__nv_bfloat162*)&g_vtb[(hb * 128 + c) * 1024 + mbase + mp * 2] =
            __float22bfloat162_rn(make_float2(f0, f1));
    }
    if (tid < 64)
        g_v128[hb * 1024 + mbase + tid] = vtile[tid * 132 + 128];
}

// ---------------- K3: HMMA flash attention, 64-row CTAs, 2 CTA/SM ----------------
#define AKS_OFF 0
#define AVT_OFF 6144
#define AV1_OFF (6144 + 34816)
#define SMEM_ATT (AV1_OFF + 512)

__global__ void __launch_bounds__(128, 2) k_attn_mma() {
    extern __shared__ char smc[];
    uint32_t* Ks  = (uint32_t*)(smc + AKS_OFF);
    uint32_t* VTs = (uint32_t*)(smc + AVT_OFF);
    float*    v1s = (float*)(smc + AV1_OFF);
    int tid = threadIdx.x, w = tid >> 5, lane = tid & 31;
    int g = lane >> 2, t = lane & 3;
    int rblk = blockIdx.x, b = blockIdx.y, hh = blockIdx.z;
    size_t hb = hh * 8 + b;
    int brow = b * 1024 + rblk * 64;

    const __nv_bfloat16* qsrc = g_qb + ((size_t)hh * ROWS + brow + 16 * w) * 16;
    uint32_t qa0 = *(const uint32_t*)(qsrc + g * 16 + 2 * t);
    uint32_t qa1 = *(const uint32_t*)(qsrc + (g + 8) * 16 + 2 * t);
    uint32_t qa2 = *(const uint32_t*)(qsrc + g * 16 + 2 * t + 8);
    uint32_t qa3 = *(const uint32_t*)(qsrc + (g + 8) * 16 + 2 * t + 8);

    int nrow0 = rblk * 64 + 16 * w + g;
    int nrow1 = nrow0 + 8;

    float O[16][4];
    #pragma unroll
    for (int i = 0; i < 16; i++) { O[i][0] = O[i][1] = O[i][2] = O[i][3] = 0.f; }
    float rs0 = 0.f, rs1 = 0.f, ax0 = 0.f, ax1 = 0.f;

    const uint32_t* kbase = (const uint32_t*)(g_kb + ((size_t)hh * ROWS + b * 1024) * 16);
    const __nv_bfloat16* vbase = g_vtb + hb * 131072;

    for (int j = 0; j < 8; j++) {
        __syncthreads();
        const uint32_t* ks = kbase + j * 128 * 8;
        #pragma unroll
        for (int it = 0; it < 8; it++) {
            int e = tid + 128 * it;
            int r = e >> 3, c8 = e & 7;
            Ks[r * 12 + c8] = ks[e];
        }
        #pragma unroll
        for (int it = 0; it < 16; it++) {
            int e = tid + 128 * it;
            int c = e >> 4, q = e & 15;
            ((uint4*)(smc + AVT_OFF + c * 272))[q] =
                ((const uint4*)(vbase + (size_t)c * 1024 + j * 128))[q];
        }
        v1s[tid] = g_v128[hb * 1024 + j * 128 + tid];
        uint4 A0 = ((const uint4*)g_adjbits)[nrow0 * 8 + j];
        uint4 A1 = ((const uint4*)g_adjbits)[nrow1 * 8 + j];
        __syncthreads();

        uint32_t af[8][4];
        #pragma unroll
        for (int nt = 0; nt < 16; nt++) {
            uint32_t b0 = Ks[(8 * nt + g) * 12 + t];
            uint32_t b1 = Ks[(8 * nt + g) * 12 + t + 4];
            float c[4] = {0.f, 0.f, 0.f, 0.f};
            mma_bf16(c, qa0, qa1, qa2, qa3, b0, b1);
            uint32_t wA = (nt < 4) ? A0.x : (nt < 8) ? A0.y : (nt < 12) ? A0.z : A0.w;
            uint32_t wB = (nt < 4) ? A1.x : (nt < 8) ? A1.y : (nt < 12) ? A1.z : A1.w;
            int bitb = ((nt & 3) << 3) + 2 * t;
            float p00 = expleaky(c[0], (wA >> bitb) & 1);
            float p01 = expleaky(c[1], (wA >> (bitb + 1)) & 1);
            float p10 = expleaky(c[2], (wB >> bitb) & 1);
            float p11 = expleaky(c[3], (wB >> (bitb + 1)) & 1);
            rs0 += p00 + p01; rs1 += p10 + p11;
            float2 v2 = *(const float2*)&v1s[8 * nt + 2 * t];
            ax0 += p00 * v2.x + p01 * v2.y;
            ax1 += p10 * v2.x + p11 * v2.y;
            int kc = nt >> 1;
            if ((nt & 1) == 0) {
                af[kc][0] = cvt_bf16x2(p01, p00);
                af[kc][1] = cvt_bf16x2(p11, p10);
            } else {
                af[kc][2] = cvt_bf16x2(p01, p00);
                af[kc][3] = cvt_bf16x2(p11, p10);
            }
        }
        #pragma unroll
        for (int kc = 0; kc < 8; kc++) {
            #pragma unroll
            for (int nt2 = 0; nt2 < 16; nt2++) {
                uint32_t b0 = VTs[(8 * nt2 + g) * 68 + 8 * kc + t];
                uint32_t b1 = VTs[(8 * nt2 + g) * 68 + 8 * kc + t + 4];
                mma_bf16(O[nt2], af[kc][0], af[kc][1], af[kc][2], af[kc][3], b0, b1);
            }
        }
    }

    rs0 += __shfl_xor_sync(0xFFFFFFFFu, rs0, 1); rs0 += __shfl_xor_sync(0xFFFFFFFFu, rs0, 2);
    rs1 += __shfl_xor_sync(0xFFFFFFFFu, rs1, 1); rs1 += __shfl_xor_sync(0xFFFFFFFFu, rs1, 2);
    ax0 += __shfl_xor_sync(0xFFFFFFFFu, ax0, 1); ax0 += __shfl_xor_sync(0xFFFFFFFFu, ax0, 2);
    ax1 += __shfl_xor_sync(0xFFFFFFFFu, ax1, 1); ax1 += __shfl_xor_sync(0xFFFFFFFFu, ax1, 2);
    float inv0 = 1.f / rs0, inv1 = 1.f / rs1;

    float* d0 = g_hp + ((size_t)(brow + 16 * w + g) * 4 + hh) * 132;
    float* d1 = d0 + 8 * 4 * 132;
    #pragma unroll
    for (int nt2 = 0; nt2 < 16; nt2++) {
        *(float2*)&d0[8 * nt2 + 2 * t] = make_float2(O[nt2][0] * inv0, O[nt2][1] * inv0);
        *(float2*)&d1[8 * nt2 + 2 * t] = make_float2(O[nt2][2] * inv1, O[nt2][3] * inv1);
    }
    if (t == 0) { d0[128] = ax0 * inv0; d1[128] = ax1 * inv1; }
}

// ---------------- K4: attention MLP + skip via tf32 mma; coalesced W fills ----------------
#define MLP_A_OFF 0                         // u32[32*140] = 17920 (aliased as Hs after GEMM1)
#define MLP_W_OFF 17920                     // u32[136*140] = 76160
#define MLP_B_OFF (17920 + 76160)           // f32[272]
#define SMEM_MLP (MLP_B_OFF + 272 * 4)

__global__ void __launch_bounds__(256, 2) k_mlp(const float* __restrict__ W1, const float* __restrict__ b1,
                                                const float* __restrict__ W2, const float* __restrict__ b2) {
    extern __shared__ char smc[];
    uint32_t* As = (uint32_t*)(smc + MLP_A_OFF);
    uint32_t* Ws = (uint32_t*)(smc + MLP_W_OFF);
    float* bias_s = (float*)(smc + MLP_B_OFF);
    int blk = blockIdx.x, tid = threadIdx.x;
    int w = tid >> 5, lane = tid & 31, g = lane >> 2, t = lane & 3;
    int wm = w & 1, wn = w >> 1;
    int m0 = wm * 16;
    int NT = wn ? 4 : 5;
    int ntb = wn ? (4 * wn + 1) : 0;

    for (int e = tid; e < 272; e += 256) {
        float bval = 0.f;
        if (e < 129) bval = b1[e];
        else if (e >= 136 && e < 265) bval = b2[e - 136];
        bias_s[e] = bval;
    }
    // zero-pad As cols >=129 and Ws pad entries ONCE (persist across refills)
    for (int e = tid; e < 32 * 140; e += 256) {
        int u = e - (e / 140) * 140;
        if (u >= 129) As[e] = 0;
    }
    for (int e = tid; e < 136 * 140; e += 256) {
        int n = e / 140, u = e - n * 140;
        if (n >= 129 || u >= 129) Ws[e] = 0;
    }

    float areg[17];
    auto ldA = [&](int kc) {
        #pragma unroll
        for (int it = 0; it < 17; it++) {
            int e = tid + 256 * it;
            if (e < 4128) {
                int r = e / 129, u = e - r * 129;
                areg[it] = g_hp[((size_t)(blk * 32 + r) * 4 + kc) * 132 + u];
            }
        }
    };
    auto stA = [&]() {
        #pragma unroll
        for (int it = 0; it < 17; it++) {
            int e = tid + 256 * it;
            if (e < 4128) {
                int r = e / 129, u = e - r * 129;
                As[r * 140 + u] = to_tf32(areg[it]);
            }
        }
    };
    // coalesced W fill: consecutive threads read consecutive n (row-major W src)
    auto fillW = [&](const float* Wsrc) {
        for (int e = tid; e < 129 * 132; e += 256) {
            int u = e / 132, n = e - u * 132;
            if (n < 129) Ws[n * 140 + u] = to_tf32(Wsrc[(size_t)u * 129 + n]);
        }
    };

    float acc[5][4];
    #pragma unroll
    for (int i = 0; i < 5; i++) { acc[i][0] = acc[i][1] = acc[i][2] = acc[i][3] = 0.f; }

    ldA(0);
    stA();
    fillW(W1);
    __syncthreads();

    for (int kc = 0; kc < 4; kc++) {
        if (kc < 3) ldA(kc + 1);
        #pragma unroll
        for (int ks = 0; ks < 17; ks++) {
            uint32_t a0 = As[(m0 + g) * 140 + 8 * ks + t];
            uint32_t a1 = As[(m0 + g + 8) * 140 + 8 * ks + t];
            uint32_t a2 = As[(m0 + g) * 140 + 8 * ks + t + 4];
            uint32_t a3 = As[(m0 + g + 8) * 140 + 8 * ks + t + 4];
            #pragma unroll
            for (int i = 0; i < 5; i++) {
                if (i >= NT) break;
                int nt = ntb + i;
                uint32_t b0 = Ws[(8 * nt + g) * 140 + 8 * ks + t];
                uint32_t b1r = Ws[(8 * nt + g) * 140 + 8 * ks + t + 4];
                mma_tf32(acc[i], a0, a1, a2, a3, b0, b1r);
            }
        }
        __syncthreads();
        if (kc < 3) {
            stA();
            fillW(W1 + (size_t)(kc + 1) * 129 * 129);
            __syncthreads();
        }
    }
    uint32_t* Hs = As;
    #pragma unroll
    for (int i = 0; i < 5; i++) {
        if (i >= NT) break;
        int nt = ntb + i;
        int col = 8 * nt + 2 * t;
        if (col <= 128) {
            Hs[(m0 + g) * 140 + col]     = to_tf32(fmaxf(acc[i][0] + bias_s[col], 0.f));
            Hs[(m0 + g + 8) * 140 + col] = to_tf32(fmaxf(acc[i][2] + bias_s[col], 0.f));
        }
        if (col + 1 <= 128) {
            Hs[(m0 + g) * 140 + col + 1]     = to_tf32(fmaxf(acc[i][1] + bias_s[col + 1], 0.f));
            Hs[(m0 + g + 8) * 140 + col + 1] = to_tf32(fmaxf(acc[i][3] + bias_s[col + 1], 0.f));
        }
        acc[i][0] = acc[i][1] = acc[i][2] = acc[i][3] = 0.f;
    }
    __syncthreads();
    fillW(W2);
    __syncthreads();
    #pragma unroll
    for (int ks = 0; ks < 17; ks++) {
        uint32_t a0 = Hs[(m0 + g) * 140 + 8 * ks + t];
        uint32_t a1 = Hs[(m0 + g + 8) * 140 + 8 * ks + t];
        uint32_t a2 = Hs[(m0 + g) * 140 + 8 * ks + t + 4];
        uint32_t a3 = Hs[(m0 + g + 8) * 140 + 8 * ks + t + 4];
        #pragma unroll
        for (int i = 0; i < 5; i++) {
            if (i >= NT) break;
            int nt = ntb + i;
            uint32_t b0 = Ws[(8 * nt + g) * 140 + 8 * ks + t];
            uint32_t b1r = Ws[(8 * nt + g) * 140 + 8 * ks + t + 4];
            mma_tf32(acc[i], a0, a1, a2, a3, b0, b1r);
        }
    }
    #pragma unroll
    for (int i = 0; i < 5; i++) {
        if (i >= NT) break;
        int nt = ntb + i;
        int col = 8 * nt + 2 * t;
        if (col <= 128) {
            int idx = (blk * 32 + m0 + g) * Cc + col;
            g_combined[idx]          += acc[i][0] + bias_s[136 + col];
            g_combined[idx + 8 * Cc] += acc[i][2] + bias_s[136 + col];
        }
        if (col + 1 <= 128) {
            int idx = (blk * 32 + m0 + g) * Cc + col + 1;
            g_combined[idx]          += acc[i][1] + bias_s[137 + col];
            g_combined[idx + 8 * Cc] += acc[i][3] + bias_s[137 + col];
        }
    }
}

// ---------------- K5: r,u gates; on-the-fly A, double-buffered W, 1 sync/iter ----------------
__global__ void __launch_bounds__(256, 2) k_gate_ru(const float* __restrict__ qv,
                                                    const int* __restrict__ nodes_b, const int* __restrict__ nodes_n,
                                                    const float* __restrict__ Wr, const float* __restrict__ br,
                                                    const float* __restrict__ Wu, const float* __restrict__ bu,
                                                    const float* __restrict__ x, const float* __restrict__ hin) {
    extern __shared__ float sm[];
    float*    sel_s = sm;                              // [32][132]
    float*    qv_s  = sel_s + 32 * 132;                // [32][33]
    uint32_t* Ws    = (uint32_t*)(qv_s + 32 * 33);     // [2 buf][2 mat][129][36]
    float*    bs    = (float*)(Ws + 2 * 2 * 129 * 36); // [2][32][34]
    int blk = blockIdx.x, nh = blockIdx.y, tid = threadIdx.x;
    int ob = nh * 32;
    int w = tid >> 5, lane = tid & 31;
    int g = lane >> 2, t = lane & 3;
    int mt = w & 1, mat = (w >> 1) & 1, nsub = w >> 2;
    int m0 = mt * 16, n0l = nsub * 16;

    for (int e = tid; e < 32 * 132; e += 256) {
        int lm = e / 132, i = e - lm * 132;
        int gm = blk * 32 + lm;
        int node = nodes_b[gm] * Nn + nodes_n[gm];
        sel_s[e] = (i < Cc) ? g_combined[node * Cc + i] : 0.f;
    }
    for (int e = tid; e < 32 * 32; e += 256) {
        int lm = e >> 5, d = e & 31;
        qv_s[lm * 33 + d] = qv[(blk * 32 + lm) * 32 + d];
    }
    for (int e = tid; e < 2048; e += 256) {
        int m2 = e >> 10, r2 = e & 1023;
        int d2 = r2 >> 5, o = r2 & 31;
        bs[m2 * 1088 + d2 * 34 + o] = (m2 ? bu : br)[d2 * 64 + ob + o];
    }

    float wreg[33];
    auto ldW = [&](int d) {
        #pragma unroll
        for (int it = 0; it < 33; it++) {
            int e = tid + 256 * it;
            if (e < 8256) {
                int m2 = (e >= 4128);
                int e2 = e - m2 * 4128;
                int k = e2 >> 5, o = e2 & 31;
                wreg[it] = (m2 ? Wu : Wr)[((size_t)d * Cc + k) * 64 + ob + o];
            }
        }
    };
    auto stW = [&](int buf) {
        #pragma unroll
        for (int it = 0; it < 33; it++) {
            int e = tid + 256 * it;
            if (e < 8256) {
                int m2 = (e >= 4128);
                int e2 = e - m2 * 4128;
                int k = e2 >> 5, o = e2 & 31;
                Ws[buf * 9288 + m2 * 4644 + k * 36 + o] = to_tf32(wreg[it]);
            }
        }
    };

    ldW(0);
    stW(0);
    __syncthreads();

    float acc[2][4] = {};
    const int selr0 = (m0 + g) * 132, selr1 = (m0 + g + 8) * 132;
    const int qvr0 = (m0 + g) * 33,  qvr1 = (m0 + g + 8) * 33;

    for (int d = 0; d < 32; d++) {
        if (d < 31) ldW(d + 1);
        float q0 = qv_s[qvr0 + d];
        float q1 = qv_s[qvr1 + d];
        const uint32_t* Wm = Ws + (d & 1) * 9288 + mat * 4644;
        #pragma unroll 4
        for (int ks = 0; ks < 16; ks++) {
            int k0 = ks * 8;
            uint32_t a0 = to_tf32(q0 * sel_s[selr0 + k0 + t]);
            uint32_t a1 = to_tf32(q1 * sel_s[selr1 + k0 + t]);
            uint32_t a2 = to_tf32(q0 * sel_s[selr0 + k0 + t + 4]);
            uint32_t a3 = to_tf32(q1 * sel_s[selr1 + k0 + t + 4]);
            #pragma unroll
            for (int cn = 0; cn < 2; cn++) {
                uint32_t b0 = Wm[(k0 + t) * 36 + n0l + cn * 8 + g];
                uint32_t b1 = Wm[(k0 + t + 4) * 36 + n0l + cn * 8 + g];
                mma_tf32(acc[cn], a0, a1, a2, a3, b0, b1);
            }
        }
        float z0 = q0 * sel_s[selr0 + 128];
        float z1 = q1 * sel_s[selr1 + 128];
        #pragma unroll
        for (int cn = 0; cn < 2; cn++) {
            float w0 = __uint_as_float(Wm[128 * 36 + n0l + cn * 8 + 2 * t]);
            float w1 = __uint_as_float(Wm[128 * 36 + n0l + cn * 8 + 2 * t + 1]);
            acc[cn][0] += z0 * w0; acc[cn][1] += z0 * w1;
            acc[cn][2] += z1 * w0; acc[cn][3] += z1 * w1;
        }
        if (d < 31) stW((d + 1) & 1);
        __syncthreads();
    }

    const float* bm = bs + mat * 1088;
    #pragma unroll 4
    for (int d = 0; d < 32; d++) {
        float q0 = qv_s[qvr0 + d];
        float q1 = qv_s[qvr1 + d];
        #pragma unroll
        for (int cn = 0; cn < 2; cn++) {
            float w0 = bm[d * 34 + n0l + cn * 8 + 2 * t];
            float w1 = bm[d * 34 + n0l + cn * 8 + 2 * t + 1];
            acc[cn][0] += q0 * w0; acc[cn][1] += q0 * w1;
            acc[cn][2] += q1 * w0; acc[cn][3] += q1 * w1;
        }
    }

    __syncthreads();
    float* stg = sel_s;
    int cb = mat * 40;
    #pragma unroll
    for (int cn = 0; cn < 2; cn++) {
        int col = cb + n0l + cn * 8 + 2 * t;
        stg[(m0 + g) * 132 + col]     = acc[cn][0];
        stg[(m0 + g) * 132 + col + 1] = acc[cn][1];
        stg[(m0 + g + 8) * 132 + col]     = acc[cn][2];
        stg[(m0 + g + 8) * 132 + col + 1] = acc[cn][3];
    }
    __syncthreads();

    for (int e = tid; e < 32 * 32; e += 256) {
        int lm = e >> 5, o = e & 31;
        int gm = blk * 32 + lm;
        int node = nodes_b[gm] * Nn + nodes_n[gm];
        float ar = stg[lm * 132 + o];
        float au = stg[lm * 132 + 40 + o];
        float hv = hin[node * 64 + ob + o];
        float r = 1.f / (1.f + __expf(-ar));
        float u = 1.f / (1.f + __expf(-au));
        float hn = r * hv;
        g_hn[gm * 64 + ob + o] = hn;
        g_u[gm * 64 + ob + o] = u;
        g_sel2[gm * Cc + 65 + ob + o] = hn;
    }
    if (nh == 0) {
        for (int e = tid; e < 32 * 65; e += 256) {
            int lm = e / 65, i = e - lm * 65;
            int gm = blk * 32 + lm;
            int node = nodes_b[gm] * Nn + nodes_n[gm];
            g_sel2[gm * Cc + i] = x[node * 65 + i];
        }
    }
}

// ---------------- K6: cand gate; on-the-fly A, double-buffered W, 1 sync/iter ----------------
__global__ void __launch_bounds__(128, 3) k_gate_c(const float* __restrict__ qv,
                                                   const float* __restrict__ Wc, const float* __restrict__ bc,
                                                   float* __restrict__ out) {
    extern __shared__ float sm[];
    float*    sel_s = sm;                              // [32][132]
    float*    qv_s  = sel_s + 32 * 132;                // [32][33]
    uint32_t* Ws    = (uint32_t*)(qv_s + 32 * 33);     // [2 buf][129][36]
    float*    bs    = (float*)(Ws + 2 * 129 * 36);     // [32][34]
    int blk = blockIdx.x, nh = blockIdx.y, tid = threadIdx.x;
    int ob = nh * 32;
    int w = tid >> 5, lane = tid & 31;
    int g = lane >> 2, t = lane & 3;
    int mt = w & 1, nsub = w >> 1;
    int m0 = mt * 16, n0l = nsub * 16;

    for (int e = tid; e < 32 * 132; e += 128) {
        int lm = e / 132, i = e - lm * 132;
        sel_s[e] = (i < Cc) ? g_sel2[(blk * 32 + lm) * Cc + i] : 0.f;
    }
    for (int e = tid; e < 32 * 32; e += 128) {
        int lm = e >> 5, d = e & 31;
        qv_s[lm * 33 + d] = qv[(blk * 32 + lm) * 32 + d];
    }
    for (int e = tid; e < 1024; e += 128) {
        int d2 = e >> 5, o = e & 31;
        bs[d2 * 34 + o] = bc[d2 * 64 + ob + o];
    }

    float wreg[33];
    auto ldW = [&](int d) {
        #pragma unroll
        for (int it = 0; it < 33; it++) {
            int e = tid + 128 * it;
            if (e < 4128) {
                int k = e >> 5, o = e & 31;
                wreg[it] = Wc[((size_t)d * Cc + k) * 64 + ob + o];
            }
        }
    };
    auto stW = [&](int buf) {
        #pragma unroll
        for (int it = 0; it < 33; it++) {
            int e = tid + 128 * it;
            if (e < 4128) {
                int k = e >> 5, o = e & 31;
                Ws[buf * 4644 + k * 36 + o] = to_tf32(wreg[it]);
            }
        }
    };

    ldW(0);
    stW(0);
    __syncthreads();

    float acc[2][4] = {};
    const int selr0 = (m0 + g) * 132, selr1 = (m0 + g + 8) * 132;
    const int qvr0 = (m0 + g) * 33,  qvr1 = (m0 + g + 8) * 33;

    for (int d = 0; d < 32; d++) {
        if (d < 31) ldW(d + 1);
        float q0 = qv_s[qvr0 + d];
        float q1 = qv_s[qvr1 + d];
        const uint32_t* Wm = Ws + (d & 1) * 4644;
        #pragma unroll 4
        for (int ks = 0; ks < 16; ks++) {
            int k0 = ks * 8;
            uint32_t a0 = to_tf32(q0 * sel_s[selr0 + k0 + t]);
            uint32_t a1 = to_tf32(q1 * sel_s[selr1 + k0 + t]);
            uint32_t a2 = to_tf32(q0 * sel_s[selr0 + k0 + t + 4]);
            uint32_t a3 = to_tf32(q1 * sel_s[selr1 + k0 + t + 4]);
            #pragma unroll
            for (int cn = 0; cn < 2; cn++) {
                uint32_t b0 = Wm[(k0 + t) * 36 + n0l + cn * 8 + g];
                uint32_t b1 = Wm[(k0 + t + 4) * 36 + n0l + cn * 8 + g];
                mma_tf32(acc[cn], a0, a1, a2, a3, b0, b1);
            }
        }
        float z0 = q0 * sel_s[selr0 + 128];
        float z1 = q1 * sel_s[selr1 + 128];
        #pragma unroll
        for (int cn = 0; cn < 2; cn++) {
            float w0 = __uint_as_float(Wm[128 * 36 + n0l + cn * 8 + 2 * t]);
            float w1 = __uint_as_float(Wm[128 * 36 + n0l + cn * 8 + 2 * t + 1]);
            acc[cn][0] += z0 * w0; acc[cn][1] += z0 * w1;
            acc[cn][2] += z1 * w0; acc[cn][3] += z1 * w1;
        }
        if (d < 31) stW((d + 1) & 1);
        __syncthreads();
    }

    #pragma unroll 4
    for (int d = 0; d < 32; d++) {
        float q0 = qv_s[qvr0 + d];
        float q1 = qv_s[qvr1 + d];
        #pragma unroll
        for (int cn = 0; cn < 2; cn++) {
            float w0 = bs[d * 34 + n0l + cn * 8 + 2 * t];
            float w1 = bs[d * 34 + n0l + cn * 8 + 2 * t + 1];
            acc[cn][0] += q0 * w0; acc[cn][1] += q0 * w1;
            acc[cn][2] += q1 * w0; acc[cn][3] += q1 * w1;
        }
    }

    int gm0 = blk * 32 + m0 + g;
    int gm1 = gm0 + 8;
    #pragma unroll
    for (int cn = 0; cn < 2; cn++) {
        int col = ob + n0l + cn * 8 + 2 * t;
        #pragma unroll
        for (int jj = 0; jj < 2; jj++) {
            int gm = jj ? gm1 : gm0;
            float c0 = acc[cn][2 * jj], c1 = acc[cn][2 * jj + 1];
            float u0 = g_u[gm * 64 + col],     hn0 = g_hn[gm * 64 + col];
            float u1 = g_u[gm * 64 + col + 1], hn1 = g_hn[gm * 64 + col + 1];
            out[gm * 64 + col]     = (1.f - u0) * hn0 + u0 * tanhf(c0);
            out[gm * 64 + col + 1] = (1.f - u1) * hn1 + u1 * tanhf(c1);
        }
    }
}

// ---------------- launch ----------------
extern "C" void kernel_launch(void* const* d_in, const int* in_sizes, int n_in,
                              void* d_out, int out_size) {
    const float* x   = (const float*)d_in[0];
    const float* h   = (const float*)d_in[1];
    const float* qv  = (const float*)d_in[2];
    const int*   adj = (const int*)  d_in[3];
    const int*   nb  = (const int*)  d_in[4];
    const int*   nn  = (const int*)  d_in[5];
    const float* Wq  = (const float*)d_in[6];
    const float* bq  = (const float*)d_in[7];
    const float* Wk  = (const float*)d_in[8];
    const float* bk  = (const float*)d_in[9];
    const float* Wv  = (const float*)d_in[10];
    const float* bv  = (const float*)d_in[11];
    const float* W1  = (const float*)d_in[12];
    const float* b1  = (const float*)d_in[13];
    const float* W2  = (const float*)d_in[14];
    const float* b2  = (const float*)d_in[15];
    const float* Wr  = (const float*)d_in[16];
    const float* br  = (const float*)d_in[17];
    const float* Wu  = (const float*)d_in[18];
    const float* bu  = (const float*)d_in[19];
    const float* Wc  = (const float*)d_in[20];
    const float* bc  = (const float*)d_in[21];
    float* out = (float*)d_out;

    const int SZ_RU = (32 * 132 + 32 * 33 + 2 * 2 * 129 * 36 + 2 * 32 * 34 + 16) * 4;
    const int SZ_C  = (32 * 132 + 32 * 33 + 2 * 129 * 36 + 32 * 34 + 16) * 4;

    cudaFuncSetAttribute(k_qkv,      cudaFuncAttributeMaxDynamicSharedMemorySize, SMEM_QKV);
    cudaFuncSetAttribute(k_attn_mma, cudaFuncAttributeMaxDynamicSharedMemorySize, SMEM_ATT);
    cudaFuncSetAttribute(k_mlp,      cudaFuncAttributeMaxDynamicSharedMemorySize, SMEM_MLP);
    cudaFuncSetAttribute(k_gate_ru,  cudaFuncAttributeMaxDynamicSharedMemorySize, SZ_RU);
    cudaFuncSetAttribute(k_gate_c,   cudaFuncAttributeMaxDynamicSharedMemorySize, SZ_C);

    k_adjpack<<<(Nn * Nn) / 256, 256>>>(adj);
    k_qkv<<<dim3(128, 4), 256, SMEM_QKV>>>(x, h, Wv, bv, Wq, bq, Wk, bk);
    k_attn_mma<<<dim3(16, 8, 4), 128, SMEM_ATT>>>();
    k_mlp<<<256, 256, SMEM_MLP>>>(W1, b1, W2, b2);
    k_gate_ru<<<dim3(128, 2), 256, SZ_RU>>>(qv, nb, nn, Wr, br, Wu, bu, x, h);
    k_gate_c<<<dim3(128, 2), 128, SZ_C>>>(qv, Wc, bc, out);
}